// round 1
// baseline (speedup 1.0000x reference)
#include <cuda_runtime.h>
#include <math.h>

#define SEQ 2048
#define HID 1024
#define NHEAD 16
#define HD 128
#define QDIM 512
#define NEXP 32
#define IDIM 1024
#define QKV_N 768
#define SCALE 0.08838834764831845f   // 1/sqrt(128)

// ------------------------- device scratch (no cudaMalloc allowed) ----------
__device__ float g_hnorm[SEQ*HID];
__device__ float g_qkv[SEQ*QKV_N];
__device__ float g_qn[SEQ*QDIM];
__device__ float g_qproj[SEQ*NHEAD*HD];
__device__ float g_krope[SEQ*HD];
__device__ float g_attnout[SEQ*NHEAD*HD];
__device__ float g_resid2[SEQ*HID];
__device__ float g_h2[SEQ*HID];
__device__ float g_gu[SEQ*2*IDIM];
__device__ float g_actse[SEQ*IDIM];
__device__ float g_acte[SEQ*3*IDIM];
__device__ int   g_topi[SEQ*3];
__device__ float g_topw[SEQ*3];
__device__ int   g_cnt[NEXP];
__device__ int   g_off[NEXP];
__device__ int   g_fill[NEXP];
__device__ int   g_ptok[SEQ*3];
__device__ float g_pw[SEQ*3];

// ------------------------- small utility kernels ---------------------------
__global__ void zero_counts_k() {
    if (threadIdx.x < NEXP) g_cnt[threadIdx.x] = 0;
}

// generic rmsnorm: one block per row
__global__ void rmsnorm_k(const float* __restrict__ x, const float* __restrict__ w,
                          float* __restrict__ y, int cols, int ldx, int ldy)
{
    int row = blockIdx.x;
    const float* xr = x + (size_t)row * ldx;
    float ss = 0.f;
    for (int c = threadIdx.x; c < cols; c += 256) { float v = xr[c]; ss = fmaf(v, v, ss); }
    __shared__ float red[256];
    red[threadIdx.x] = ss;
    __syncthreads();
    for (int s = 128; s > 0; s >>= 1) {
        if (threadIdx.x < s) red[threadIdx.x] += red[threadIdx.x + s];
        __syncthreads();
    }
    float r = rsqrtf(red[0] / (float)cols + 1e-5f);
    float* yr = y + (size_t)row * ldy;
    for (int c = threadIdx.x; c < cols; c += 256) yr[c] = xr[c] * r * w[c];
}

// rope on q (in place, 16 heads of 128) and k (qkv cols 512..639 -> g_krope)
__global__ void rope_k(float* __restrict__ qp, const float* __restrict__ qkv,
                       float* __restrict__ kout, const int* __restrict__ pos)
{
    __shared__ float sinv[64];
    int t = blockIdx.x;
    if (threadIdx.x < 64) {
        double e = exp(-((double)(2 * threadIdx.x) / 128.0) * log(500000.0));
        sinv[threadIdx.x] = (float)e;
    }
    __syncthreads();
    float p = (float)pos[t];
    for (int idx = threadIdx.x; idx < NHEAD * 64; idx += 256) {
        int hh = idx >> 6, i = idx & 63;
        float f = p * sinv[i];
        float sn, cs; sincosf(f, &sn, &cs);
        float* b = qp + (size_t)t * (NHEAD * HD) + hh * HD;
        float x1 = b[i], x2 = b[i + 64];
        b[i]      = x1 * cs - x2 * sn;
        b[i + 64] = x2 * cs + x1 * sn;
    }
    if (threadIdx.x < 64) {
        int i = threadIdx.x;
        float f = p * sinv[i];
        float sn, cs; sincosf(f, &sn, &cs);
        const float* kb = qkv + (size_t)t * QKV_N + QDIM;
        float x1 = kb[i], x2 = kb[i + 64];
        kout[(size_t)t * HD + i]      = x1 * cs - x2 * sn;
        kout[(size_t)t * HD + i + 64] = x2 * cs + x1 * sn;
    }
}

__global__ void silu_mul_k(const float* __restrict__ gu, float* __restrict__ act)
{
    int idx = blockIdx.x * 256 + threadIdx.x;   // SEQ*IDIM total
    int r = idx >> 10, c = idx & 1023;
    float g = gu[(size_t)r * 2048 + c];
    float u = gu[(size_t)r * 2048 + c + IDIM];
    act[idx] = g / (1.f + expf(-g)) * u;
}

// ------------------------- SGEMM 128x64 tile, 4x8 micro --------------------
__global__ __launch_bounds__(256) void sgemm_k(
    const float* __restrict__ A, const float* __restrict__ B, float* __restrict__ C,
    int M, int N, int K, int lda, int ldb, int ldc, const float* __restrict__ add)
{
    __shared__ float sA[16][132];
    __shared__ float sB[16][68];
    const int m0 = blockIdx.y * 128, n0 = blockIdx.x * 64;
    const int tid = threadIdx.x;
    const int tx = tid & 7, ty = tid >> 3;
    float acc[4][8] = {};
    for (int k0 = 0; k0 < K; k0 += 16) {
        #pragma unroll
        for (int i = tid; i < 2048; i += 256) {
            int m = i >> 4, kk = i & 15;
            sA[kk][m] = A[(size_t)(m0 + m) * lda + k0 + kk];
        }
        #pragma unroll
        for (int i = tid; i < 1024; i += 256) {
            int kk = i >> 6, n = i & 63;
            sB[kk][n] = B[(size_t)(k0 + kk) * ldb + n0 + n];
        }
        __syncthreads();
        #pragma unroll
        for (int kk = 0; kk < 16; kk++) {
            float4 a4 = *(const float4*)&sA[kk][ty * 4];
            float4 b0 = *(const float4*)&sB[kk][tx * 8];
            float4 b1 = *(const float4*)&sB[kk][tx * 8 + 4];
            float a[4] = {a4.x, a4.y, a4.z, a4.w};
            float b[8] = {b0.x, b0.y, b0.z, b0.w, b1.x, b1.y, b1.z, b1.w};
            #pragma unroll
            for (int i = 0; i < 4; i++)
                #pragma unroll
                for (int j = 0; j < 8; j++)
                    acc[i][j] = fmaf(a[i], b[j], acc[i][j]);
        }
        __syncthreads();
    }
    #pragma unroll
    for (int i = 0; i < 4; i++) {
        size_t r = m0 + ty * 4 + i;
        #pragma unroll
        for (int j = 0; j < 8; j++) {
            size_t c = n0 + tx * 8 + j;
            float v = acc[i][j];
            if (add) v += add[r * ldc + c];
            C[r * ldc + c] = v;
        }
    }
}

// ------------------------- attention (causal MQA, flash-style) -------------
// grid (32 qtiles, 16 heads), 256 threads, dynamic smem
#define ATTN_SMEM ((128*68*2 + 64*132 + 64*65 + 192) * 4)
__global__ __launch_bounds__(256) void attn_k(
    const float* __restrict__ Qm, const float* __restrict__ Km,
    const float* __restrict__ qkv, float* __restrict__ Om)
{
    extern __shared__ float sm[];
    float* sQt = sm;                 // [128][68] k-major
    float* sKt = sQt + 128 * 68;     // [128][68] k-major
    float* sV  = sKt + 128 * 68;     // [64][132]
    float* sS  = sV + 64 * 132;      // [64][65]
    float* sM  = sS + 64 * 65;
    float* sL  = sM + 64;
    float* sF  = sL + 64;

    const int h = blockIdx.y, q0 = blockIdx.x * 64;
    const int tid = threadIdx.x;
    const int tx = tid & 15, ty = tid >> 4;

    for (int i = tid; i < 64 * 128; i += 256) {
        int r = i >> 7, c = i & 127;
        sQt[c * 68 + r] = Qm[(size_t)(q0 + r) * 2048 + h * HD + c];
    }
    if (tid < 64) { sM[tid] = -INFINITY; sL[tid] = 0.f; }
    float o[4][8] = {};
    __syncthreads();

    for (int kt = 0; kt <= blockIdx.x; kt++) {
        int k0 = kt * 64;
        for (int i = tid; i < 64 * 128; i += 256) {
            int r = i >> 7, c = i & 127;
            sKt[c * 68 + r] = Km[(size_t)(k0 + r) * HD + c];
            sV[r * 132 + c] = qkv[(size_t)(k0 + r) * QKV_N + QDIM + HD + c];
        }
        __syncthreads();

        float s[4][4] = {};
        #pragma unroll 8
        for (int kk = 0; kk < 128; kk++) {
            float4 a4 = *(const float4*)&sQt[kk * 68 + ty * 4];
            float4 b4 = *(const float4*)&sKt[kk * 68 + tx * 4];
            float a[4] = {a4.x, a4.y, a4.z, a4.w};
            float b[4] = {b4.x, b4.y, b4.z, b4.w};
            #pragma unroll
            for (int i = 0; i < 4; i++)
                #pragma unroll
                for (int j = 0; j < 4; j++)
                    s[i][j] = fmaf(a[i], b[j], s[i][j]);
        }
        #pragma unroll
        for (int i = 0; i < 4; i++)
            #pragma unroll
            for (int j = 0; j < 4; j++) {
                int gr = q0 + ty * 4 + i, gc = k0 + tx * 4 + j;
                sS[(ty * 4 + i) * 65 + tx * 4 + j] = (gc <= gr) ? s[i][j] * SCALE : -1e30f;
            }
        __syncthreads();

        // online softmax: 4 threads per row
        {
            int row = tid >> 2, sub = tid & 3;
            float mx = -INFINITY;
            for (int c = sub; c < 64; c += 4) mx = fmaxf(mx, sS[row * 65 + c]);
            mx = fmaxf(mx, __shfl_xor_sync(0xffffffffu, mx, 1));
            mx = fmaxf(mx, __shfl_xor_sync(0xffffffffu, mx, 2));
            float mo = sM[row];
            float mn = fmaxf(mo, mx);
            float ssum = 0.f;
            for (int c = sub; c < 64; c += 4) {
                float pv = __expf(sS[row * 65 + c] - mn);
                sS[row * 65 + c] = pv;
                ssum += pv;
            }
            ssum += __shfl_xor_sync(0xffffffffu, ssum, 1);
            ssum += __shfl_xor_sync(0xffffffffu, ssum, 2);
            if (sub == 0) {
                float f = __expf(mo - mn);
                sM[row] = mn;
                sL[row] = sL[row] * f + ssum;
                sF[row] = f;
            }
        }
        __syncthreads();

        float f[4];
        #pragma unroll
        for (int i = 0; i < 4; i++) f[i] = sF[ty * 4 + i];
        #pragma unroll
        for (int i = 0; i < 4; i++)
            #pragma unroll
            for (int j = 0; j < 8; j++) o[i][j] *= f[i];

        #pragma unroll 4
        for (int kk = 0; kk < 64; kk++) {
            float p[4];
            #pragma unroll
            for (int i = 0; i < 4; i++) p[i] = sS[(ty * 4 + i) * 65 + kk];
            float4 v0 = *(const float4*)&sV[kk * 132 + tx * 8];
            float4 v1 = *(const float4*)&sV[kk * 132 + tx * 8 + 4];
            float v[8] = {v0.x, v0.y, v0.z, v0.w, v1.x, v1.y, v1.z, v1.w};
            #pragma unroll
            for (int i = 0; i < 4; i++)
                #pragma unroll
                for (int j = 0; j < 8; j++)
                    o[i][j] = fmaf(p[i], v[j], o[i][j]);
        }
        __syncthreads();
    }

    #pragma unroll
    for (int i = 0; i < 4; i++) {
        float inv = 1.f / sL[ty * 4 + i];
        size_t base = (size_t)(q0 + ty * 4 + i) * 2048 + h * HD + tx * 8;
        #pragma unroll
        for (int j = 0; j < 8; j++) Om[base + j] = o[i][j] * inv;
    }
}

// ------------------------- router / topk / scan / fill ---------------------
__global__ __launch_bounds__(256) void router_k(const float* __restrict__ X,
                                                const float* __restrict__ Wr)
{
    __shared__ float part[8][32];
    int t = blockIdx.x;
    int e = threadIdx.x & 31, p = threadIdx.x >> 5;
    const float* xr = X + (size_t)t * HID;
    float s = 0.f;
    for (int k = p * 128; k < p * 128 + 128; k++) s = fmaf(xr[k], Wr[k * 32 + e], s);
    part[p][e] = s;
    __syncthreads();
    if (threadIdx.x < 32) {
        float logit = 0.f;
        #pragma unroll
        for (int q = 0; q < 8; q++) logit += part[q][e];
        float m = logit;
        for (int d = 16; d; d >>= 1) m = fmaxf(m, __shfl_xor_sync(0xffffffffu, m, d));
        float ex = __expf(logit - m);
        float cur = ex;
        float wsel[3]; int isel[3];
        #pragma unroll
        for (int kk = 0; kk < 3; kk++) {
            float v = cur; int idx = e;
            for (int d = 16; d; d >>= 1) {
                float v2 = __shfl_xor_sync(0xffffffffu, v, d);
                int   i2 = __shfl_xor_sync(0xffffffffu, idx, d);
                if (v2 > v || (v2 == v && i2 < idx)) { v = v2; idx = i2; }
            }
            wsel[kk] = v; isel[kk] = idx;
            if (e == idx) cur = -1.f;
        }
        float tot = wsel[0] + wsel[1] + wsel[2];
        if (e < 3) { g_topi[t * 3 + e] = isel[e]; g_topw[t * 3 + e] = wsel[e] / tot; }
        if (e == 0) {
            atomicAdd(&g_cnt[isel[0]], 1);
            atomicAdd(&g_cnt[isel[1]], 1);
            atomicAdd(&g_cnt[isel[2]], 1);
        }
    }
}

__global__ void scan_k()
{
    int e = threadIdx.x;
    int c = g_cnt[e];
    int x = c;
    for (int d = 1; d < 32; d <<= 1) {
        int y = __shfl_up_sync(0xffffffffu, x, d);
        if (e >= d) x += y;
    }
    int excl = x - c;
    g_off[e] = excl;
    g_fill[e] = excl;
}

__global__ void fill_k()
{
    int t = blockIdx.x * 256 + threadIdx.x;
    if (t < SEQ) {
        #pragma unroll
        for (int k = 0; k < 3; k++) {
            int e = g_topi[t * 3 + k];
            int slot = atomicAdd(&g_fill[e], 1);
            g_ptok[slot] = t;
            g_pw[slot] = g_topw[t * 3 + k];
        }
    }
}

// ------------------------- MoE expert GEMMs --------------------------------
// gemm1: act = silu(Xg @ Wg) * (Xg @ Wu), gathered rows, fused dual acc
__global__ __launch_bounds__(256) void moe1_k(const float* __restrict__ X,
                                              const float* __restrict__ Wgu)
{
    int e = blockIdx.z;
    int cnt = g_cnt[e];
    int m0 = blockIdx.y * 128;
    if (m0 >= cnt) return;
    int off = g_off[e];
    int n0 = blockIdx.x * 64;
    const float* B = Wgu + (size_t)e * HID * (2 * IDIM);

    __shared__ float sA[16][132];
    __shared__ float sBg[16][68];
    __shared__ float sBu[16][68];
    __shared__ int sTok[128];
    int tid = threadIdx.x;
    if (tid < 128) {
        int gr = m0 + tid;
        sTok[tid] = (gr < cnt) ? g_ptok[off + gr] : -1;
    }
    __syncthreads();
    int tx = tid & 7, ty = tid >> 3;
    float accg[4][8] = {}, accu[4][8] = {};
    for (int k0 = 0; k0 < HID; k0 += 16) {
        #pragma unroll
        for (int i = tid; i < 2048; i += 256) {
            int m = i >> 4, kk = i & 15;
            int tk = sTok[m];
            sA[kk][m] = (tk >= 0) ? X[(size_t)tk * HID + k0 + kk] : 0.f;
        }
        #pragma unroll
        for (int i = tid; i < 1024; i += 256) {
            int kk = i >> 6, n = i & 63;
            size_t base = (size_t)(k0 + kk) * (2 * IDIM) + n0 + n;
            sBg[kk][n] = B[base];
            sBu[kk][n] = B[base + IDIM];
        }
        __syncthreads();
        #pragma unroll
        for (int kk = 0; kk < 16; kk++) {
            float4 a4 = *(const float4*)&sA[kk][ty * 4];
            float4 g0 = *(const float4*)&sBg[kk][tx * 8];
            float4 g1 = *(const float4*)&sBg[kk][tx * 8 + 4];
            float4 u0 = *(const float4*)&sBu[kk][tx * 8];
            float4 u1 = *(const float4*)&sBu[kk][tx * 8 + 4];
            float a[4] = {a4.x, a4.y, a4.z, a4.w};
            float bg[8] = {g0.x, g0.y, g0.z, g0.w, g1.x, g1.y, g1.z, g1.w};
            float bu[8] = {u0.x, u0.y, u0.z, u0.w, u1.x, u1.y, u1.z, u1.w};
            #pragma unroll
            for (int i = 0; i < 4; i++)
                #pragma unroll
                for (int j = 0; j < 8; j++) {
                    accg[i][j] = fmaf(a[i], bg[j], accg[i][j]);
                    accu[i][j] = fmaf(a[i], bu[j], accu[i][j]);
                }
        }
        __syncthreads();
    }
    #pragma unroll
    for (int i = 0; i < 4; i++) {
        int r = m0 + ty * 4 + i;
        if (r < cnt) {
            #pragma unroll
            for (int j = 0; j < 8; j++) {
                float g = accg[i][j], u = accu[i][j];
                g_acte[(size_t)(off + r) * IDIM + n0 + tx * 8 + j] = g / (1.f + expf(-g)) * u;
            }
        }
    }
}

// gemm2: out[tok] += w * (act @ Wd)
__global__ __launch_bounds__(256) void moe2_k(const float* __restrict__ Wd,
                                              float* __restrict__ out)
{
    int e = blockIdx.z;
    int cnt = g_cnt[e];
    int m0 = blockIdx.y * 128;
    if (m0 >= cnt) return;
    int off = g_off[e];
    int n0 = blockIdx.x * 64;
    const float* B = Wd + (size_t)e * IDIM * HID;
    const float* A = g_acte + (size_t)off * IDIM;

    __shared__ float sA[16][132];
    __shared__ float sB[16][68];
    int tid = threadIdx.x;
    int tx = tid & 7, ty = tid >> 3;
    float acc[4][8] = {};
    for (int k0 = 0; k0 < IDIM; k0 += 16) {
        #pragma unroll
        for (int i = tid; i < 2048; i += 256) {
            int m = i >> 4, kk = i & 15;
            sA[kk][m] = (m0 + m < cnt) ? A[(size_t)(m0 + m) * IDIM + k0 + kk] : 0.f;
        }
        #pragma unroll
        for (int i = tid; i < 1024; i += 256) {
            int kk = i >> 6, n = i & 63;
            sB[kk][n] = B[(size_t)(k0 + kk) * HID + n0 + n];
        }
        __syncthreads();
        #pragma unroll
        for (int kk = 0; kk < 16; kk++) {
            float4 a4 = *(const float4*)&sA[kk][ty * 4];
            float4 b0 = *(const float4*)&sB[kk][tx * 8];
            float4 b1 = *(const float4*)&sB[kk][tx * 8 + 4];
            float a[4] = {a4.x, a4.y, a4.z, a4.w};
            float b[8] = {b0.x, b0.y, b0.z, b0.w, b1.x, b1.y, b1.z, b1.w};
            #pragma unroll
            for (int i = 0; i < 4; i++)
                #pragma unroll
                for (int j = 0; j < 8; j++)
                    acc[i][j] = fmaf(a[i], b[j], acc[i][j]);
        }
        __syncthreads();
    }
    #pragma unroll
    for (int i = 0; i < 4; i++) {
        int r = m0 + ty * 4 + i;
        if (r < cnt) {
            int tok = g_ptok[off + r];
            float w = g_pw[off + r];
            #pragma unroll
            for (int j = 0; j < 8; j++)
                atomicAdd(&out[(size_t)tok * HID + n0 + tx * 8 + j], w * acc[i][j]);
        }
    }
}

// ------------------------- launch -------------------------------------------
extern "C" void kernel_launch(void* const* d_in, const int* in_sizes, int n_in,
                              void* d_out, int out_size)
{
    const float* hidden   = (const float*)d_in[0];
    const float* w_in     = (const float*)d_in[1];
    const float* w_qkv    = (const float*)d_in[2];
    const float* w_inter  = (const float*)d_in[3];
    const float* w_q      = (const float*)d_in[4];
    const float* w_o      = (const float*)d_in[5];
    const float* w_post   = (const float*)d_in[6];
    const float* w_guse   = (const float*)d_in[7];
    const float* w_dse    = (const float*)d_in[8];
    const float* w_router = (const float*)d_in[9];
    const float* w_gue    = (const float*)d_in[10];
    const float* w_de     = (const float*)d_in[11];
    const int*   pos      = (const int*)d_in[12];
    float* out = (float*)d_out;

    float *hnorm, *qkv, *qn, *qproj, *krope, *attnout, *resid2, *h2, *gu, *actse;
    cudaGetSymbolAddress((void**)&hnorm,   g_hnorm);
    cudaGetSymbolAddress((void**)&qkv,     g_qkv);
    cudaGetSymbolAddress((void**)&qn,      g_qn);
    cudaGetSymbolAddress((void**)&qproj,   g_qproj);
    cudaGetSymbolAddress((void**)&krope,   g_krope);
    cudaGetSymbolAddress((void**)&attnout, g_attnout);
    cudaGetSymbolAddress((void**)&resid2,  g_resid2);
    cudaGetSymbolAddress((void**)&h2,      g_h2);
    cudaGetSymbolAddress((void**)&gu,      g_gu);
    cudaGetSymbolAddress((void**)&actse,   g_actse);

    cudaFuncSetAttribute(attn_k, cudaFuncAttributeMaxDynamicSharedMemorySize, ATTN_SMEM);

    zero_counts_k<<<1, 32>>>();
    rmsnorm_k<<<SEQ, 256>>>(hidden, w_in, hnorm, HID, HID, HID);
    sgemm_k<<<dim3(QKV_N/64, SEQ/128), 256>>>(hnorm, w_qkv, qkv,
                                              SEQ, QKV_N, HID, HID, QKV_N, QKV_N, nullptr);
    rmsnorm_k<<<SEQ, 256>>>(qkv, w_inter, qn, QDIM, QKV_N, QDIM);
    sgemm_k<<<dim3(2048/64, SEQ/128), 256>>>(qn, w_q, qproj,
                                             SEQ, 2048, QDIM, QDIM, 2048, 2048, nullptr);
    rope_k<<<SEQ, 256>>>(qproj, qkv, krope, pos);
    attn_k<<<dim3(SEQ/64, NHEAD), 256, ATTN_SMEM>>>(qproj, krope, qkv, attnout);
    sgemm_k<<<dim3(HID/64, SEQ/128), 256>>>(attnout, w_o, resid2,
                                            SEQ, HID, 2048, 2048, HID, HID, hidden);
    rmsnorm_k<<<SEQ, 256>>>(resid2, w_post, h2, HID, HID, HID);
    sgemm_k<<<dim3(2048/64, SEQ/128), 256>>>(h2, w_guse, gu,
                                             SEQ, 2048, HID, HID, 2048, 2048, nullptr);
    silu_mul_k<<<SEQ * IDIM / 256, 256>>>(gu, actse);
    sgemm_k<<<dim3(HID/64, SEQ/128), 256>>>(actse, w_dse, out,
                                            SEQ, HID, IDIM, IDIM, HID, HID, resid2);
    router_k<<<SEQ, 256>>>(h2, w_router);
    scan_k<<<1, 32>>>();
    fill_k<<<SEQ / 256, 256>>>();
    moe1_k<<<dim3(IDIM/64, 16, NEXP), 256>>>(h2, w_gue);
    moe2_k<<<dim3(HID/64, 16, NEXP), 256>>>(w_de, out);
}

// round 3
// speedup vs baseline: 2.0516x; 2.0516x over previous
#include <cuda_runtime.h>
#include <cuda_bf16.h>
#include <math.h>
#include <stdint.h>

#define SEQ 2048
#define HID 1024
#define NHEAD 16
#define HD 128
#define QDIM 512
#define NEXP 32
#define IDIM 1024
#define QKV_N 768
#define SCALE 0.08838834764831845f   // 1/sqrt(128)

// ------------------------- device scratch ----------------------------------
__device__ float g_hnorm[SEQ*HID];
__device__ float g_qkv[SEQ*QKV_N];
__device__ float g_qn[SEQ*QDIM];
__device__ float g_qproj[SEQ*NHEAD*HD];
__device__ float g_krope[SEQ*HD];
__device__ float g_attnout[SEQ*NHEAD*HD];
__device__ float g_resid2[SEQ*HID];
__device__ float g_h2[SEQ*HID];
__device__ float g_actse[SEQ*IDIM];
__device__ float g_acte[SEQ*3*IDIM];
__device__ int   g_topi[SEQ*3];
__device__ float g_topw[SEQ*3];
__device__ int   g_cnt[NEXP];
__device__ int   g_off[NEXP];
__device__ int   g_fill[NEXP];
__device__ int   g_ptok[SEQ*3];
__device__ float g_pw[SEQ*3];

// ------------------------- warp-mma helpers --------------------------------
__device__ __forceinline__ uint32_t s2u(const void* p) {
    uint32_t a;
    asm("{ .reg .u64 t; cvta.to.shared.u64 t, %1; cvt.u32.u64 %0, t; }" : "=r"(a) : "l"(p));
    return a;
}

__device__ __forceinline__ void ldsm4(uint32_t* r, uint32_t addr) {
    asm volatile("ldmatrix.sync.aligned.m8n8.x4.shared.b16 {%0,%1,%2,%3}, [%4];"
        : "=r"(r[0]), "=r"(r[1]), "=r"(r[2]), "=r"(r[3]) : "r"(addr));
}
__device__ __forceinline__ void ldsm4t(uint32_t* r, uint32_t addr) {
    asm volatile("ldmatrix.sync.aligned.m8n8.x4.trans.shared.b16 {%0,%1,%2,%3}, [%4];"
        : "=r"(r[0]), "=r"(r[1]), "=r"(r[2]), "=r"(r[3]) : "r"(addr));
}
__device__ __forceinline__ void mma16816(float* c, const uint32_t* a, uint32_t b0, uint32_t b1) {
    asm volatile("mma.sync.aligned.m16n8k16.row.col.f32.bf16.bf16.f32 "
        "{%0,%1,%2,%3}, {%4,%5,%6,%7}, {%8,%9}, {%0,%1,%2,%3};"
        : "+f"(c[0]), "+f"(c[1]), "+f"(c[2]), "+f"(c[3])
        : "r"(a[0]), "r"(a[1]), "r"(a[2]), "r"(a[3]), "r"(b0), "r"(b1));
}

__device__ __forceinline__ uint32_t pack_hi(float f0, float f1) {
    __nv_bfloat162 h = __floats2bfloat162_rn(f0, f1);
    return *(uint32_t*)&h;
}
__device__ __forceinline__ uint32_t pack_lo(float f0, float f1, uint32_t hibits) {
    __nv_bfloat162 h = *(__nv_bfloat162*)&hibits;
    __nv_bfloat162 l = __floats2bfloat162_rn(f0 - __bfloat162float(h.x),
                                             f1 - __bfloat162float(h.y));
    return *(uint32_t*)&l;
}

// smem layout (bytes)
#define LDA 40
#define LDB 136
#define OFF_AH 0
#define OFF_AL (128*LDA*2)
#define OFF_BH (OFF_AL + 128*LDA*2)
#define OFF_BL (OFF_BH + 32*LDB*2)
#define OFF_TOK (OFF_BL + 32*LDB*2)
#define SMEM_TOTAL_G (OFF_TOK + 128*4)

// MODE 0: plain  C = A@B (+add)          (128 out cols / CTA)
// MODE 1: gated  C = silu(A@Bg)*(A@Bu)   (64 out cols / CTA, up at +upOff)
// MODE 2: moe gathered gated -> C rows off+r
// MODE 3: moe scatter: out[tok] += w * (A@B)
template<int MODE>
__global__ __launch_bounds__(256) void gemm_tc(
    const float* __restrict__ A, const float* __restrict__ B,
    float* __restrict__ C, const float* __restrict__ add,
    int K, int lda, int ldb, int ldc, int upOff, size_t bStride)
{
    int cnt = 0, off = 0;
    if (MODE >= 2) {
        int e = blockIdx.z;
        cnt = g_cnt[e];
        if ((int)blockIdx.y * 128 >= cnt) return;
        off = g_off[e];
        B += bStride * e;
    }
    const int m0 = blockIdx.y * 128;
    const int nb = blockIdx.x * ((MODE == 1 || MODE == 2) ? 64 : 128);

    __shared__ char sm[SMEM_TOTAL_G];
    __nv_bfloat16* sAh = (__nv_bfloat16*)(sm + OFF_AH);
    __nv_bfloat16* sAl = (__nv_bfloat16*)(sm + OFF_AL);
    __nv_bfloat16* sBh = (__nv_bfloat16*)(sm + OFF_BH);
    __nv_bfloat16* sBl = (__nv_bfloat16*)(sm + OFF_BL);
    int* sTok = (int*)(sm + OFF_TOK);
    const uint32_t uAh = s2u(sAh), uAl = s2u(sAl), uBh = s2u(sBh), uBl = s2u(sBl);

    const int tid = threadIdx.x;
    const int wid = tid >> 5, lane = tid & 31;
    const int wm = wid >> 2, wn = wid & 3;

    if (MODE == 2 && tid < 128) {
        int gr = m0 + tid;
        sTok[tid] = (gr < cnt) ? g_ptok[off + gr] : -1;
    }
    __syncthreads();

    float acc[4][4][4] = {};

    // ldmatrix lane address components
    const int lrow = lane & 15, lcol8 = (lane >> 4) * 8;

    const int nkt = K >> 5;
    for (int c = 0; c < nkt; c++) {
        const int k0 = c << 5;
        // ---- A tile: 128 rows x 32 k ----
        #pragma unroll
        for (int it = 0; it < 4; it++) {
            int i = tid + it * 256;          // float4 index, 1024 total
            int m = i >> 3;
            int kq = (i & 7) << 2;
            float4 v;
            if (MODE == 2) {
                int tk = sTok[m];
                v = (tk >= 0) ? *(const float4*)(A + (size_t)tk * lda + k0 + kq)
                              : make_float4(0.f, 0.f, 0.f, 0.f);
            } else if (MODE == 3) {
                v = (m0 + m < cnt) ? *(const float4*)(A + (size_t)(off + m0 + m) * lda + k0 + kq)
                                   : make_float4(0.f, 0.f, 0.f, 0.f);
            } else {
                v = *(const float4*)(A + (size_t)(m0 + m) * lda + k0 + kq);
            }
            uint32_t h0 = pack_hi(v.x, v.y), h1 = pack_hi(v.z, v.w);
            uint32_t l0 = pack_lo(v.x, v.y, h0), l1 = pack_lo(v.z, v.w, h1);
            uint32_t* ph = (uint32_t*)(sAh + m * LDA + kq);
            uint32_t* pl = (uint32_t*)(sAl + m * LDA + kq);
            ph[0] = h0; ph[1] = h1;
            pl[0] = l0; pl[1] = l1;
        }
        // ---- B tile: 32 k x 128 n ----
        #pragma unroll
        for (int it = 0; it < 4; it++) {
            int i = tid + it * 256;          // float4 index, 1024 total
            int kk = i >> 5;
            int n4 = (i & 31) << 2;
            int col;
            if (MODE == 1 || MODE == 2) col = (n4 < 64) ? nb + n4 : upOff + nb + (n4 - 64);
            else                        col = nb + n4;
            float4 v = *(const float4*)(B + (size_t)(k0 + kk) * ldb + col);
            uint32_t h0 = pack_hi(v.x, v.y), h1 = pack_hi(v.z, v.w);
            uint32_t l0 = pack_lo(v.x, v.y, h0), l1 = pack_lo(v.z, v.w, h1);
            uint32_t* ph = (uint32_t*)(sBh + kk * LDB + n4);
            uint32_t* pl = (uint32_t*)(sBl + kk * LDB + n4);
            ph[0] = h0; ph[1] = h1;
            pl[0] = l0; pl[1] = l1;
        }
        __syncthreads();

        #pragma unroll
        for (int ks = 0; ks < 2; ks++) {
            uint32_t ah[4][4], al[4][4], bh[2][4], bl[2][4];
            #pragma unroll
            for (int mf = 0; mf < 4; mf++) {
                uint32_t ro = (uint32_t)((wm * 64 + mf * 16 + lrow) * LDA + ks * 16 + lcol8) * 2;
                ldsm4(ah[mf], uAh + ro);
                ldsm4(al[mf], uAl + ro);
            }
            #pragma unroll
            for (int nh = 0; nh < 2; nh++) {
                uint32_t ro = (uint32_t)((ks * 16 + lrow) * LDB + wn * 32 + nh * 16 + lcol8) * 2;
                ldsm4t(bh[nh], uBh + ro);
                ldsm4t(bl[nh], uBl + ro);
            }
            #pragma unroll
            for (int mf = 0; mf < 4; mf++)
                #pragma unroll
                for (int nf = 0; nf < 4; nf++) {
                    uint32_t bh0 = bh[nf >> 1][(nf & 1) * 2], bh1 = bh[nf >> 1][(nf & 1) * 2 + 1];
                    uint32_t bl0 = bl[nf >> 1][(nf & 1) * 2], bl1 = bl[nf >> 1][(nf & 1) * 2 + 1];
                    mma16816(acc[mf][nf], ah[mf], bh0, bh1);
                    mma16816(acc[mf][nf], ah[mf], bl0, bl1);
                    mma16816(acc[mf][nf], al[mf], bh0, bh1);
                }
        }
        __syncthreads();
    }

    // ---- epilogue ----
    const int r4 = lane >> 2, c2 = (lane & 3) * 2;
    if (MODE == 0) {
        #pragma unroll
        for (int mf = 0; mf < 4; mf++) {
            #pragma unroll
            for (int nf = 0; nf < 4; nf++) {
                int col = nb + wn * 32 + nf * 8 + c2;
                size_t r1 = (size_t)(m0 + wm * 64 + mf * 16 + r4);
                size_t r2 = r1 + 8;
                float v0 = acc[mf][nf][0], v1 = acc[mf][nf][1];
                float v2 = acc[mf][nf][2], v3 = acc[mf][nf][3];
                if (add) {
                    v0 += add[r1 * ldc + col]; v1 += add[r1 * ldc + col + 1];
                    v2 += add[r2 * ldc + col]; v3 += add[r2 * ldc + col + 1];
                }
                *(float2*)(C + r1 * ldc + col) = make_float2(v0, v1);
                *(float2*)(C + r2 * ldc + col) = make_float2(v2, v3);
            }
        }
    } else if (MODE == 1 || MODE == 2) {
        float* sG = (float*)sm;              // [128][65]
        if (wn < 2) {
            #pragma unroll
            for (int mf = 0; mf < 4; mf++)
                #pragma unroll
                for (int nf = 0; nf < 4; nf++) {
                    int col = wn * 32 + nf * 8 + c2;
                    int rr1 = wm * 64 + mf * 16 + r4, rr2 = rr1 + 8;
                    sG[rr1 * 65 + col]     = acc[mf][nf][0];
                    sG[rr1 * 65 + col + 1] = acc[mf][nf][1];
                    sG[rr2 * 65 + col]     = acc[mf][nf][2];
                    sG[rr2 * 65 + col + 1] = acc[mf][nf][3];
                }
        }
        __syncthreads();
        if (wn >= 2) {
            #pragma unroll
            for (int mf = 0; mf < 4; mf++)
                #pragma unroll
                for (int nf = 0; nf < 4; nf++) {
                    int col = (wn - 2) * 32 + nf * 8 + c2;
                    int rr1 = wm * 64 + mf * 16 + r4, rr2 = rr1 + 8;
                    #pragma unroll
                    for (int half = 0; half < 2; half++) {
                        int rr = half ? rr2 : rr1;
                        bool ok = (MODE == 1) || (m0 + rr < cnt);
                        if (ok) {
                            size_t row = (MODE == 1) ? (size_t)(m0 + rr) : (size_t)(off + m0 + rr);
                            float g0 = sG[rr * 65 + col], g1 = sG[rr * 65 + col + 1];
                            float u0 = acc[mf][nf][half * 2], u1 = acc[mf][nf][half * 2 + 1];
                            float o0 = g0 / (1.f + expf(-g0)) * u0;
                            float o1 = g1 / (1.f + expf(-g1)) * u1;
                            *(float2*)(C + row * ldc + nb + col) = make_float2(o0, o1);
                        }
                    }
                }
        }
    } else {  // MODE 3
        #pragma unroll
        for (int mf = 0; mf < 4; mf++) {
            int rr1 = wm * 64 + mf * 16 + r4, rr2 = rr1 + 8;
            #pragma unroll
            for (int half = 0; half < 2; half++) {
                int rr = half ? rr2 : rr1;
                if (m0 + rr < cnt) {
                    int tok = g_ptok[off + m0 + rr];
                    float w = g_pw[off + m0 + rr];
                    float* dst = C + (size_t)tok * ldc;
                    #pragma unroll
                    for (int nf = 0; nf < 4; nf++) {
                        int col = nb + wn * 32 + nf * 8 + c2;
                        atomicAdd(dst + col,     w * acc[mf][nf][half * 2]);
                        atomicAdd(dst + col + 1, w * acc[mf][nf][half * 2 + 1]);
                    }
                }
            }
        }
    }
}

// ------------------------- small utility kernels ---------------------------
__global__ void zero_counts_k() {
    if (threadIdx.x < NEXP) g_cnt[threadIdx.x] = 0;
}

__global__ void rmsnorm_k(const float* __restrict__ x, const float* __restrict__ w,
                          float* __restrict__ y, int cols, int ldx, int ldy)
{
    int row = blockIdx.x;
    const float* xr = x + (size_t)row * ldx;
    float ss = 0.f;
    for (int c = threadIdx.x; c < cols; c += 256) { float v = xr[c]; ss = fmaf(v, v, ss); }
    __shared__ float red[256];
    red[threadIdx.x] = ss;
    __syncthreads();
    for (int s = 128; s > 0; s >>= 1) {
        if (threadIdx.x < s) red[threadIdx.x] += red[threadIdx.x + s];
        __syncthreads();
    }
    float r = rsqrtf(red[0] / (float)cols + 1e-5f);
    float* yr = y + (size_t)row * ldy;
    for (int c = threadIdx.x; c < cols; c += 256) yr[c] = xr[c] * r * w[c];
}

__global__ void rope_k(float* __restrict__ qp, const float* __restrict__ qkv,
                       float* __restrict__ kout, const int* __restrict__ pos)
{
    __shared__ float sinv[64];
    int t = blockIdx.x;
    if (threadIdx.x < 64) {
        double e = exp(-((double)(2 * threadIdx.x) / 128.0) * log(500000.0));
        sinv[threadIdx.x] = (float)e;
    }
    __syncthreads();
    float p = (float)pos[t];
    for (int idx = threadIdx.x; idx < NHEAD * 64; idx += 256) {
        int hh = idx >> 6, i = idx & 63;
        float f = p * sinv[i];
        float sn, cs; sincosf(f, &sn, &cs);
        float* b = qp + (size_t)t * (NHEAD * HD) + hh * HD;
        float x1 = b[i], x2 = b[i + 64];
        b[i]      = x1 * cs - x2 * sn;
        b[i + 64] = x2 * cs + x1 * sn;
    }
    if (threadIdx.x < 64) {
        int i = threadIdx.x;
        float f = p * sinv[i];
        float sn, cs; sincosf(f, &sn, &cs);
        const float* kb = qkv + (size_t)t * QKV_N + QDIM;
        float x1 = kb[i], x2 = kb[i + 64];
        kout[(size_t)t * HD + i]      = x1 * cs - x2 * sn;
        kout[(size_t)t * HD + i + 64] = x2 * cs + x1 * sn;
    }
}

// ------------------------- attention (causal MQA, flash-style) -------------
#define ATTN_SMEM ((128*68*2 + 64*132 + 64*65 + 192) * 4)
__global__ __launch_bounds__(256) void attn_k(
    const float* __restrict__ Qm, const float* __restrict__ Km,
    const float* __restrict__ qkv, float* __restrict__ Om)
{
    extern __shared__ float smf[];
    float* sQt = smf;
    float* sKt = sQt + 128 * 68;
    float* sV  = sKt + 128 * 68;
    float* sS  = sV + 64 * 132;
    float* sM  = sS + 64 * 65;
    float* sL  = sM + 64;
    float* sF  = sL + 64;

    const int h = blockIdx.y, q0 = blockIdx.x * 64;
    const int tid = threadIdx.x;
    const int tx = tid & 15, ty = tid >> 4;

    for (int i = tid; i < 64 * 128; i += 256) {
        int r = i >> 7, c = i & 127;
        sQt[c * 68 + r] = Qm[(size_t)(q0 + r) * 2048 + h * HD + c];
    }
    if (tid < 64) { sM[tid] = -INFINITY; sL[tid] = 0.f; }
    float o[4][8] = {};
    __syncthreads();

    for (int kt = 0; kt <= blockIdx.x; kt++) {
        int k0 = kt * 64;
        for (int i = tid; i < 64 * 128; i += 256) {
            int r = i >> 7, c = i & 127;
            sKt[c * 68 + r] = Km[(size_t)(k0 + r) * HD + c];
            sV[r * 132 + c] = qkv[(size_t)(k0 + r) * QKV_N + QDIM + HD + c];
        }
        __syncthreads();

        float s[4][4] = {};
        #pragma unroll 8
        for (int kk = 0; kk < 128; kk++) {
            float4 a4 = *(const float4*)&sQt[kk * 68 + ty * 4];
            float4 b4 = *(const float4*)&sKt[kk * 68 + tx * 4];
            float a[4] = {a4.x, a4.y, a4.z, a4.w};
            float b[4] = {b4.x, b4.y, b4.z, b4.w};
            #pragma unroll
            for (int i = 0; i < 4; i++)
                #pragma unroll
                for (int j = 0; j < 4; j++)
                    s[i][j] = fmaf(a[i], b[j], s[i][j]);
        }
        #pragma unroll
        for (int i = 0; i < 4; i++)
            #pragma unroll
            for (int j = 0; j < 4; j++) {
                int gr = q0 + ty * 4 + i, gc = k0 + tx * 4 + j;
                sS[(ty * 4 + i) * 65 + tx * 4 + j] = (gc <= gr) ? s[i][j] * SCALE : -1e30f;
            }
        __syncthreads();

        {
            int row = tid >> 2, sub = tid & 3;
            float mx = -INFINITY;
            for (int c = sub; c < 64; c += 4) mx = fmaxf(mx, sS[row * 65 + c]);
            mx = fmaxf(mx, __shfl_xor_sync(0xffffffffu, mx, 1));
            mx = fmaxf(mx, __shfl_xor_sync(0xffffffffu, mx, 2));
            float mo = sM[row];
            float mn = fmaxf(mo, mx);
            float ssum = 0.f;
            for (int c = sub; c < 64; c += 4) {
                float pv = __expf(sS[row * 65 + c] - mn);
                sS[row * 65 + c] = pv;
                ssum += pv;
            }
            ssum += __shfl_xor_sync(0xffffffffu, ssum, 1);
            ssum += __shfl_xor_sync(0xffffffffu, ssum, 2);
            if (sub == 0) {
                float f = __expf(mo - mn);
                sM[row] = mn;
                sL[row] = sL[row] * f + ssum;
                sF[row] = f;
            }
        }
        __syncthreads();

        float f[4];
        #pragma unroll
        for (int i = 0; i < 4; i++) f[i] = sF[ty * 4 + i];
        #pragma unroll
        for (int i = 0; i < 4; i++)
            #pragma unroll
            for (int j = 0; j < 8; j++) o[i][j] *= f[i];

        #pragma unroll 4
        for (int kk = 0; kk < 64; kk++) {
            float p[4];
            #pragma unroll
            for (int i = 0; i < 4; i++) p[i] = sS[(ty * 4 + i) * 65 + kk];
            float4 v0 = *(const float4*)&sV[kk * 132 + tx * 8];
            float4 v1 = *(const float4*)&sV[kk * 132 + tx * 8 + 4];
            float v[8] = {v0.x, v0.y, v0.z, v0.w, v1.x, v1.y, v1.z, v1.w};
            #pragma unroll
            for (int i = 0; i < 4; i++)
                #pragma unroll
                for (int j = 0; j < 8; j++)
                    o[i][j] = fmaf(p[i], v[j], o[i][j]);
        }
        __syncthreads();
    }

    #pragma unroll
    for (int i = 0; i < 4; i++) {
        float inv = 1.f / sL[ty * 4 + i];
        size_t base = (size_t)(q0 + ty * 4 + i) * 2048 + h * HD + tx * 8;
        #pragma unroll
        for (int j = 0; j < 8; j++) Om[base + j] = o[i][j] * inv;
    }
}

// ------------------------- router / topk / scan / fill ---------------------
__global__ __launch_bounds__(256) void router_k(const float* __restrict__ X,
                                                const float* __restrict__ Wr)
{
    __shared__ float part[8][32];
    int t = blockIdx.x;
    int e = threadIdx.x & 31, p = threadIdx.x >> 5;
    const float* xr = X + (size_t)t * HID;
    float s = 0.f;
    for (int k = p * 128; k < p * 128 + 128; k++) s = fmaf(xr[k], Wr[k * 32 + e], s);
    part[p][e] = s;
    __syncthreads();
    if (threadIdx.x < 32) {
        float logit = 0.f;
        #pragma unroll
        for (int q = 0; q < 8; q++) logit += part[q][e];
        float m = logit;
        for (int d = 16; d; d >>= 1) m = fmaxf(m, __shfl_xor_sync(0xffffffffu, m, d));
        float ex = __expf(logit - m);
        float cur = ex;
        float wsel[3]; int isel[3];
        #pragma unroll
        for (int kk = 0; kk < 3; kk++) {
            float v = cur; int idx = e;
            for (int d = 16; d; d >>= 1) {
                float v2 = __shfl_xor_sync(0xffffffffu, v, d);
                int   i2 = __shfl_xor_sync(0xffffffffu, idx, d);
                if (v2 > v || (v2 == v && i2 < idx)) { v = v2; idx = i2; }
            }
            wsel[kk] = v; isel[kk] = idx;
            if (e == idx) cur = -1.f;
        }
        float tot = wsel[0] + wsel[1] + wsel[2];
        if (e < 3) { g_topi[t * 3 + e] = isel[e]; g_topw[t * 3 + e] = wsel[e] / tot; }
        if (e == 0) {
            atomicAdd(&g_cnt[isel[0]], 1);
            atomicAdd(&g_cnt[isel[1]], 1);
            atomicAdd(&g_cnt[isel[2]], 1);
        }
    }
}

__global__ void scan_k()
{
    int e = threadIdx.x;
    int c = g_cnt[e];
    int x = c;
    for (int d = 1; d < 32; d <<= 1) {
        int y = __shfl_up_sync(0xffffffffu, x, d);
        if (e >= d) x += y;
    }
    int excl = x - c;
    g_off[e] = excl;
    g_fill[e] = excl;
}

__global__ void fill_k()
{
    int t = blockIdx.x * 256 + threadIdx.x;
    if (t < SEQ) {
        #pragma unroll
        for (int k = 0; k < 3; k++) {
            int e = g_topi[t * 3 + k];
            int slot = atomicAdd(&g_fill[e], 1);
            g_ptok[slot] = t;
            g_pw[slot] = g_topw[t * 3 + k];
        }
    }
}

// ------------------------- launch ------------------------------------------
extern "C" void kernel_launch(void* const* d_in, const int* in_sizes, int n_in,
                              void* d_out, int out_size)
{
    const float* hidden   = (const float*)d_in[0];
    const float* w_in     = (const float*)d_in[1];
    const float* w_qkv    = (const float*)d_in[2];
    const float* w_inter  = (const float*)d_in[3];
    const float* w_q      = (const float*)d_in[4];
    const float* w_o      = (const float*)d_in[5];
    const float* w_post   = (const float*)d_in[6];
    const float* w_guse   = (const float*)d_in[7];
    const float* w_dse    = (const float*)d_in[8];
    const float* w_router = (const float*)d_in[9];
    const float* w_gue    = (const float*)d_in[10];
    const float* w_de     = (const float*)d_in[11];
    const int*   pos      = (const int*)d_in[12];
    float* out = (float*)d_out;

    float *hnorm, *qkv, *qn, *qproj, *krope, *attnout, *resid2, *h2, *actse, *acte;
    cudaGetSymbolAddress((void**)&hnorm,   g_hnorm);
    cudaGetSymbolAddress((void**)&qkv,     g_qkv);
    cudaGetSymbolAddress((void**)&qn,      g_qn);
    cudaGetSymbolAddress((void**)&qproj,   g_qproj);
    cudaGetSymbolAddress((void**)&krope,   g_krope);
    cudaGetSymbolAddress((void**)&attnout, g_attnout);
    cudaGetSymbolAddress((void**)&resid2,  g_resid2);
    cudaGetSymbolAddress((void**)&h2,      g_h2);
    cudaGetSymbolAddress((void**)&actse,   g_actse);
    cudaGetSymbolAddress((void**)&acte,    g_acte);

    cudaFuncSetAttribute(attn_k, cudaFuncAttributeMaxDynamicSharedMemorySize, ATTN_SMEM);

    zero_counts_k<<<1, 32>>>();
    rmsnorm_k<<<SEQ, 256>>>(hidden, w_in, hnorm, HID, HID, HID);
    gemm_tc<0><<<dim3(QKV_N/128, SEQ/128), 256>>>(
        hnorm, w_qkv, qkv, nullptr, HID, HID, QKV_N, QKV_N, 0, 0);
    rmsnorm_k<<<SEQ, 256>>>(qkv, w_inter, qn, QDIM, QKV_N, QDIM);
    gemm_tc<0><<<dim3(2048/128, SEQ/128), 256>>>(
        qn, w_q, qproj, nullptr, QDIM, QDIM, 2048, 2048, 0, 0);
    rope_k<<<SEQ, 256>>>(qproj, qkv, krope, pos);
    attn_k<<<dim3(SEQ/64, NHEAD), 256, ATTN_SMEM>>>(qproj, krope, qkv, attnout);
    gemm_tc<0><<<dim3(HID/128, SEQ/128), 256>>>(
        attnout, w_o, resid2, hidden, 2048, 2048, HID, HID, 0, 0);
    rmsnorm_k<<<SEQ, 256>>>(resid2, w_post, h2, HID, HID, HID);
    gemm_tc<1><<<dim3(IDIM/64, SEQ/128), 256>>>(
        h2, w_guse, actse, nullptr, HID, HID, 2 * IDIM, IDIM, IDIM, 0);
    gemm_tc<0><<<dim3(HID/128, SEQ/128), 256>>>(
        actse, w_dse, out, resid2, IDIM, IDIM, HID, HID, 0, 0);
    router_k<<<SEQ, 256>>>(h2, w_router);
    scan_k<<<1, 32>>>();
    fill_k<<<SEQ / 256, 256>>>();
    gemm_tc<2><<<dim3(IDIM/64, 16, NEXP), 256>>>(
        h2, w_gue, acte, nullptr, HID, HID, 2 * IDIM, IDIM, IDIM, (size_t)HID * 2 * IDIM);
    gemm_tc<3><<<dim3(HID/128, 16, NEXP), 256>>>(
        acte, w_de, out, nullptr, IDIM, IDIM, HID, HID, 0, (size_t)IDIM * HID);
}

// round 4
// speedup vs baseline: 3.5537x; 1.7322x over previous
#include <cuda_runtime.h>
#include <cuda_bf16.h>
#include <math.h>
#include <stdint.h>

#define SEQ 2048
#define HID 1024
#define NHEAD 16
#define HD 128
#define QDIM 512
#define NEXP 32
#define IDIM 1024
#define QKV_N 768
#define SCALE 0.08838834764831845f   // 1/sqrt(128)

// ------------------------- device scratch ----------------------------------
__device__ float g_qkv[SEQ*QKV_N];
__device__ float g_qproj[SEQ*NHEAD*HD];
__device__ float g_resid2[SEQ*HID];
__device__ float g_h2[SEQ*HID];
__device__ float2 g_cs[SEQ*64];

__device__ __nv_bfloat16 g_hnh[SEQ*HID],  g_hnl[SEQ*HID];
__device__ __nv_bfloat16 g_qnh[SEQ*QDIM], g_qnl[SEQ*QDIM];
__device__ __nv_bfloat16 g_qh[SEQ*2048],  g_ql[SEQ*2048];
__device__ __nv_bfloat16 g_kth[128*SEQ],  g_ktl[128*SEQ];   // transposed [d][token]
__device__ __nv_bfloat16 g_vh[SEQ*128],   g_vl[SEQ*128];
__device__ __nv_bfloat16 g_aoh[SEQ*2048], g_aol[SEQ*2048];
__device__ __nv_bfloat16 g_h2h[SEQ*HID],  g_h2l[SEQ*HID];
__device__ __nv_bfloat16 g_aseh[SEQ*IDIM],g_asel[SEQ*IDIM];
__device__ __nv_bfloat16 g_aceh[SEQ*3*IDIM], g_acel[SEQ*3*IDIM];

__device__ int   g_topi[SEQ*3];
__device__ float g_topw[SEQ*3];
__device__ int   g_cnt[NEXP];
__device__ int   g_off[NEXP];
__device__ int   g_fill[NEXP];
__device__ int   g_ptok[SEQ*3];
__device__ float g_pw[SEQ*3];

// ------------------------- helpers -----------------------------------------
__device__ __forceinline__ uint32_t s2u(const void* p) {
    uint32_t a;
    asm("{ .reg .u64 t; cvta.to.shared.u64 t, %1; cvt.u32.u64 %0, t; }" : "=r"(a) : "l"(p));
    return a;
}
__device__ __forceinline__ void ldsm4(uint32_t* r, uint32_t addr) {
    asm volatile("ldmatrix.sync.aligned.m8n8.x4.shared.b16 {%0,%1,%2,%3}, [%4];"
        : "=r"(r[0]), "=r"(r[1]), "=r"(r[2]), "=r"(r[3]) : "r"(addr));
}
__device__ __forceinline__ void ldsm4t(uint32_t* r, uint32_t addr) {
    asm volatile("ldmatrix.sync.aligned.m8n8.x4.trans.shared.b16 {%0,%1,%2,%3}, [%4];"
        : "=r"(r[0]), "=r"(r[1]), "=r"(r[2]), "=r"(r[3]) : "r"(addr));
}
__device__ __forceinline__ void mma16816(float* c, const uint32_t* a, uint32_t b0, uint32_t b1) {
    asm volatile("mma.sync.aligned.m16n8k16.row.col.f32.bf16.bf16.f32 "
        "{%0,%1,%2,%3}, {%4,%5,%6,%7}, {%8,%9}, {%0,%1,%2,%3};"
        : "+f"(c[0]), "+f"(c[1]), "+f"(c[2]), "+f"(c[3])
        : "r"(a[0]), "r"(a[1]), "r"(a[2]), "r"(a[3]), "r"(b0), "r"(b1));
}
__device__ __forceinline__ uint32_t pack_hi(float f0, float f1) {
    __nv_bfloat162 h = __floats2bfloat162_rn(f0, f1);
    return *(uint32_t*)&h;
}
__device__ __forceinline__ uint32_t pack_lo(float f0, float f1, uint32_t hibits) {
    __nv_bfloat162 h = *(__nv_bfloat162*)&hibits;
    __nv_bfloat162 l = __floats2bfloat162_rn(f0 - __bfloat162float(h.x),
                                             f1 - __bfloat162float(h.y));
    return *(uint32_t*)&l;
}
__device__ __forceinline__ void split2(float a, float b, uint32_t& hi, uint32_t& lo) {
    hi = pack_hi(a, b);
    lo = pack_lo(a, b, hi);
}
// FFMA-only exp (rel err ~4e-5), avoids MUFU
__device__ __forceinline__ float fexp(float x) {
    x = fminf(fmaxf(x, -80.f), 80.f);
    float y = x * 1.4426950408889634f;
    float n = rintf(y);
    float f = y - n;
    float p = fmaf(f, 0.009618130f, 0.055504110f);
    p = fmaf(p, f, 0.240226507f);
    p = fmaf(p, f, 0.693147181f);
    p = fmaf(p, f, 1.0f);
    return p * __int_as_float(((int)n + 127) << 23);
}

// ------------------------- GEMM (A pre-split bf16, B fp32 weights) ---------
#define LDA 40
#define LDB 136
#define OFF_AH 0
#define OFF_AL (128*LDA*2)
#define OFF_BH (OFF_AL + 128*LDA*2)
#define OFF_BL (OFF_BH + 32*LDB*2)
#define OFF_TOK (OFF_BL + 32*LDB*2)
#define SMEM_TOTAL_G (OFF_TOK + 128*4)

// MODE 0: plain  C = A@B (+add) fp32       (128 out cols / CTA)
// MODE 1: gated  Ch/Cl = split(silu(A@Bg)*(A@Bu))  (64 cols/CTA, up at +upOff)
// MODE 2: moe gathered gated -> split rows off+r
// MODE 3: moe scatter: C[tok] += w * (A@B)  fp32 atomic
template<int MODE>
__global__ __launch_bounds__(256) void gemm_tc(
    const __nv_bfloat16* __restrict__ Ah, const __nv_bfloat16* __restrict__ Al,
    const float* __restrict__ B,
    float* __restrict__ C, __nv_bfloat16* __restrict__ Ch, __nv_bfloat16* __restrict__ Cl,
    const float* __restrict__ add,
    int K, int lda, int ldb, int ldc, int upOff, size_t bStride)
{
    int cnt = 0, off = 0;
    if (MODE >= 2) {
        int e = blockIdx.z;
        cnt = g_cnt[e];
        if ((int)blockIdx.y * 128 >= cnt) return;
        off = g_off[e];
        B += bStride * e;
    }
    const int m0 = blockIdx.y * 128;
    const int nb = blockIdx.x * ((MODE == 1 || MODE == 2) ? 64 : 128);

    __shared__ __align__(16) char sm[SMEM_TOTAL_G];
    int* sTok = (int*)(sm + OFF_TOK);
    const uint32_t uAh = s2u(sm + OFF_AH), uAl = s2u(sm + OFF_AL);
    const uint32_t uBh = s2u(sm + OFF_BH), uBl = s2u(sm + OFF_BL);

    const int tid = threadIdx.x;
    const int wid = tid >> 5, lane = tid & 31;
    const int wm = wid >> 2, wn = wid & 3;

    if (MODE == 2 && tid < 128) {
        int gr = m0 + tid;
        sTok[tid] = (gr < cnt) ? g_ptok[off + gr] : -1;
    }
    __syncthreads();

    float acc[4][4][4] = {};
    const int lrow = lane & 15, lcol8 = (lane >> 4) * 8;

    const int nkt = K >> 5;
    for (int c = 0; c < nkt; c++) {
        const int k0 = c << 5;
        // ---- A tiles (bf16 hi/lo): 128 rows x 32 k, 512 uint4 per copy ----
        #pragma unroll
        for (int it = 0; it < 2; it++) {
            int i = tid + it * 256;
            int m = i >> 2, kq = (i & 3) << 3;
            uint4 vh = make_uint4(0,0,0,0), vl = make_uint4(0,0,0,0);
            size_t rowbase;
            bool valid = true;
            if (MODE == 2) {
                int tk = sTok[m];
                valid = (tk >= 0);
                rowbase = (size_t)(valid ? tk : 0) * lda;
            } else if (MODE == 3) {
                valid = (m0 + m < cnt);
                rowbase = (size_t)(off + m0 + (valid ? m : 0)) * lda;
            } else {
                rowbase = (size_t)(m0 + m) * lda;
            }
            if (valid) {
                vh = *(const uint4*)(Ah + rowbase + k0 + kq);
                vl = *(const uint4*)(Al + rowbase + k0 + kq);
            }
            *(uint4*)(sm + OFF_AH + m * (LDA*2) + kq * 2) = vh;
            *(uint4*)(sm + OFF_AL + m * (LDA*2) + kq * 2) = vl;
        }
        // ---- B tile (fp32 -> split): 32 k x 128 n ----
        #pragma unroll
        for (int it = 0; it < 4; it++) {
            int i = tid + it * 256;
            int kk = i >> 5;
            int n4 = (i & 31) << 2;
            int col;
            if (MODE == 1 || MODE == 2) col = (n4 < 64) ? nb + n4 : upOff + nb + (n4 - 64);
            else                        col = nb + n4;
            float4 v = *(const float4*)(B + (size_t)(k0 + kk) * ldb + col);
            uint32_t h0 = pack_hi(v.x, v.y), h1 = pack_hi(v.z, v.w);
            uint32_t l0 = pack_lo(v.x, v.y, h0), l1 = pack_lo(v.z, v.w, h1);
            uint32_t* ph = (uint32_t*)(sm + OFF_BH + kk * (LDB*2) + n4 * 2);
            uint32_t* pl = (uint32_t*)(sm + OFF_BL + kk * (LDB*2) + n4 * 2);
            ph[0] = h0; ph[1] = h1;
            pl[0] = l0; pl[1] = l1;
        }
        __syncthreads();

        #pragma unroll
        for (int ks = 0; ks < 2; ks++) {
            uint32_t ah[4][4], al[4][4], bh[2][4], bl[2][4];
            #pragma unroll
            for (int mf = 0; mf < 4; mf++) {
                uint32_t ro = (uint32_t)((wm * 64 + mf * 16 + lrow) * LDA + ks * 16 + lcol8) * 2;
                ldsm4(ah[mf], uAh + ro);
                ldsm4(al[mf], uAl + ro);
            }
            #pragma unroll
            for (int nh = 0; nh < 2; nh++) {
                uint32_t ro = (uint32_t)((ks * 16 + lrow) * LDB + wn * 32 + nh * 16 + lcol8) * 2;
                ldsm4t(bh[nh], uBh + ro);
                ldsm4t(bl[nh], uBl + ro);
            }
            #pragma unroll
            for (int mf = 0; mf < 4; mf++)
                #pragma unroll
                for (int nf = 0; nf < 4; nf++) {
                    uint32_t bh0 = bh[nf >> 1][(nf & 1) * 2], bh1 = bh[nf >> 1][(nf & 1) * 2 + 1];
                    uint32_t bl0 = bl[nf >> 1][(nf & 1) * 2], bl1 = bl[nf >> 1][(nf & 1) * 2 + 1];
                    mma16816(acc[mf][nf], ah[mf], bh0, bh1);
                    mma16816(acc[mf][nf], ah[mf], bl0, bl1);
                    mma16816(acc[mf][nf], al[mf], bh0, bh1);
                }
        }
        __syncthreads();
    }

    // ---- epilogue ----
    const int r4 = lane >> 2, c2 = (lane & 3) * 2;
    if (MODE == 0) {
        #pragma unroll
        for (int mf = 0; mf < 4; mf++) {
            #pragma unroll
            for (int nf = 0; nf < 4; nf++) {
                int col = nb + wn * 32 + nf * 8 + c2;
                size_t r1 = (size_t)(m0 + wm * 64 + mf * 16 + r4);
                size_t r2 = r1 + 8;
                float v0 = acc[mf][nf][0], v1 = acc[mf][nf][1];
                float v2 = acc[mf][nf][2], v3 = acc[mf][nf][3];
                if (add) {
                    v0 += add[r1 * ldc + col]; v1 += add[r1 * ldc + col + 1];
                    v2 += add[r2 * ldc + col]; v3 += add[r2 * ldc + col + 1];
                }
                *(float2*)(C + r1 * ldc + col) = make_float2(v0, v1);
                *(float2*)(C + r2 * ldc + col) = make_float2(v2, v3);
            }
        }
    } else if (MODE == 1 || MODE == 2) {
        float* sG = (float*)sm;              // [128][65]
        if (wn < 2) {
            #pragma unroll
            for (int mf = 0; mf < 4; mf++)
                #pragma unroll
                for (int nf = 0; nf < 4; nf++) {
                    int col = wn * 32 + nf * 8 + c2;
                    int rr1 = wm * 64 + mf * 16 + r4, rr2 = rr1 + 8;
                    sG[rr1 * 65 + col]     = acc[mf][nf][0];
                    sG[rr1 * 65 + col + 1] = acc[mf][nf][1];
                    sG[rr2 * 65 + col]     = acc[mf][nf][2];
                    sG[rr2 * 65 + col + 1] = acc[mf][nf][3];
                }
        }
        __syncthreads();
        if (wn >= 2) {
            #pragma unroll
            for (int mf = 0; mf < 4; mf++)
                #pragma unroll
                for (int nf = 0; nf < 4; nf++) {
                    int col = (wn - 2) * 32 + nf * 8 + c2;
                    int rr1 = wm * 64 + mf * 16 + r4;
                    #pragma unroll
                    for (int half = 0; half < 2; half++) {
                        int rr = rr1 + half * 8;
                        bool ok = (MODE == 1) || (m0 + rr < cnt);
                        if (ok) {
                            size_t row = (MODE == 1) ? (size_t)(m0 + rr) : (size_t)(off + m0 + rr);
                            float g0 = sG[rr * 65 + col], g1 = sG[rr * 65 + col + 1];
                            float u0 = acc[mf][nf][half * 2], u1 = acc[mf][nf][half * 2 + 1];
                            float o0 = g0 / (1.f + fexp(-g0)) * u0;
                            float o1 = g1 / (1.f + fexp(-g1)) * u1;
                            uint32_t hi, lo;
                            split2(o0, o1, hi, lo);
                            *(uint32_t*)(Ch + row * ldc + nb + col) = hi;
                            *(uint32_t*)(Cl + row * ldc + nb + col) = lo;
                        }
                    }
                }
        }
    } else {  // MODE 3
        #pragma unroll
        for (int mf = 0; mf < 4; mf++) {
            int rr1 = wm * 64 + mf * 16 + r4;
            #pragma unroll
            for (int half = 0; half < 2; half++) {
                int rr = rr1 + half * 8;
                if (m0 + rr < cnt) {
                    int tok = g_ptok[off + m0 + rr];
                    float w = g_pw[off + m0 + rr];
                    float* dst = C + (size_t)tok * ldc;
                    #pragma unroll
                    for (int nf = 0; nf < 4; nf++) {
                        int col = nb + wn * 32 + nf * 8 + c2;
                        atomicAdd(dst + col,     w * acc[mf][nf][half * 2]);
                        atomicAdd(dst + col + 1, w * acc[mf][nf][half * 2 + 1]);
                    }
                }
            }
        }
    }
}

// ------------------------- small kernels ------------------------------------
__global__ void zero_counts_k() {
    if (threadIdx.x < NEXP) g_cnt[threadIdx.x] = 0;
}

__global__ void cs_prep_k(const int* __restrict__ pos) {
    int t = blockIdx.x, i = threadIdx.x;   // 64 threads
    double e = exp(-((double)(2 * i) / 128.0) * log(500000.0));
    float f = (float)pos[t] * (float)e;
    float sn, cs; sincosf(f, &sn, &cs);
    g_cs[t * 64 + i] = make_float2(cs, sn);
}

// rmsnorm: writes optional fp32 y + optional bf16 split yh/yl
__global__ void rmsnorm_k(const float* __restrict__ x, const float* __restrict__ w,
                          float* __restrict__ y,
                          __nv_bfloat16* __restrict__ yh, __nv_bfloat16* __restrict__ yl,
                          int cols, int ldx, int ldy)
{
    int row = blockIdx.x;
    const float* xr = x + (size_t)row * ldx;
    float ss = 0.f;
    for (int c = threadIdx.x; c < cols; c += 256) { float v = xr[c]; ss = fmaf(v, v, ss); }
    __shared__ float red[256];
    red[threadIdx.x] = ss;
    __syncthreads();
    for (int s = 128; s > 0; s >>= 1) {
        if (threadIdx.x < s) red[threadIdx.x] += red[threadIdx.x + s];
        __syncthreads();
    }
    float r = rsqrtf(red[0] / (float)cols + 1e-5f);
    for (int c = threadIdx.x; c < cols; c += 256) {
        float v = xr[c] * r * w[c];
        if (y) y[(size_t)row * ldy + c] = v;
        if (yh) {
            __nv_bfloat16 h = __float2bfloat16_rn(v);
            yh[(size_t)row * ldy + c] = h;
            yl[(size_t)row * ldy + c] = __float2bfloat16_rn(v - __bfloat162float(h));
        }
    }
}

// rope on q (reads qproj fp32, writes split bf16 with SCALE folded)
__global__ void rope_q_k(const float* __restrict__ qp,
                         __nv_bfloat16* __restrict__ qh, __nv_bfloat16* __restrict__ ql)
{
    int t = blockIdx.x;
    for (int idx = threadIdx.x; idx < NHEAD * 64; idx += 256) {
        int hh = idx >> 6, i = idx & 63;
        float2 cs = g_cs[t * 64 + i];
        const float* b = qp + (size_t)t * 2048 + hh * HD;
        float x1 = b[i], x2 = b[i + 64];
        float y1 = (x1 * cs.x - x2 * cs.y) * SCALE;
        float y2 = (x2 * cs.x + x1 * cs.y) * SCALE;
        size_t o1 = (size_t)t * 2048 + hh * HD + i;
        __nv_bfloat16 h1 = __float2bfloat16_rn(y1);
        qh[o1] = h1; ql[o1] = __float2bfloat16_rn(y1 - __bfloat162float(h1));
        __nv_bfloat16 h2 = __float2bfloat16_rn(y2);
        qh[o1 + 64] = h2; ql[o1 + 64] = __float2bfloat16_rn(y2 - __bfloat162float(h2));
    }
}

// K rope + transpose split; V split
__global__ void kv_prep_k(const float* __restrict__ qkv)
{
    int t = blockIdx.x;
    int tid = threadIdx.x;   // 128
    if (tid < 64) {
        int i = tid;
        float2 cs = g_cs[t * 64 + i];
        const float* kb = qkv + (size_t)t * QKV_N + QDIM;
        float x1 = kb[i], x2 = kb[i + 64];
        float y1 = x1 * cs.x - x2 * cs.y;
        float y2 = x2 * cs.x + x1 * cs.y;
        __nv_bfloat16 h1 = __float2bfloat16_rn(y1);
        g_kth[(size_t)i * SEQ + t] = h1;
        g_ktl[(size_t)i * SEQ + t] = __float2bfloat16_rn(y1 - __bfloat162float(h1));
        __nv_bfloat16 h2 = __float2bfloat16_rn(y2);
        g_kth[(size_t)(i + 64) * SEQ + t] = h2;
        g_ktl[(size_t)(i + 64) * SEQ + t] = __float2bfloat16_rn(y2 - __bfloat162float(h2));
    }
    {
        float v = qkv[(size_t)t * QKV_N + QDIM + HD + tid];
        __nv_bfloat16 h = __float2bfloat16_rn(v);
        g_vh[(size_t)t * HD + tid] = h;
        g_vl[(size_t)t * HD + tid] = __float2bfloat16_rn(v - __bfloat162float(h));
    }
}

// ------------------------- attention: bf16 HMMA flash ----------------------
#define AQ_LD 136
#define AK_LD 72
#define AV_LD 136
#define AP_LD 72
#define AOF_QH 0
#define AOF_QL 34816
#define AOF_KH 69632
#define AOF_KL 88064
#define AOF_VH 106496
#define AOF_VL 123904
#define AOF_PH 141312
#define AOF_PL 159744
#define AOF_M  178176
#define AOF_L  178688
#define AOF_RMAX 179200
#define AOF_RSUM 180224
#define ATTN_SMEM 181248

__global__ __launch_bounds__(256, 1) void attn_k(
    const __nv_bfloat16* __restrict__ Qh, const __nv_bfloat16* __restrict__ Ql,
    __nv_bfloat16* __restrict__ Oh, __nv_bfloat16* __restrict__ Ol)
{
    extern __shared__ __align__(16) char sm[];
    const int bx = blockIdx.x;
    const int qt = 15 - (bx >> 4);     // longest tiles first
    const int h = bx & 15;
    const int q0 = qt * 128;

    const int tid = threadIdx.x;
    const int wid = tid >> 5, lane = tid & 31;
    const int wm = wid >> 1, wn = wid & 1;
    const int lrow = lane & 15, lcol8 = (lane >> 4) * 8;
    const int r4 = lane >> 2, c2 = (lane & 3) * 2;

    float* sM = (float*)(sm + AOF_M);
    float* sL = (float*)(sm + AOF_L);
    float* sRmax = (float*)(sm + AOF_RMAX);   // [2][128]
    float* sRsum = (float*)(sm + AOF_RSUM);   // [2][128]
    const uint32_t uQh = s2u(sm + AOF_QH), uQl = s2u(sm + AOF_QL);
    const uint32_t uKh = s2u(sm + AOF_KH), uKl = s2u(sm + AOF_KL);
    const uint32_t uVh = s2u(sm + AOF_VH), uVl = s2u(sm + AOF_VL);
    const uint32_t uPh = s2u(sm + AOF_PH), uPl = s2u(sm + AOF_PL);

    // load Q tile (128 x 128, hi+lo)
    #pragma unroll
    for (int it = 0; it < 8; it++) {
        int i = tid + it * 256;          // 2048 uint4 per copy
        int r = i >> 4, c = (i & 15) << 3;
        size_t src = (size_t)(q0 + r) * 2048 + h * HD + c;
        *(uint4*)(sm + AOF_QH + r * (AQ_LD*2) + c * 2) = *(const uint4*)(Qh + src);
        *(uint4*)(sm + AOF_QL + r * (AQ_LD*2) + c * 2) = *(const uint4*)(Ql + src);
    }
    if (tid < 128) { sM[tid] = -3.0e30f; sL[tid] = 0.f; }

    float o[2][8][4] = {};
    const int nkt = 2 * qt + 2;

    for (int kt = 0; kt < nkt; kt++) {
        const int k0 = kt * 64;
        __syncthreads();
        // load K tile (transposed source [d][tok]): 128 x 64
        #pragma unroll
        for (int it = 0; it < 4; it++) {
            int i = tid + it * 256;      // 1024 uint4 per copy
            int d = i >> 3, tc = (i & 7) << 3;
            size_t src = (size_t)d * SEQ + k0 + tc;
            *(uint4*)(sm + AOF_KH + d * (AK_LD*2) + tc * 2) = *(const uint4*)(g_kth + src);
            *(uint4*)(sm + AOF_KL + d * (AK_LD*2) + tc * 2) = *(const uint4*)(g_ktl + src);
        }
        // load V tile: 64 x 128
        #pragma unroll
        for (int it = 0; it < 4; it++) {
            int i = tid + it * 256;
            int r = i >> 4, c = (i & 15) << 3;
            size_t src = (size_t)(k0 + r) * HD + c;
            *(uint4*)(sm + AOF_VH + r * (AV_LD*2) + c * 2) = *(const uint4*)(g_vh + src);
            *(uint4*)(sm + AOF_VL + r * (AV_LD*2) + c * 2) = *(const uint4*)(g_vl + src);
        }
        __syncthreads();

        // ---- S = Q K^T (3-pass split) ----
        float sacc[2][4][4] = {};
        #pragma unroll
        for (int ks = 0; ks < 8; ks++) {
            uint32_t ah[2][4], al[2][4], bh[2][4], bl[2][4];
            #pragma unroll
            for (int mf = 0; mf < 2; mf++) {
                uint32_t ro = (uint32_t)((wm * 32 + mf * 16 + lrow) * AQ_LD + ks * 16 + lcol8) * 2;
                ldsm4(ah[mf], uQh + ro);
                ldsm4(al[mf], uQl + ro);
            }
            #pragma unroll
            for (int nh = 0; nh < 2; nh++) {
                uint32_t ro = (uint32_t)((ks * 16 + lrow) * AK_LD + wn * 32 + nh * 16 + lcol8) * 2;
                ldsm4t(bh[nh], uKh + ro);
                ldsm4t(bl[nh], uKl + ro);
            }
            #pragma unroll
            for (int mf = 0; mf < 2; mf++)
                #pragma unroll
                for (int nf = 0; nf < 4; nf++) {
                    uint32_t b0h = bh[nf >> 1][(nf & 1) * 2], b1h = bh[nf >> 1][(nf & 1) * 2 + 1];
                    uint32_t b0l = bl[nf >> 1][(nf & 1) * 2], b1l = bl[nf >> 1][(nf & 1) * 2 + 1];
                    mma16816(sacc[mf][nf], ah[mf], b0h, b1h);
                    mma16816(sacc[mf][nf], ah[mf], b0l, b1l);
                    mma16816(sacc[mf][nf], al[mf], b0h, b1h);
                }
        }

        // causal mask on diagonal tiles
        if (kt >= nkt - 2) {
            #pragma unroll
            for (int mf = 0; mf < 2; mf++)
                #pragma unroll
                for (int nf = 0; nf < 4; nf++)
                    #pragma unroll
                    for (int v = 0; v < 4; v++) {
                        int row = q0 + wm * 32 + mf * 16 + r4 + (v >= 2 ? 8 : 0);
                        int col = k0 + wn * 32 + nf * 8 + c2 + (v & 1);
                        if (col > row) sacc[mf][nf][v] = -1.0e30f;
                    }
        }

        // ---- row max (warp-local then cross-warp) ----
        float rmax[4] = {-3.0e30f, -3.0e30f, -3.0e30f, -3.0e30f};
        #pragma unroll
        for (int mf = 0; mf < 2; mf++)
            #pragma unroll
            for (int nf = 0; nf < 4; nf++) {
                rmax[mf*2]   = fmaxf(rmax[mf*2],   fmaxf(sacc[mf][nf][0], sacc[mf][nf][1]));
                rmax[mf*2+1] = fmaxf(rmax[mf*2+1], fmaxf(sacc[mf][nf][2], sacc[mf][nf][3]));
            }
        #pragma unroll
        for (int s = 0; s < 4; s++) {
            rmax[s] = fmaxf(rmax[s], __shfl_xor_sync(0xffffffffu, rmax[s], 1));
            rmax[s] = fmaxf(rmax[s], __shfl_xor_sync(0xffffffffu, rmax[s], 2));
        }
        if ((lane & 3) == 0) {
            #pragma unroll
            for (int s = 0; s < 4; s++) {
                int lr = wm * 32 + (s >> 1) * 16 + r4 + (s & 1) * 8;
                sRmax[wn * 128 + lr] = rmax[s];
            }
        }
        __syncthreads();

        float mn[4], fct[4];
        #pragma unroll
        for (int s = 0; s < 4; s++) {
            int lr = wm * 32 + (s >> 1) * 16 + r4 + (s & 1) * 8;
            float mo = sM[lr];
            float m2 = fmaxf(sRmax[lr], sRmax[128 + lr]);
            mn[s] = fmaxf(mo, m2);
            fct[s] = fexp(mo - mn[s]);
        }

        // ---- p = exp(s-mn), store split P, partial sums, rescale o ----
        float rsum[4] = {0.f, 0.f, 0.f, 0.f};
        #pragma unroll
        for (int mf = 0; mf < 2; mf++) {
            int lr0 = wm * 32 + mf * 16 + r4;
            #pragma unroll
            for (int nf = 0; nf < 4; nf++) {
                int col = wn * 32 + nf * 8 + c2;
                float p0 = fexp(sacc[mf][nf][0] - mn[mf*2]);
                float p1 = fexp(sacc[mf][nf][1] - mn[mf*2]);
                float p2 = fexp(sacc[mf][nf][2] - mn[mf*2+1]);
                float p3 = fexp(sacc[mf][nf][3] - mn[mf*2+1]);
                rsum[mf*2]   += p0 + p1;
                rsum[mf*2+1] += p2 + p3;
                uint32_t hi, lo;
                split2(p0, p1, hi, lo);
                *(uint32_t*)(sm + AOF_PH + (lr0 * AP_LD + col) * 2) = hi;
                *(uint32_t*)(sm + AOF_PL + (lr0 * AP_LD + col) * 2) = lo;
                split2(p2, p3, hi, lo);
                *(uint32_t*)(sm + AOF_PH + ((lr0 + 8) * AP_LD + col) * 2) = hi;
                *(uint32_t*)(sm + AOF_PL + ((lr0 + 8) * AP_LD + col) * 2) = lo;
            }
        }
        #pragma unroll
        for (int mf = 0; mf < 2; mf++)
            #pragma unroll
            for (int nf8 = 0; nf8 < 8; nf8++) {
                o[mf][nf8][0] *= fct[mf*2];   o[mf][nf8][1] *= fct[mf*2];
                o[mf][nf8][2] *= fct[mf*2+1]; o[mf][nf8][3] *= fct[mf*2+1];
            }
        #pragma unroll
        for (int s = 0; s < 4; s++) {
            rsum[s] += __shfl_xor_sync(0xffffffffu, rsum[s], 1);
            rsum[s] += __shfl_xor_sync(0xffffffffu, rsum[s], 2);
        }
        if ((lane & 3) == 0) {
            #pragma unroll
            for (int s = 0; s < 4; s++) {
                int lr = wm * 32 + (s >> 1) * 16 + r4 + (s & 1) * 8;
                sRsum[wn * 128 + lr] = rsum[s];
            }
        }
        __syncthreads();
        if (wn == 0 && (lane & 3) == 0) {
            #pragma unroll
            for (int s = 0; s < 4; s++) {
                int lr = wm * 32 + (s >> 1) * 16 + r4 + (s & 1) * 8;
                sL[lr] = sL[lr] * fct[s] + sRsum[lr] + sRsum[128 + lr];
                sM[lr] = mn[s];
            }
        }

        // ---- O += P V (3-pass split) ----
        #pragma unroll
        for (int ks = 0; ks < 4; ks++) {
            uint32_t aph[2][4], apl[2][4], bvh[4][4], bvl[4][4];
            #pragma unroll
            for (int mf = 0; mf < 2; mf++) {
                uint32_t ro = (uint32_t)((wm * 32 + mf * 16 + lrow) * AP_LD + ks * 16 + lcol8) * 2;
                ldsm4(aph[mf], uPh + ro);
                ldsm4(apl[mf], uPl + ro);
            }
            #pragma unroll
            for (int nh = 0; nh < 4; nh++) {
                uint32_t ro = (uint32_t)((ks * 16 + lrow) * AV_LD + wn * 64 + nh * 16 + lcol8) * 2;
                ldsm4t(bvh[nh], uVh + ro);
                ldsm4t(bvl[nh], uVl + ro);
            }
            #pragma unroll
            for (int mf = 0; mf < 2; mf++)
                #pragma unroll
                for (int nf8 = 0; nf8 < 8; nf8++) {
                    uint32_t b0h = bvh[nf8 >> 1][(nf8 & 1) * 2], b1h = bvh[nf8 >> 1][(nf8 & 1) * 2 + 1];
                    uint32_t b0l = bvl[nf8 >> 1][(nf8 & 1) * 2], b1l = bvl[nf8 >> 1][(nf8 & 1) * 2 + 1];
                    mma16816(o[mf][nf8], aph[mf], b0h, b1h);
                    mma16816(o[mf][nf8], aph[mf], b0l, b1l);
                    mma16816(o[mf][nf8], apl[mf], b0h, b1h);
                }
        }
    }
    __syncthreads();

    // ---- write O (split bf16) ----
    float inv[4];
    #pragma unroll
    for (int s = 0; s < 4; s++) {
        int lr = wm * 32 + (s >> 1) * 16 + r4 + (s & 1) * 8;
        inv[s] = 1.f / sL[lr];
    }
    #pragma unroll
    for (int mf = 0; mf < 2; mf++) {
        int row0 = q0 + wm * 32 + mf * 16 + r4;
        #pragma unroll
        for (int nf8 = 0; nf8 < 8; nf8++) {
            int col = h * HD + wn * 64 + nf8 * 8 + c2;
            uint32_t hi, lo;
            split2(o[mf][nf8][0] * inv[mf*2], o[mf][nf8][1] * inv[mf*2], hi, lo);
            *(uint32_t*)(Oh + (size_t)row0 * 2048 + col) = hi;
            *(uint32_t*)(Ol + (size_t)row0 * 2048 + col) = lo;
            split2(o[mf][nf8][2] * inv[mf*2+1], o[mf][nf8][3] * inv[mf*2+1], hi, lo);
            *(uint32_t*)(Oh + (size_t)(row0 + 8) * 2048 + col) = hi;
            *(uint32_t*)(Ol + (size_t)(row0 + 8) * 2048 + col) = lo;
        }
    }
}

// ------------------------- router / topk / scan / fill ---------------------
__global__ __launch_bounds__(256) void router_k(const float* __restrict__ X,
                                                const float* __restrict__ Wr)
{
    __shared__ float part[8][32];
    int t = blockIdx.x;
    int e = threadIdx.x & 31, p = threadIdx.x >> 5;
    const float* xr = X + (size_t)t * HID;
    float s = 0.f;
    for (int k = p * 128; k < p * 128 + 128; k++) s = fmaf(xr[k], Wr[k * 32 + e], s);
    part[p][e] = s;
    __syncthreads();
    if (threadIdx.x < 32) {
        float logit = 0.f;
        #pragma unroll
        for (int q = 0; q < 8; q++) logit += part[q][e];
        float m = logit;
        for (int d = 16; d; d >>= 1) m = fmaxf(m, __shfl_xor_sync(0xffffffffu, m, d));
        float ex = __expf(logit - m);
        float cur = ex;
        float wsel[3]; int isel[3];
        #pragma unroll
        for (int kk = 0; kk < 3; kk++) {
            float v = cur; int idx = e;
            for (int d = 16; d; d >>= 1) {
                float v2 = __shfl_xor_sync(0xffffffffu, v, d);
                int   i2 = __shfl_xor_sync(0xffffffffu, idx, d);
                if (v2 > v || (v2 == v && i2 < idx)) { v = v2; idx = i2; }
            }
            wsel[kk] = v; isel[kk] = idx;
            if (e == idx) cur = -1.f;
        }
        float tot = wsel[0] + wsel[1] + wsel[2];
        if (e < 3) { g_topi[t * 3 + e] = isel[e]; g_topw[t * 3 + e] = wsel[e] / tot; }
        if (e == 0) {
            atomicAdd(&g_cnt[isel[0]], 1);
            atomicAdd(&g_cnt[isel[1]], 1);
            atomicAdd(&g_cnt[isel[2]], 1);
        }
    }
}

__global__ void scan_k()
{
    int e = threadIdx.x;
    int c = g_cnt[e];
    int x = c;
    for (int d = 1; d < 32; d <<= 1) {
        int y = __shfl_up_sync(0xffffffffu, x, d);
        if (e >= d) x += y;
    }
    int excl = x - c;
    g_off[e] = excl;
    g_fill[e] = excl;
}

__global__ void fill_k()
{
    int t = blockIdx.x * 256 + threadIdx.x;
    if (t < SEQ) {
        #pragma unroll
        for (int k = 0; k < 3; k++) {
            int e = g_topi[t * 3 + k];
            int slot = atomicAdd(&g_fill[e], 1);
            g_ptok[slot] = t;
            g_pw[slot] = g_topw[t * 3 + k];
        }
    }
}

// ------------------------- launch ------------------------------------------
extern "C" void kernel_launch(void* const* d_in, const int* in_sizes, int n_in,
                              void* d_out, int out_size)
{
    const float* hidden   = (const float*)d_in[0];
    const float* w_in     = (const float*)d_in[1];
    const float* w_qkv    = (const float*)d_in[2];
    const float* w_inter  = (const float*)d_in[3];
    const float* w_q      = (const float*)d_in[4];
    const float* w_o      = (const float*)d_in[5];
    const float* w_post   = (const float*)d_in[6];
    const float* w_guse   = (const float*)d_in[7];
    const float* w_dse    = (const float*)d_in[8];
    const float* w_router = (const float*)d_in[9];
    const float* w_gue    = (const float*)d_in[10];
    const float* w_de     = (const float*)d_in[11];
    const int*   pos      = (const int*)d_in[12];
    float* out = (float*)d_out;

    float *qkv, *qproj, *resid2, *h2;
    cudaGetSymbolAddress((void**)&qkv,    g_qkv);
    cudaGetSymbolAddress((void**)&qproj,  g_qproj);
    cudaGetSymbolAddress((void**)&resid2, g_resid2);
    cudaGetSymbolAddress((void**)&h2,     g_h2);
    __nv_bfloat16 *hnh,*hnl,*qnh,*qnl,*qh,*ql,*aoh,*aol,*h2h,*h2l,*aseh,*asel,*aceh,*acel;
    cudaGetSymbolAddress((void**)&hnh, g_hnh);   cudaGetSymbolAddress((void**)&hnl, g_hnl);
    cudaGetSymbolAddress((void**)&qnh, g_qnh);   cudaGetSymbolAddress((void**)&qnl, g_qnl);
    cudaGetSymbolAddress((void**)&qh,  g_qh);    cudaGetSymbolAddress((void**)&ql,  g_ql);
    cudaGetSymbolAddress((void**)&aoh, g_aoh);   cudaGetSymbolAddress((void**)&aol, g_aol);
    cudaGetSymbolAddress((void**)&h2h, g_h2h);   cudaGetSymbolAddress((void**)&h2l, g_h2l);
    cudaGetSymbolAddress((void**)&aseh,g_aseh);  cudaGetSymbolAddress((void**)&asel,g_asel);
    cudaGetSymbolAddress((void**)&aceh,g_aceh);  cudaGetSymbolAddress((void**)&acel,g_acel);

    cudaFuncSetAttribute(attn_k, cudaFuncAttributeMaxDynamicSharedMemorySize, ATTN_SMEM);

    zero_counts_k<<<1, 32>>>();
    cs_prep_k<<<SEQ, 64>>>(pos);
    rmsnorm_k<<<SEQ, 256>>>(hidden, w_in, nullptr, hnh, hnl, HID, HID, HID);
    gemm_tc<0><<<dim3(QKV_N/128, SEQ/128), 256>>>(
        hnh, hnl, w_qkv, qkv, nullptr, nullptr, nullptr, HID, HID, QKV_N, QKV_N, 0, 0);
    rmsnorm_k<<<SEQ, 256>>>(qkv, w_inter, nullptr, qnh, qnl, QDIM, QKV_N, QDIM);
    gemm_tc<0><<<dim3(2048/128, SEQ/128), 256>>>(
        qnh, qnl, w_q, qproj, nullptr, nullptr, nullptr, QDIM, QDIM, 2048, 2048, 0, 0);
    rope_q_k<<<SEQ, 256>>>(qproj, qh, ql);
    kv_prep_k<<<SEQ, 128>>>(qkv);
    attn_k<<<256, 256, ATTN_SMEM>>>(qh, ql, aoh, aol);
    gemm_tc<0><<<dim3(HID/128, SEQ/128), 256>>>(
        aoh, aol, w_o, resid2, nullptr, nullptr, hidden, 2048, 2048, HID, HID, 0, 0);
    rmsnorm_k<<<SEQ, 256>>>(resid2, w_post, h2, h2h, h2l, HID, HID, HID);
    gemm_tc<1><<<dim3(IDIM/64, SEQ/128), 256>>>(
        h2h, h2l, w_guse, nullptr, aseh, asel, nullptr, HID, HID, 2*IDIM, IDIM, IDIM, 0);
    gemm_tc<0><<<dim3(HID/128, SEQ/128), 256>>>(
        aseh, asel, w_dse, out, nullptr, nullptr, resid2, IDIM, IDIM, HID, HID, 0, 0);
    router_k<<<SEQ, 256>>>(h2, w_router);
    scan_k<<<1, 32>>>();
    fill_k<<<SEQ/256, 256>>>();
    gemm_tc<2><<<dim3(IDIM/64, 16, NEXP), 256>>>(
        h2h, h2l, w_gue, nullptr, aceh, acel, nullptr, HID, HID, 2*IDIM, IDIM, IDIM,
        (size_t)HID * 2 * IDIM);
    gemm_tc<3><<<dim3(HID/128, 16, NEXP), 256>>>(
        aceh, acel, w_de, out, nullptr, nullptr, nullptr, IDIM, IDIM, HID, HID, 0,
        (size_t)IDIM * HID);
}

// round 5
// speedup vs baseline: 4.0007x; 1.1258x over previous
#include <cuda_runtime.h>
#include <cuda_bf16.h>
#include <math.h>
#include <stdint.h>

#define SEQ 2048
#define HID 1024
#define NHEAD 16
#define HD 128
#define QDIM 512
#define NEXP 32
#define IDIM 1024
#define QKV_N 768
#define SCALE 0.08838834764831845f   // 1/sqrt(128)

// ------------------------- device scratch ----------------------------------
__device__ float g_qkv[SEQ*QKV_N];
__device__ float g_qproj[SEQ*NHEAD*HD];
__device__ float g_resid2[SEQ*HID];
__device__ float g_h2[SEQ*HID];
__device__ float2 g_cs[SEQ*64];

__device__ __nv_bfloat16 g_hnh[SEQ*HID],  g_hnl[SEQ*HID];
__device__ __nv_bfloat16 g_qnh[SEQ*QDIM], g_qnl[SEQ*QDIM];
__device__ __nv_bfloat16 g_qh[SEQ*2048],  g_ql[SEQ*2048];
__device__ __nv_bfloat16 g_kth[128*SEQ],  g_ktl[128*SEQ];   // transposed [d][token]
__device__ __nv_bfloat16 g_vh[SEQ*128],   g_vl[SEQ*128];
__device__ __nv_bfloat16 g_aoh[SEQ*2048], g_aol[SEQ*2048];
__device__ __nv_bfloat16 g_h2h[SEQ*HID],  g_h2l[SEQ*HID];
__device__ __nv_bfloat16 g_aseh[SEQ*IDIM],g_asel[SEQ*IDIM];
__device__ __nv_bfloat16 g_aceh[SEQ*3*IDIM], g_acel[SEQ*3*IDIM];

__device__ int   g_topi[SEQ*3];
__device__ float g_topw[SEQ*3];
__device__ int   g_cnt[NEXP];
__device__ int   g_off[NEXP];
__device__ int   g_fill[NEXP];
__device__ int   g_ptok[SEQ*3];
__device__ float g_pw[SEQ*3];

// ------------------------- helpers -----------------------------------------
__device__ __forceinline__ uint32_t s2u(const void* p) {
    uint32_t a;
    asm("{ .reg .u64 t; cvta.to.shared.u64 t, %1; cvt.u32.u64 %0, t; }" : "=r"(a) : "l"(p));
    return a;
}
__device__ __forceinline__ void ldsm4(uint32_t* r, uint32_t addr) {
    asm volatile("ldmatrix.sync.aligned.m8n8.x4.shared.b16 {%0,%1,%2,%3}, [%4];"
        : "=r"(r[0]), "=r"(r[1]), "=r"(r[2]), "=r"(r[3]) : "r"(addr));
}
__device__ __forceinline__ void ldsm4t(uint32_t* r, uint32_t addr) {
    asm volatile("ldmatrix.sync.aligned.m8n8.x4.trans.shared.b16 {%0,%1,%2,%3}, [%4];"
        : "=r"(r[0]), "=r"(r[1]), "=r"(r[2]), "=r"(r[3]) : "r"(addr));
}
__device__ __forceinline__ void mma16816(float* c, const uint32_t* a, uint32_t b0, uint32_t b1) {
    asm volatile("mma.sync.aligned.m16n8k16.row.col.f32.bf16.bf16.f32 "
        "{%0,%1,%2,%3}, {%4,%5,%6,%7}, {%8,%9}, {%0,%1,%2,%3};"
        : "+f"(c[0]), "+f"(c[1]), "+f"(c[2]), "+f"(c[3])
        : "r"(a[0]), "r"(a[1]), "r"(a[2]), "r"(a[3]), "r"(b0), "r"(b1));
}
__device__ __forceinline__ void cpa16(uint32_t dst, const void* src) {
    asm volatile("cp.async.cg.shared.global [%0], [%1], 16;" :: "r"(dst), "l"(src));
}
#define CPA_COMMIT() asm volatile("cp.async.commit_group;" ::: "memory")
#define CPA_WAIT()   asm volatile("cp.async.wait_group 0;" ::: "memory")

__device__ __forceinline__ uint32_t pack_hi(float f0, float f1) {
    __nv_bfloat162 h = __floats2bfloat162_rn(f0, f1);
    return *(uint32_t*)&h;
}
__device__ __forceinline__ uint32_t pack_lo(float f0, float f1, uint32_t hibits) {
    __nv_bfloat162 h = *(__nv_bfloat162*)&hibits;
    __nv_bfloat162 l = __floats2bfloat162_rn(f0 - __bfloat162float(h.x),
                                             f1 - __bfloat162float(h.y));
    return *(uint32_t*)&l;
}
__device__ __forceinline__ void split2(float a, float b, uint32_t& hi, uint32_t& lo) {
    hi = pack_hi(a, b);
    lo = pack_lo(a, b, hi);
}
// FFMA-only exp (rel err ~4e-5), avoids MUFU
__device__ __forceinline__ float fexp(float x) {
    x = fminf(fmaxf(x, -80.f), 80.f);
    float y = x * 1.4426950408889634f;
    float n = rintf(y);
    float f = y - n;
    float p = fmaf(f, 0.009618130f, 0.055504110f);
    p = fmaf(p, f, 0.240226507f);
    p = fmaf(p, f, 0.693147181f);
    p = fmaf(p, f, 1.0f);
    return p * __int_as_float(((int)n + 127) << 23);
}

// ------------------------- GEMM (pipelined, double-buffered) ----------------
#define LDA 40
#define LDB 136
#define ASZ (128*LDA*2)          // 10240 bytes per A array
#define BSZ (32*LDB*2)           // 8704 bytes per B array
#define OFF_AH(b) ((b) * (2*ASZ))
#define OFF_AL(b) ((b) * (2*ASZ) + ASZ)
#define OFF_BH(b) (4*ASZ + (b) * (2*BSZ))
#define OFF_BL(b) (4*ASZ + (b) * (2*BSZ) + BSZ)
#define OFF_TOK   (4*ASZ + 4*BSZ)
#define SMEM_TOTAL_G (OFF_TOK + 128*4)

// MODE 0: plain  C = A@B (+add) fp32       (128 out cols / CTA)
// MODE 1: gated  Ch/Cl = split(silu(A@Bg)*(A@Bu))  (64 cols/CTA, up at +upOff)
// MODE 2: moe gathered gated -> split rows off+r
// MODE 3: moe scatter: C[tok] += w * (A@B)  fp32 atomic
template<int MODE>
__global__ __launch_bounds__(256) void gemm_tc(
    const __nv_bfloat16* __restrict__ Ah, const __nv_bfloat16* __restrict__ Al,
    const float* __restrict__ B,
    float* __restrict__ C, __nv_bfloat16* __restrict__ Ch, __nv_bfloat16* __restrict__ Cl,
    const float* __restrict__ add,
    int K, int lda, int ldb, int ldc, int upOff, size_t bStride)
{
    int cnt = 0, off = 0;
    if (MODE >= 2) {
        int e = blockIdx.z;
        cnt = g_cnt[e];
        if ((int)blockIdx.y * 128 >= cnt) return;
        off = g_off[e];
        B += bStride * e;
    }
    const int m0 = blockIdx.y * 128;
    const int nb = blockIdx.x * ((MODE == 1 || MODE == 2) ? 64 : 128);

    extern __shared__ __align__(16) char sm[];
    int* sTok = (int*)(sm + OFF_TOK);
    const uint32_t sb = s2u(sm);

    const int tid = threadIdx.x;
    const int wid = tid >> 5, lane = tid & 31;
    const int wm = wid >> 2, wn = wid & 3;

    if (MODE == 2 && tid < 128) {
        int gr = m0 + tid;
        sTok[tid] = (gr < cnt) ? g_ptok[off + gr] : 0;
    }
    __syncthreads();

    float acc[4][4][4] = {};
    const int lrow = lane & 15, lcol8 = (lane >> 4) * 8;

    // per-thread A cp.async indices: 2 segments (idx, idx+256)
    const int am0 = tid >> 2, aseg0 = (tid & 3);
    const int am1 = (tid + 256) >> 2, aseg1 = ((tid + 256) & 3);

    // A row base pointers (element offsets)
    size_t arow0, arow1;
    {
        int mA0 = am0, mA1 = am1;
        if (MODE == 2) {
            arow0 = (size_t)sTok[mA0] * lda;
            arow1 = (size_t)sTok[mA1] * lda;
        } else if (MODE == 3) {
            int r0 = (m0 + mA0 < cnt) ? m0 + mA0 : 0;
            int r1 = (m0 + mA1 < cnt) ? m0 + mA1 : 0;
            arow0 = (size_t)(off + r0) * lda;
            arow1 = (size_t)(off + r1) * lda;
        } else {
            arow0 = (size_t)(m0 + am0) * lda;
            arow1 = (size_t)(m0 + am1) * lda;
        }
    }
    const uint32_t adst0 = sb + am0 * (LDA*2) + aseg0 * 16;
    const uint32_t adst1 = sb + am1 * (LDA*2) + aseg1 * 16;

    // B load indexing (4 float4 per thread)
    int bcol[4]; size_t brow[4];
    #pragma unroll
    for (int it = 0; it < 4; it++) {
        int i = tid + it * 256;
        int kk = i >> 5;
        int n4 = (i & 31) << 2;
        int col;
        if (MODE == 1 || MODE == 2) col = (n4 < 64) ? nb + n4 : upOff + nb + (n4 - 64);
        else                        col = nb + n4;
        bcol[it] = n4;
        brow[it] = (size_t)kk * ldb + col;
    }

    const int nkt = K >> 5;
    float4 br[4];

    // ---- prologue: chunk 0 ----
    {
        cpa16(adst0 + OFF_AH(0), Ah + arow0 + aseg0 * 8);
        cpa16(adst0 + OFF_AL(0), Al + arow0 + aseg0 * 8);
        cpa16(adst1 + OFF_AH(0), Ah + arow1 + aseg1 * 8);
        cpa16(adst1 + OFF_AL(0), Al + arow1 + aseg1 * 8);
        CPA_COMMIT();
        #pragma unroll
        for (int it = 0; it < 4; it++) br[it] = *(const float4*)(B + brow[it]);
        CPA_WAIT();
        __syncthreads();
        #pragma unroll
        for (int it = 0; it < 4; it++) {
            int i = tid + it * 256;
            int kk = i >> 5;
            uint32_t h0 = pack_hi(br[it].x, br[it].y), h1 = pack_hi(br[it].z, br[it].w);
            uint32_t l0 = pack_lo(br[it].x, br[it].y, h0), l1 = pack_lo(br[it].z, br[it].w, h1);
            uint32_t* ph = (uint32_t*)(sm + OFF_BH(0) + kk * (LDB*2) + bcol[it] * 2);
            uint32_t* pl = (uint32_t*)(sm + OFF_BL(0) + kk * (LDB*2) + bcol[it] * 2);
            ph[0] = h0; ph[1] = h1;
            pl[0] = l0; pl[1] = l1;
        }
        __syncthreads();
    }

    int p = 0;
    for (int c = 0; c < nkt; c++) {
        const int q = p ^ 1;
        const bool more = (c + 1 < nkt);
        if (more) {
            const int k1 = (c + 1) << 5;
            cpa16(adst0 + OFF_AH(q), Ah + arow0 + k1 + aseg0 * 8);
            cpa16(adst0 + OFF_AL(q), Al + arow0 + k1 + aseg0 * 8);
            cpa16(adst1 + OFF_AH(q), Ah + arow1 + k1 + aseg1 * 8);
            cpa16(adst1 + OFF_AL(q), Al + arow1 + k1 + aseg1 * 8);
            CPA_COMMIT();
            #pragma unroll
            for (int it = 0; it < 4; it++)
                br[it] = *(const float4*)(B + (size_t)k1 * ldb + brow[it]);
        }

        // ---- MMA on buffer p ----
        const uint32_t uAh = sb + OFF_AH(p), uAl = sb + OFF_AL(p);
        const uint32_t uBh = sb + OFF_BH(p), uBl = sb + OFF_BL(p);
        #pragma unroll
        for (int ks = 0; ks < 2; ks++) {
            uint32_t ah[4][4], al[4][4], bh[2][4], bl[2][4];
            #pragma unroll
            for (int mf = 0; mf < 4; mf++) {
                uint32_t ro = (uint32_t)((wm * 64 + mf * 16 + lrow) * LDA + ks * 16 + lcol8) * 2;
                ldsm4(ah[mf], uAh + ro);
                ldsm4(al[mf], uAl + ro);
            }
            #pragma unroll
            for (int nh = 0; nh < 2; nh++) {
                uint32_t ro = (uint32_t)((ks * 16 + lrow) * LDB + wn * 32 + nh * 16 + lcol8) * 2;
                ldsm4t(bh[nh], uBh + ro);
                ldsm4t(bl[nh], uBl + ro);
            }
            #pragma unroll
            for (int mf = 0; mf < 4; mf++)
                #pragma unroll
                for (int nf = 0; nf < 4; nf++) {
                    uint32_t bh0 = bh[nf >> 1][(nf & 1) * 2], bh1 = bh[nf >> 1][(nf & 1) * 2 + 1];
                    uint32_t bl0 = bl[nf >> 1][(nf & 1) * 2], bl1 = bl[nf >> 1][(nf & 1) * 2 + 1];
                    mma16816(acc[mf][nf], ah[mf], bh0, bh1);
                    mma16816(acc[mf][nf], ah[mf], bl0, bl1);
                    mma16816(acc[mf][nf], al[mf], bh0, bh1);
                }
        }

        if (more) {
            #pragma unroll
            for (int it = 0; it < 4; it++) {
                int i = tid + it * 256;
                int kk = i >> 5;
                uint32_t h0 = pack_hi(br[it].x, br[it].y), h1 = pack_hi(br[it].z, br[it].w);
                uint32_t l0 = pack_lo(br[it].x, br[it].y, h0), l1 = pack_lo(br[it].z, br[it].w, h1);
                uint32_t* ph = (uint32_t*)(sm + OFF_BH(q) + kk * (LDB*2) + bcol[it] * 2);
                uint32_t* pl = (uint32_t*)(sm + OFF_BL(q) + kk * (LDB*2) + bcol[it] * 2);
                ph[0] = h0; ph[1] = h1;
                pl[0] = l0; pl[1] = l1;
            }
            CPA_WAIT();
            __syncthreads();
        }
        p = q;
    }
    __syncthreads();

    // ---- epilogue ----
    const int r4 = lane >> 2, c2 = (lane & 3) * 2;
    if (MODE == 0) {
        #pragma unroll
        for (int mf = 0; mf < 4; mf++) {
            #pragma unroll
            for (int nf = 0; nf < 4; nf++) {
                int col = nb + wn * 32 + nf * 8 + c2;
                size_t r1 = (size_t)(m0 + wm * 64 + mf * 16 + r4);
                size_t r2 = r1 + 8;
                float v0 = acc[mf][nf][0], v1 = acc[mf][nf][1];
                float v2 = acc[mf][nf][2], v3 = acc[mf][nf][3];
                if (add) {
                    v0 += add[r1 * ldc + col]; v1 += add[r1 * ldc + col + 1];
                    v2 += add[r2 * ldc + col]; v3 += add[r2 * ldc + col + 1];
                }
                *(float2*)(C + r1 * ldc + col) = make_float2(v0, v1);
                *(float2*)(C + r2 * ldc + col) = make_float2(v2, v3);
            }
        }
    } else if (MODE == 1 || MODE == 2) {
        float* sG = (float*)sm;              // [128][65]
        if (wn < 2) {
            #pragma unroll
            for (int mf = 0; mf < 4; mf++)
                #pragma unroll
                for (int nf = 0; nf < 4; nf++) {
                    int col = wn * 32 + nf * 8 + c2;
                    int rr1 = wm * 64 + mf * 16 + r4, rr2 = rr1 + 8;
                    sG[rr1 * 65 + col]     = acc[mf][nf][0];
                    sG[rr1 * 65 + col + 1] = acc[mf][nf][1];
                    sG[rr2 * 65 + col]     = acc[mf][nf][2];
                    sG[rr2 * 65 + col + 1] = acc[mf][nf][3];
                }
        }
        __syncthreads();
        if (wn >= 2) {
            #pragma unroll
            for (int mf = 0; mf < 4; mf++)
                #pragma unroll
                for (int nf = 0; nf < 4; nf++) {
                    int col = (wn - 2) * 32 + nf * 8 + c2;
                    int rr1 = wm * 64 + mf * 16 + r4;
                    #pragma unroll
                    for (int half = 0; half < 2; half++) {
                        int rr = rr1 + half * 8;
                        bool ok = (MODE == 1) || (m0 + rr < cnt);
                        if (ok) {
                            size_t row = (MODE == 1) ? (size_t)(m0 + rr) : (size_t)(off + m0 + rr);
                            float g0 = sG[rr * 65 + col], g1 = sG[rr * 65 + col + 1];
                            float u0 = acc[mf][nf][half * 2], u1 = acc[mf][nf][half * 2 + 1];
                            float o0 = g0 / (1.f + fexp(-g0)) * u0;
                            float o1 = g1 / (1.f + fexp(-g1)) * u1;
                            uint32_t hi, lo;
                            split2(o0, o1, hi, lo);
                            *(uint32_t*)(Ch + row * ldc + nb + col) = hi;
                            *(uint32_t*)(Cl + row * ldc + nb + col) = lo;
                        }
                    }
                }
        }
    } else {  // MODE 3
        #pragma unroll
        for (int mf = 0; mf < 4; mf++) {
            int rr1 = wm * 64 + mf * 16 + r4;
            #pragma unroll
            for (int half = 0; half < 2; half++) {
                int rr = rr1 + half * 8;
                if (m0 + rr < cnt) {
                    int tok = g_ptok[off + m0 + rr];
                    float w = g_pw[off + m0 + rr];
                    float* dst = C + (size_t)tok * ldc;
                    #pragma unroll
                    for (int nf = 0; nf < 4; nf++) {
                        int col = nb + wn * 32 + nf * 8 + c2;
                        atomicAdd(dst + col,     w * acc[mf][nf][half * 2]);
                        atomicAdd(dst + col + 1, w * acc[mf][nf][half * 2 + 1]);
                    }
                }
            }
        }
    }
}

// ------------------------- small kernels ------------------------------------
__global__ void zero_counts_k() {
    if (threadIdx.x < NEXP) g_cnt[threadIdx.x] = 0;
}

__global__ void cs_prep_k(const int* __restrict__ pos) {
    int t = blockIdx.x, i = threadIdx.x;   // 64 threads
    double e = exp(-((double)(2 * i) / 128.0) * log(500000.0));
    float f = (float)pos[t] * (float)e;
    float sn, cs; sincosf(f, &sn, &cs);
    g_cs[t * 64 + i] = make_float2(cs, sn);
}

// rmsnorm: writes optional fp32 y + optional bf16 split yh/yl
__global__ void rmsnorm_k(const float* __restrict__ x, const float* __restrict__ w,
                          float* __restrict__ y,
                          __nv_bfloat16* __restrict__ yh, __nv_bfloat16* __restrict__ yl,
                          int cols, int ldx, int ldy)
{
    int row = blockIdx.x;
    const float* xr = x + (size_t)row * ldx;
    float ss = 0.f;
    for (int c = threadIdx.x; c < cols; c += 256) { float v = xr[c]; ss = fmaf(v, v, ss); }
    __shared__ float wred[8];
    #pragma unroll
    for (int d = 16; d; d >>= 1) ss += __shfl_xor_sync(0xffffffffu, ss, d);
    if ((threadIdx.x & 31) == 0) wred[threadIdx.x >> 5] = ss;
    __syncthreads();
    if (threadIdx.x < 32) {
        float v = (threadIdx.x < 8) ? wred[threadIdx.x] : 0.f;
        #pragma unroll
        for (int d = 4; d; d >>= 1) v += __shfl_xor_sync(0xffffffffu, v, d);
        if (threadIdx.x == 0) wred[0] = v;
    }
    __syncthreads();
    float r = rsqrtf(wred[0] / (float)cols + 1e-5f);
    for (int c = threadIdx.x; c < cols; c += 256) {
        float v = xr[c] * r * w[c];
        if (y) y[(size_t)row * ldy + c] = v;
        if (yh) {
            __nv_bfloat16 h = __float2bfloat16_rn(v);
            yh[(size_t)row * ldy + c] = h;
            yl[(size_t)row * ldy + c] = __float2bfloat16_rn(v - __bfloat162float(h));
        }
    }
}

// rope on q (reads qproj fp32, writes split bf16 with SCALE folded)
__global__ void rope_q_k(const float* __restrict__ qp,
                         __nv_bfloat16* __restrict__ qh, __nv_bfloat16* __restrict__ ql)
{
    int t = blockIdx.x;
    for (int idx = threadIdx.x; idx < NHEAD * 64; idx += 256) {
        int hh = idx >> 6, i = idx & 63;
        float2 cs = g_cs[t * 64 + i];
        const float* b = qp + (size_t)t * 2048 + hh * HD;
        float x1 = b[i], x2 = b[i + 64];
        float y1 = (x1 * cs.x - x2 * cs.y) * SCALE;
        float y2 = (x2 * cs.x + x1 * cs.y) * SCALE;
        size_t o1 = (size_t)t * 2048 + hh * HD + i;
        __nv_bfloat16 h1 = __float2bfloat16_rn(y1);
        qh[o1] = h1; ql[o1] = __float2bfloat16_rn(y1 - __bfloat162float(h1));
        __nv_bfloat16 h2 = __float2bfloat16_rn(y2);
        qh[o1 + 64] = h2; ql[o1 + 64] = __float2bfloat16_rn(y2 - __bfloat162float(h2));
    }
}

// K rope + transpose split; V split
__global__ void kv_prep_k(const float* __restrict__ qkv)
{
    int t = blockIdx.x;
    int tid = threadIdx.x;   // 128
    if (tid < 64) {
        int i = tid;
        float2 cs = g_cs[t * 64 + i];
        const float* kb = qkv + (size_t)t * QKV_N + QDIM;
        float x1 = kb[i], x2 = kb[i + 64];
        float y1 = x1 * cs.x - x2 * cs.y;
        float y2 = x2 * cs.x + x1 * cs.y;
        __nv_bfloat16 h1 = __float2bfloat16_rn(y1);
        g_kth[(size_t)i * SEQ + t] = h1;
        g_ktl[(size_t)i * SEQ + t] = __float2bfloat16_rn(y1 - __bfloat162float(h1));
        __nv_bfloat16 h2 = __float2bfloat16_rn(y2);
        g_kth[(size_t)(i + 64) * SEQ + t] = h2;
        g_ktl[(size_t)(i + 64) * SEQ + t] = __float2bfloat16_rn(y2 - __bfloat162float(h2));
    }
    {
        float v = qkv[(size_t)t * QKV_N + QDIM + HD + tid];
        __nv_bfloat16 h = __float2bfloat16_rn(v);
        g_vh[(size_t)t * HD + tid] = h;
        g_vl[(size_t)t * HD + tid] = __float2bfloat16_rn(v - __bfloat162float(h));
    }
}

// ------------------------- attention: bf16 HMMA flash ----------------------
#define AQ_LD 136
#define AK_LD 72
#define AV_LD 136
#define AP_LD 72
#define AOF_QH 0
#define AOF_QL 34816
#define AOF_KH 69632
#define AOF_KL 88064
#define AOF_VH 106496
#define AOF_VL 123904
#define AOF_PH 141312
#define AOF_PL 159744
#define AOF_M  178176
#define AOF_L  178688
#define AOF_RMAX 179200
#define AOF_RSUM 180224
#define ATTN_SMEM 181248

__global__ __launch_bounds__(256, 1) void attn_k(
    const __nv_bfloat16* __restrict__ Qh, const __nv_bfloat16* __restrict__ Ql,
    __nv_bfloat16* __restrict__ Oh, __nv_bfloat16* __restrict__ Ol)
{
    extern __shared__ __align__(16) char sm[];
    const int bx = blockIdx.x;
    const int qt = 15 - (bx >> 4);     // longest tiles first
    const int h = bx & 15;
    const int q0 = qt * 128;

    const int tid = threadIdx.x;
    const int wid = tid >> 5, lane = tid & 31;
    const int wm = wid >> 1, wn = wid & 1;
    const int lrow = lane & 15, lcol8 = (lane >> 4) * 8;
    const int r4 = lane >> 2, c2 = (lane & 3) * 2;

    float* sM = (float*)(sm + AOF_M);
    float* sL = (float*)(sm + AOF_L);
    float* sRmax = (float*)(sm + AOF_RMAX);   // [2][128]
    float* sRsum = (float*)(sm + AOF_RSUM);   // [2][128]
    const uint32_t uQh = s2u(sm + AOF_QH), uQl = s2u(sm + AOF_QL);
    const uint32_t uKh = s2u(sm + AOF_KH), uKl = s2u(sm + AOF_KL);
    const uint32_t uVh = s2u(sm + AOF_VH), uVl = s2u(sm + AOF_VL);
    const uint32_t uPh = s2u(sm + AOF_PH), uPl = s2u(sm + AOF_PL);

    // load Q tile (128 x 128, hi+lo)
    #pragma unroll
    for (int it = 0; it < 8; it++) {
        int i = tid + it * 256;          // 2048 uint4 per copy
        int r = i >> 4, c = (i & 15) << 3;
        size_t src = (size_t)(q0 + r) * 2048 + h * HD + c;
        *(uint4*)(sm + AOF_QH + r * (AQ_LD*2) + c * 2) = *(const uint4*)(Qh + src);
        *(uint4*)(sm + AOF_QL + r * (AQ_LD*2) + c * 2) = *(const uint4*)(Ql + src);
    }
    if (tid < 128) { sM[tid] = -3.0e30f; sL[tid] = 0.f; }

    float o[2][8][4] = {};
    const int nkt = 2 * qt + 2;

    for (int kt = 0; kt < nkt; kt++) {
        const int k0 = kt * 64;
        __syncthreads();
        // load K tile (transposed source [d][tok]): 128 x 64
        #pragma unroll
        for (int it = 0; it < 4; it++) {
            int i = tid + it * 256;      // 1024 uint4 per copy
            int d = i >> 3, tc = (i & 7) << 3;
            size_t src = (size_t)d * SEQ + k0 + tc;
            *(uint4*)(sm + AOF_KH + d * (AK_LD*2) + tc * 2) = *(const uint4*)(g_kth + src);
            *(uint4*)(sm + AOF_KL + d * (AK_LD*2) + tc * 2) = *(const uint4*)(g_ktl + src);
        }
        // load V tile: 64 x 128
        #pragma unroll
        for (int it = 0; it < 4; it++) {
            int i = tid + it * 256;
            int r = i >> 4, c = (i & 15) << 3;
            size_t src = (size_t)(k0 + r) * HD + c;
            *(uint4*)(sm + AOF_VH + r * (AV_LD*2) + c * 2) = *(const uint4*)(g_vh + src);
            *(uint4*)(sm + AOF_VL + r * (AV_LD*2) + c * 2) = *(const uint4*)(g_vl + src);
        }
        __syncthreads();

        // ---- S = Q K^T (3-pass split) ----
        float sacc[2][4][4] = {};
        #pragma unroll
        for (int ks = 0; ks < 8; ks++) {
            uint32_t ah[2][4], al[2][4], bh[2][4], bl[2][4];
            #pragma unroll
            for (int mf = 0; mf < 2; mf++) {
                uint32_t ro = (uint32_t)((wm * 32 + mf * 16 + lrow) * AQ_LD + ks * 16 + lcol8) * 2;
                ldsm4(ah[mf], uQh + ro);
                ldsm4(al[mf], uQl + ro);
            }
            #pragma unroll
            for (int nh = 0; nh < 2; nh++) {
                uint32_t ro = (uint32_t)((ks * 16 + lrow) * AK_LD + wn * 32 + nh * 16 + lcol8) * 2;
                ldsm4t(bh[nh], uKh + ro);
                ldsm4t(bl[nh], uKl + ro);
            }
            #pragma unroll
            for (int mf = 0; mf < 2; mf++)
                #pragma unroll
                for (int nf = 0; nf < 4; nf++) {
                    uint32_t b0h = bh[nf >> 1][(nf & 1) * 2], b1h = bh[nf >> 1][(nf & 1) * 2 + 1];
                    uint32_t b0l = bl[nf >> 1][(nf & 1) * 2], b1l = bl[nf >> 1][(nf & 1) * 2 + 1];
                    mma16816(sacc[mf][nf], ah[mf], b0h, b1h);
                    mma16816(sacc[mf][nf], ah[mf], b0l, b1l);
                    mma16816(sacc[mf][nf], al[mf], b0h, b1h);
                }
        }

        // causal mask on diagonal tiles
        if (kt >= nkt - 2) {
            #pragma unroll
            for (int mf = 0; mf < 2; mf++)
                #pragma unroll
                for (int nf = 0; nf < 4; nf++)
                    #pragma unroll
                    for (int v = 0; v < 4; v++) {
                        int row = q0 + wm * 32 + mf * 16 + r4 + (v >= 2 ? 8 : 0);
                        int col = k0 + wn * 32 + nf * 8 + c2 + (v & 1);
                        if (col > row) sacc[mf][nf][v] = -1.0e30f;
                    }
        }

        // ---- row max (warp-local then cross-warp) ----
        float rmax[4] = {-3.0e30f, -3.0e30f, -3.0e30f, -3.0e30f};
        #pragma unroll
        for (int mf = 0; mf < 2; mf++)
            #pragma unroll
            for (int nf = 0; nf < 4; nf++) {
                rmax[mf*2]   = fmaxf(rmax[mf*2],   fmaxf(sacc[mf][nf][0], sacc[mf][nf][1]));
                rmax[mf*2+1] = fmaxf(rmax[mf*2+1], fmaxf(sacc[mf][nf][2], sacc[mf][nf][3]));
            }
        #pragma unroll
        for (int s = 0; s < 4; s++) {
            rmax[s] = fmaxf(rmax[s], __shfl_xor_sync(0xffffffffu, rmax[s], 1));
            rmax[s] = fmaxf(rmax[s], __shfl_xor_sync(0xffffffffu, rmax[s], 2));
        }
        if ((lane & 3) == 0) {
            #pragma unroll
            for (int s = 0; s < 4; s++) {
                int lr = wm * 32 + (s >> 1) * 16 + r4 + (s & 1) * 8;
                sRmax[wn * 128 + lr] = rmax[s];
            }
        }
        __syncthreads();

        float mn[4], fct[4];
        #pragma unroll
        for (int s = 0; s < 4; s++) {
            int lr = wm * 32 + (s >> 1) * 16 + r4 + (s & 1) * 8;
            float mo = sM[lr];
            float m2 = fmaxf(sRmax[lr], sRmax[128 + lr]);
            mn[s] = fmaxf(mo, m2);
            fct[s] = fexp(mo - mn[s]);
        }

        // ---- p = exp(s-mn), store split P, partial sums, rescale o ----
        float rsum[4] = {0.f, 0.f, 0.f, 0.f};
        #pragma unroll
        for (int mf = 0; mf < 2; mf++) {
            int lr0 = wm * 32 + mf * 16 + r4;
            #pragma unroll
            for (int nf = 0; nf < 4; nf++) {
                int col = wn * 32 + nf * 8 + c2;
                float p0 = fexp(sacc[mf][nf][0] - mn[mf*2]);
                float p1 = fexp(sacc[mf][nf][1] - mn[mf*2]);
                float p2 = fexp(sacc[mf][nf][2] - mn[mf*2+1]);
                float p3 = fexp(sacc[mf][nf][3] - mn[mf*2+1]);
                rsum[mf*2]   += p0 + p1;
                rsum[mf*2+1] += p2 + p3;
                uint32_t hi, lo;
                split2(p0, p1, hi, lo);
                *(uint32_t*)(sm + AOF_PH + (lr0 * AP_LD + col) * 2) = hi;
                *(uint32_t*)(sm + AOF_PL + (lr0 * AP_LD + col) * 2) = lo;
                split2(p2, p3, hi, lo);
                *(uint32_t*)(sm + AOF_PH + ((lr0 + 8) * AP_LD + col) * 2) = hi;
                *(uint32_t*)(sm + AOF_PL + ((lr0 + 8) * AP_LD + col) * 2) = lo;
            }
        }
        #pragma unroll
        for (int mf = 0; mf < 2; mf++)
            #pragma unroll
            for (int nf8 = 0; nf8 < 8; nf8++) {
                o[mf][nf8][0] *= fct[mf*2];   o[mf][nf8][1] *= fct[mf*2];
                o[mf][nf8][2] *= fct[mf*2+1]; o[mf][nf8][3] *= fct[mf*2+1];
            }
        #pragma unroll
        for (int s = 0; s < 4; s++) {
            rsum[s] += __shfl_xor_sync(0xffffffffu, rsum[s], 1);
            rsum[s] += __shfl_xor_sync(0xffffffffu, rsum[s], 2);
        }
        if ((lane & 3) == 0) {
            #pragma unroll
            for (int s = 0; s < 4; s++) {
                int lr = wm * 32 + (s >> 1) * 16 + r4 + (s & 1) * 8;
                sRsum[wn * 128 + lr] = rsum[s];
            }
        }
        __syncthreads();
        if (wn == 0 && (lane & 3) == 0) {
            #pragma unroll
            for (int s = 0; s < 4; s++) {
                int lr = wm * 32 + (s >> 1) * 16 + r4 + (s & 1) * 8;
                sL[lr] = sL[lr] * fct[s] + sRsum[lr] + sRsum[128 + lr];
                sM[lr] = mn[s];
            }
        }

        // ---- O += P V (3-pass split) ----
        #pragma unroll
        for (int ks = 0; ks < 4; ks++) {
            uint32_t aph[2][4], apl[2][4], bvh[4][4], bvl[4][4];
            #pragma unroll
            for (int mf = 0; mf < 2; mf++) {
                uint32_t ro = (uint32_t)((wm * 32 + mf * 16 + lrow) * AP_LD + ks * 16 + lcol8) * 2;
                ldsm4(aph[mf], uPh + ro);
                ldsm4(apl[mf], uPl + ro);
            }
            #pragma unroll
            for (int nh = 0; nh < 4; nh++) {
                uint32_t ro = (uint32_t)((ks * 16 + lrow) * AV_LD + wn * 64 + nh * 16 + lcol8) * 2;
                ldsm4t(bvh[nh], uVh + ro);
                ldsm4t(bvl[nh], uVl + ro);
            }
            #pragma unroll
            for (int mf = 0; mf < 2; mf++)
                #pragma unroll
                for (int nf8 = 0; nf8 < 8; nf8++) {
                    uint32_t b0h = bvh[nf8 >> 1][(nf8 & 1) * 2], b1h = bvh[nf8 >> 1][(nf8 & 1) * 2 + 1];
                    uint32_t b0l = bvl[nf8 >> 1][(nf8 & 1) * 2], b1l = bvl[nf8 >> 1][(nf8 & 1) * 2 + 1];
                    mma16816(o[mf][nf8], aph[mf], b0h, b1h);
                    mma16816(o[mf][nf8], aph[mf], b0l, b1l);
                    mma16816(o[mf][nf8], apl[mf], b0h, b1h);
                }
        }
    }
    __syncthreads();

    // ---- write O (split bf16) ----
    float inv[4];
    #pragma unroll
    for (int s = 0; s < 4; s++) {
        int lr = wm * 32 + (s >> 1) * 16 + r4 + (s & 1) * 8;
        inv[s] = 1.f / sL[lr];
    }
    #pragma unroll
    for (int mf = 0; mf < 2; mf++) {
        int row0 = q0 + wm * 32 + mf * 16 + r4;
        #pragma unroll
        for (int nf8 = 0; nf8 < 8; nf8++) {
            int col = h * HD + wn * 64 + nf8 * 8 + c2;
            uint32_t hi, lo;
            split2(o[mf][nf8][0] * inv[mf*2], o[mf][nf8][1] * inv[mf*2], hi, lo);
            *(uint32_t*)(Oh + (size_t)row0 * 2048 + col) = hi;
            *(uint32_t*)(Ol + (size_t)row0 * 2048 + col) = lo;
            split2(o[mf][nf8][2] * inv[mf*2+1], o[mf][nf8][3] * inv[mf*2+1], hi, lo);
            *(uint32_t*)(Oh + (size_t)(row0 + 8) * 2048 + col) = hi;
            *(uint32_t*)(Ol + (size_t)(row0 + 8) * 2048 + col) = lo;
        }
    }
}

// ------------------------- router / topk / scan / fill ---------------------
__global__ __launch_bounds__(256) void router_k(const float* __restrict__ X,
                                                const float* __restrict__ Wr)
{
    __shared__ float part[8][32];
    int t = blockIdx.x;
    int e = threadIdx.x & 31, p = threadIdx.x >> 5;
    const float* xr = X + (size_t)t * HID;
    float s = 0.f;
    for (int k = p * 128; k < p * 128 + 128; k++) s = fmaf(xr[k], Wr[k * 32 + e], s);
    part[p][e] = s;
    __syncthreads();
    if (threadIdx.x < 32) {
        float logit = 0.f;
        #pragma unroll
        for (int q = 0; q < 8; q++) logit += part[q][e];
        float m = logit;
        for (int d = 16; d; d >>= 1) m = fmaxf(m, __shfl_xor_sync(0xffffffffu, m, d));
        float ex = __expf(logit - m);
        float cur = ex;
        float wsel[3]; int isel[3];
        #pragma unroll
        for (int kk = 0; kk < 3; kk++) {
            float v = cur; int idx = e;
            for (int d = 16; d; d >>= 1) {
                float v2 = __shfl_xor_sync(0xffffffffu, v, d);
                int   i2 = __shfl_xor_sync(0xffffffffu, idx, d);
                if (v2 > v || (v2 == v && i2 < idx)) { v = v2; idx = i2; }
            }
            wsel[kk] = v; isel[kk] = idx;
            if (e == idx) cur = -1.f;
        }
        float tot = wsel[0] + wsel[1] + wsel[2];
        if (e < 3) { g_topi[t * 3 + e] = isel[e]; g_topw[t * 3 + e] = wsel[e] / tot; }
        if (e == 0) {
            atomicAdd(&g_cnt[isel[0]], 1);
            atomicAdd(&g_cnt[isel[1]], 1);
            atomicAdd(&g_cnt[isel[2]], 1);
        }
    }
}

__global__ void scan_k()
{
    int e = threadIdx.x;
    int c = g_cnt[e];
    int x = c;
    for (int d = 1; d < 32; d <<= 1) {
        int y = __shfl_up_sync(0xffffffffu, x, d);
        if (e >= d) x += y;
    }
    int excl = x - c;
    g_off[e] = excl;
    g_fill[e] = excl;
}

__global__ void fill_k()
{
    int t = blockIdx.x * 256 + threadIdx.x;
    if (t < SEQ) {
        #pragma unroll
        for (int k = 0; k < 3; k++) {
            int e = g_topi[t * 3 + k];
            int slot = atomicAdd(&g_fill[e], 1);
            g_ptok[slot] = t;
            g_pw[slot] = g_topw[t * 3 + k];
        }
    }
}

// ------------------------- launch ------------------------------------------
extern "C" void kernel_launch(void* const* d_in, const int* in_sizes, int n_in,
                              void* d_out, int out_size)
{
    const float* hidden   = (const float*)d_in[0];
    const float* w_in     = (const float*)d_in[1];
    const float* w_qkv    = (const float*)d_in[2];
    const float* w_inter  = (const float*)d_in[3];
    const float* w_q      = (const float*)d_in[4];
    const float* w_o      = (const float*)d_in[5];
    const float* w_post   = (const float*)d_in[6];
    const float* w_guse   = (const float*)d_in[7];
    const float* w_dse    = (const float*)d_in[8];
    const float* w_router = (const float*)d_in[9];
    const float* w_gue    = (const float*)d_in[10];
    const float* w_de     = (const float*)d_in[11];
    const int*   pos      = (const int*)d_in[12];
    float* out = (float*)d_out;

    float *qkv, *qproj, *resid2, *h2;
    cudaGetSymbolAddress((void**)&qkv,    g_qkv);
    cudaGetSymbolAddress((void**)&qproj,  g_qproj);
    cudaGetSymbolAddress((void**)&resid2, g_resid2);
    cudaGetSymbolAddress((void**)&h2,     g_h2);
    __nv_bfloat16 *hnh,*hnl,*qnh,*qnl,*qh,*ql,*aoh,*aol,*h2h,*h2l,*aseh,*asel,*aceh,*acel;
    cudaGetSymbolAddress((void**)&hnh, g_hnh);   cudaGetSymbolAddress((void**)&hnl, g_hnl);
    cudaGetSymbolAddress((void**)&qnh, g_qnh);   cudaGetSymbolAddress((void**)&qnl, g_qnl);
    cudaGetSymbolAddress((void**)&qh,  g_qh);    cudaGetSymbolAddress((void**)&ql,  g_ql);
    cudaGetSymbolAddress((void**)&aoh, g_aoh);   cudaGetSymbolAddress((void**)&aol, g_aol);
    cudaGetSymbolAddress((void**)&h2h, g_h2h);   cudaGetSymbolAddress((void**)&h2l, g_h2l);
    cudaGetSymbolAddress((void**)&aseh,g_aseh);  cudaGetSymbolAddress((void**)&asel,g_asel);
    cudaGetSymbolAddress((void**)&aceh,g_aceh);  cudaGetSymbolAddress((void**)&acel,g_acel);

    cudaFuncSetAttribute(attn_k, cudaFuncAttributeMaxDynamicSharedMemorySize, ATTN_SMEM);
    cudaFuncSetAttribute(gemm_tc<0>, cudaFuncAttributeMaxDynamicSharedMemorySize, SMEM_TOTAL_G);
    cudaFuncSetAttribute(gemm_tc<1>, cudaFuncAttributeMaxDynamicSharedMemorySize, SMEM_TOTAL_G);
    cudaFuncSetAttribute(gemm_tc<2>, cudaFuncAttributeMaxDynamicSharedMemorySize, SMEM_TOTAL_G);
    cudaFuncSetAttribute(gemm_tc<3>, cudaFuncAttributeMaxDynamicSharedMemorySize, SMEM_TOTAL_G);

    zero_counts_k<<<1, 32>>>();
    cs_prep_k<<<SEQ, 64>>>(pos);
    rmsnorm_k<<<SEQ, 256>>>(hidden, w_in, nullptr, hnh, hnl, HID, HID, HID);
    gemm_tc<0><<<dim3(QKV_N/128, SEQ/128), 256, SMEM_TOTAL_G>>>(
        hnh, hnl, w_qkv, qkv, nullptr, nullptr, nullptr, HID, HID, QKV_N, QKV_N, 0, 0);
    rmsnorm_k<<<SEQ, 256>>>(qkv, w_inter, nullptr, qnh, qnl, QDIM, QKV_N, QDIM);
    gemm_tc<0><<<dim3(2048/128, SEQ/128), 256, SMEM_TOTAL_G>>>(
        qnh, qnl, w_q, qproj, nullptr, nullptr, nullptr, QDIM, QDIM, 2048, 2048, 0, 0);
    rope_q_k<<<SEQ, 256>>>(qproj, qh, ql);
    kv_prep_k<<<SEQ, 128>>>(qkv);
    attn_k<<<256, 256, ATTN_SMEM>>>(qh, ql, aoh, aol);
    gemm_tc<0><<<dim3(HID/128, SEQ/128), 256, SMEM_TOTAL_G>>>(
        aoh, aol, w_o, resid2, nullptr, nullptr, hidden, 2048, 2048, HID, HID, 0, 0);
    rmsnorm_k<<<SEQ, 256>>>(resid2, w_post, h2, h2h, h2l, HID, HID, HID);
    gemm_tc<1><<<dim3(IDIM/64, SEQ/128), 256, SMEM_TOTAL_G>>>(
        h2h, h2l, w_guse, nullptr, aseh, asel, nullptr, HID, HID, 2*IDIM, IDIM, IDIM, 0);
    gemm_tc<0><<<dim3(HID/128, SEQ/128), 256, SMEM_TOTAL_G>>>(
        aseh, asel, w_dse, out, nullptr, nullptr, resid2, IDIM, IDIM, HID, HID, 0, 0);
    router_k<<<SEQ, 256>>>(h2, w_router);
    scan_k<<<1, 32>>>();
    fill_k<<<SEQ/256, 256>>>();
    gemm_tc<2><<<dim3(IDIM/64, 16, NEXP), 256, SMEM_TOTAL_G>>>(
        h2h, h2l, w_gue, nullptr, aceh, acel, nullptr, HID, HID, 2*IDIM, IDIM, IDIM,
        (size_t)HID * 2 * IDIM);
    gemm_tc<3><<<dim3(HID/128, 16, NEXP), 256, SMEM_TOTAL_G>>>(
        aceh, acel, w_de, out, nullptr, nullptr, nullptr, IDIM, IDIM, HID, HID, 0,
        (size_t)IDIM * HID);
}

// round 6
// speedup vs baseline: 4.1928x; 1.0480x over previous
#include <cuda_runtime.h>
#include <cuda_bf16.h>
#include <math.h>
#include <stdint.h>

#define SEQ 2048
#define HID 1024
#define NHEAD 16
#define HD 128
#define QDIM 512
#define NEXP 32
#define IDIM 1024
#define QKV_N 768
#define SCALE 0.08838834764831845f   // 1/sqrt(128)

// ------------------------- device scratch ----------------------------------
__device__ float g_qkv[SEQ*QKV_N];
__device__ float g_qproj[SEQ*NHEAD*HD];
__device__ float g_resid2[SEQ*HID];
__device__ float g_h2[SEQ*HID];
__device__ float2 g_cs[SEQ*64];

__device__ __nv_bfloat16 g_hnh[SEQ*HID],  g_hnl[SEQ*HID];
__device__ __nv_bfloat16 g_qnh[SEQ*QDIM], g_qnl[SEQ*QDIM];
__device__ __nv_bfloat16 g_qh[SEQ*2048],  g_ql[SEQ*2048];
__device__ __nv_bfloat16 g_kth[128*SEQ],  g_ktl[128*SEQ];   // transposed [d][token]
__device__ __nv_bfloat16 g_vh[SEQ*128],   g_vl[SEQ*128];
__device__ __nv_bfloat16 g_aoh[SEQ*2048], g_aol[SEQ*2048];
__device__ __nv_bfloat16 g_h2h[SEQ*HID],  g_h2l[SEQ*HID];
__device__ __nv_bfloat16 g_aseh[SEQ*IDIM],g_asel[SEQ*IDIM];
__device__ __nv_bfloat16 g_aceh[SEQ*3*IDIM], g_acel[SEQ*3*IDIM];

__device__ int   g_topi[SEQ*3];
__device__ float g_topw[SEQ*3];
__device__ int   g_cnt[NEXP];
__device__ int   g_off[NEXP];
__device__ int   g_fill[NEXP];
__device__ int   g_ptok[SEQ*3];
__device__ float g_pw[SEQ*3];

// ------------------------- helpers -----------------------------------------
__device__ __forceinline__ uint32_t s2u(const void* p) {
    uint32_t a;
    asm("{ .reg .u64 t; cvta.to.shared.u64 t, %1; cvt.u32.u64 %0, t; }" : "=r"(a) : "l"(p));
    return a;
}
__device__ __forceinline__ void ldsm4(uint32_t* r, uint32_t addr) {
    asm volatile("ldmatrix.sync.aligned.m8n8.x4.shared.b16 {%0,%1,%2,%3}, [%4];"
        : "=r"(r[0]), "=r"(r[1]), "=r"(r[2]), "=r"(r[3]) : "r"(addr));
}
__device__ __forceinline__ void ldsm4t(uint32_t* r, uint32_t addr) {
    asm volatile("ldmatrix.sync.aligned.m8n8.x4.trans.shared.b16 {%0,%1,%2,%3}, [%4];"
        : "=r"(r[0]), "=r"(r[1]), "=r"(r[2]), "=r"(r[3]) : "r"(addr));
}
__device__ __forceinline__ void mma16816(float* c, const uint32_t* a, uint32_t b0, uint32_t b1) {
    asm volatile("mma.sync.aligned.m16n8k16.row.col.f32.bf16.bf16.f32 "
        "{%0,%1,%2,%3}, {%4,%5,%6,%7}, {%8,%9}, {%0,%1,%2,%3};"
        : "+f"(c[0]), "+f"(c[1]), "+f"(c[2]), "+f"(c[3])
        : "r"(a[0]), "r"(a[1]), "r"(a[2]), "r"(a[3]), "r"(b0), "r"(b1));
}
__device__ __forceinline__ void cpa16(uint32_t dst, const void* src) {
    asm volatile("cp.async.cg.shared.global [%0], [%1], 16;" :: "r"(dst), "l"(src));
}
#define CPA_COMMIT() asm volatile("cp.async.commit_group;" ::: "memory")
#define CPA_WAIT()   asm volatile("cp.async.wait_group 0;" ::: "memory")

__device__ __forceinline__ uint32_t pack_hi(float f0, float f1) {
    __nv_bfloat162 h = __floats2bfloat162_rn(f0, f1);
    return *(uint32_t*)&h;
}
__device__ __forceinline__ uint32_t pack_lo(float f0, float f1, uint32_t hibits) {
    __nv_bfloat162 h = *(__nv_bfloat162*)&hibits;
    __nv_bfloat162 l = __floats2bfloat162_rn(f0 - __bfloat162float(h.x),
                                             f1 - __bfloat162float(h.y));
    return *(uint32_t*)&l;
}
__device__ __forceinline__ void split2(float a, float b, uint32_t& hi, uint32_t& lo) {
    hi = pack_hi(a, b);
    lo = pack_lo(a, b, hi);
}
// FFMA-only exp (rel err ~4e-5), avoids MUFU
__device__ __forceinline__ float fexp(float x) {
    x = fminf(fmaxf(x, -80.f), 80.f);
    float y = x * 1.4426950408889634f;
    float n = rintf(y);
    float f = y - n;
    float p = fmaf(f, 0.009618130f, 0.055504110f);
    p = fmaf(p, f, 0.240226507f);
    p = fmaf(p, f, 0.693147181f);
    p = fmaf(p, f, 1.0f);
    return p * __int_as_float(((int)n + 127) << 23);
}

// ------------------------- GEMM: 128 threads, 4 warps of 64x64 --------------
#define LDA 40
#define LDB 136
#define ASZ (128*LDA*2)          // 10240 bytes per A array
#define BSZ (32*LDB*2)           // 8704 bytes per B array
#define OFF_AH(b) ((b) * (2*ASZ))
#define OFF_AL(b) ((b) * (2*ASZ) + ASZ)
#define OFF_BH(b) (4*ASZ + (b) * (2*BSZ))
#define OFF_BL(b) (4*ASZ + (b) * (2*BSZ) + BSZ)
#define OFF_TOK   (4*ASZ + 4*BSZ)
#define SMEM_TOTAL_G (OFF_TOK + 128*4)

// MODE 0: plain  C = A@B (+add) fp32       (128 out cols / CTA)
// MODE 1: gated  Ch/Cl = split(silu(A@Bg)*(A@Bu))  (64 cols/CTA, up at +upOff)
// MODE 2: moe gathered gated -> split rows off+r
// MODE 3: moe scatter: C[tok] += w * (A@B)  fp32 atomic
template<int MODE>
__global__ __launch_bounds__(128, 2) void gemm_tc(
    const __nv_bfloat16* __restrict__ Ah, const __nv_bfloat16* __restrict__ Al,
    const float* __restrict__ B,
    float* __restrict__ C, __nv_bfloat16* __restrict__ Ch, __nv_bfloat16* __restrict__ Cl,
    const float* __restrict__ add,
    int K, int lda, int ldb, int ldc, int upOff, size_t bStride)
{
    int cnt = 0, off = 0;
    if (MODE >= 2) {
        int e = blockIdx.z;
        cnt = g_cnt[e];
        if ((int)blockIdx.y * 128 >= cnt) return;
        off = g_off[e];
        B += bStride * e;
    }
    const int m0 = blockIdx.y * 128;
    const int nb = blockIdx.x * ((MODE == 1 || MODE == 2) ? 64 : 128);

    extern __shared__ __align__(16) char sm[];
    int* sTok = (int*)(sm + OFF_TOK);
    const uint32_t sb = s2u(sm);

    const int tid = threadIdx.x;
    const int wid = tid >> 5, lane = tid & 31;
    const int wm = wid >> 1, wn = wid & 1;

    if (MODE == 2) {
        sTok[tid] = (m0 + tid < cnt) ? g_ptok[off + m0 + tid] : 0;
    }
    __syncthreads();

    float acc[4][8][4] = {};
    const int lrow = lane & 15, lcol8 = (lane >> 4) * 8;

    // A cp.async indexing: 4 segments per thread (512 total = 128 rows x 4)
    size_t arow[4]; uint32_t adst[4]; int aoff[4];
    #pragma unroll
    for (int it = 0; it < 4; it++) {
        int s = tid + it * 128;
        int m = s >> 2, seg = s & 3;
        size_t rb;
        if (MODE == 2) {
            rb = (size_t)sTok[m] * lda;
        } else if (MODE == 3) {
            int r = (m0 + m < cnt) ? m0 + m : 0;
            rb = (size_t)(off + r) * lda;
        } else {
            rb = (size_t)(m0 + m) * lda;
        }
        arow[it] = rb;
        adst[it] = sb + m * (LDA*2) + seg * 16;
        aoff[it] = seg * 8;
    }

    // B load indexing (8 float4 per thread)
    int bcol[8]; size_t brow[8];
    #pragma unroll
    for (int it = 0; it < 8; it++) {
        int i = tid + it * 128;
        int kk = i >> 5;
        int n4 = (i & 31) << 2;
        int col;
        if (MODE == 1 || MODE == 2) col = (n4 < 64) ? nb + n4 : upOff + nb + (n4 - 64);
        else                        col = nb + n4;
        bcol[it] = n4;
        brow[it] = (size_t)kk * ldb + col;
    }

    const int nkt = K >> 5;
    float4 br[8];

    // ---- prologue: chunk 0 ----
    {
        #pragma unroll
        for (int it = 0; it < 4; it++) {
            cpa16(adst[it] + OFF_AH(0), Ah + arow[it] + aoff[it]);
            cpa16(adst[it] + OFF_AL(0), Al + arow[it] + aoff[it]);
        }
        CPA_COMMIT();
        #pragma unroll
        for (int it = 0; it < 8; it++) br[it] = *(const float4*)(B + brow[it]);
        CPA_WAIT();
        __syncthreads();
        #pragma unroll
        for (int it = 0; it < 8; it++) {
            int i = tid + it * 128;
            int kk = i >> 5;
            uint32_t h0 = pack_hi(br[it].x, br[it].y), h1 = pack_hi(br[it].z, br[it].w);
            uint32_t l0 = pack_lo(br[it].x, br[it].y, h0), l1 = pack_lo(br[it].z, br[it].w, h1);
            uint32_t* ph = (uint32_t*)(sm + OFF_BH(0) + kk * (LDB*2) + bcol[it] * 2);
            uint32_t* pl = (uint32_t*)(sm + OFF_BL(0) + kk * (LDB*2) + bcol[it] * 2);
            ph[0] = h0; ph[1] = h1;
            pl[0] = l0; pl[1] = l1;
        }
        __syncthreads();
    }

    int p = 0;
    for (int c = 0; c < nkt; c++) {
        const int q = p ^ 1;
        const bool more = (c + 1 < nkt);
        if (more) {
            const int k1 = (c + 1) << 5;
            #pragma unroll
            for (int it = 0; it < 4; it++) {
                cpa16(adst[it] + OFF_AH(q), Ah + arow[it] + k1 + aoff[it]);
                cpa16(adst[it] + OFF_AL(q), Al + arow[it] + k1 + aoff[it]);
            }
            CPA_COMMIT();
            #pragma unroll
            for (int it = 0; it < 8; it++)
                br[it] = *(const float4*)(B + (size_t)k1 * ldb + brow[it]);
        }

        // ---- MMA on buffer p : warp tile 64x64 ----
        const uint32_t uAh = sb + OFF_AH(p), uAl = sb + OFF_AL(p);
        const uint32_t uBh = sb + OFF_BH(p), uBl = sb + OFF_BL(p);
        #pragma unroll
        for (int ks = 0; ks < 2; ks++) {
            uint32_t ah[4][4], al[4][4];
            #pragma unroll
            for (int mf = 0; mf < 4; mf++) {
                uint32_t ro = (uint32_t)((wm * 64 + mf * 16 + lrow) * LDA + ks * 16 + lcol8) * 2;
                ldsm4(ah[mf], uAh + ro);
                ldsm4(al[mf], uAl + ro);
            }
            #pragma unroll
            for (int nh = 0; nh < 4; nh++) {
                uint32_t bh[4], bl[4];
                uint32_t ro = (uint32_t)((ks * 16 + lrow) * LDB + wn * 64 + nh * 16 + lcol8) * 2;
                ldsm4t(bh, uBh + ro);
                ldsm4t(bl, uBl + ro);
                #pragma unroll
                for (int mf = 0; mf < 4; mf++)
                    #pragma unroll
                    for (int sub = 0; sub < 2; sub++) {
                        int nf = nh * 2 + sub;
                        uint32_t b0h = bh[sub * 2], b1h = bh[sub * 2 + 1];
                        uint32_t b0l = bl[sub * 2], b1l = bl[sub * 2 + 1];
                        mma16816(acc[mf][nf], ah[mf], b0h, b1h);
                        mma16816(acc[mf][nf], ah[mf], b0l, b1l);
                        mma16816(acc[mf][nf], al[mf], b0h, b1h);
                    }
            }
        }

        if (more) {
            #pragma unroll
            for (int it = 0; it < 8; it++) {
                int i = tid + it * 128;
                int kk = i >> 5;
                uint32_t h0 = pack_hi(br[it].x, br[it].y), h1 = pack_hi(br[it].z, br[it].w);
                uint32_t l0 = pack_lo(br[it].x, br[it].y, h0), l1 = pack_lo(br[it].z, br[it].w, h1);
                uint32_t* ph = (uint32_t*)(sm + OFF_BH(q) + kk * (LDB*2) + bcol[it] * 2);
                uint32_t* pl = (uint32_t*)(sm + OFF_BL(q) + kk * (LDB*2) + bcol[it] * 2);
                ph[0] = h0; ph[1] = h1;
                pl[0] = l0; pl[1] = l1;
            }
            CPA_WAIT();
            __syncthreads();
        }
        p = q;
    }
    __syncthreads();

    // ---- epilogue ----
    const int r4 = lane >> 2, c2 = (lane & 3) * 2;
    if (MODE == 0) {
        #pragma unroll
        for (int mf = 0; mf < 4; mf++) {
            #pragma unroll
            for (int nf = 0; nf < 8; nf++) {
                int col = nb + wn * 64 + nf * 8 + c2;
                size_t r1 = (size_t)(m0 + wm * 64 + mf * 16 + r4);
                size_t r2 = r1 + 8;
                float v0 = acc[mf][nf][0], v1 = acc[mf][nf][1];
                float v2 = acc[mf][nf][2], v3 = acc[mf][nf][3];
                if (add) {
                    v0 += add[r1 * ldc + col]; v1 += add[r1 * ldc + col + 1];
                    v2 += add[r2 * ldc + col]; v3 += add[r2 * ldc + col + 1];
                }
                *(float2*)(C + r1 * ldc + col) = make_float2(v0, v1);
                *(float2*)(C + r2 * ldc + col) = make_float2(v2, v3);
            }
        }
    } else if (MODE == 1 || MODE == 2) {
        float* sG = (float*)sm;              // [128][65]
        if (wn == 0) {                        // gate cols 0..63
            #pragma unroll
            for (int mf = 0; mf < 4; mf++)
                #pragma unroll
                for (int nf = 0; nf < 8; nf++) {
                    int col = nf * 8 + c2;
                    int rr1 = wm * 64 + mf * 16 + r4, rr2 = rr1 + 8;
                    sG[rr1 * 65 + col]     = acc[mf][nf][0];
                    sG[rr1 * 65 + col + 1] = acc[mf][nf][1];
                    sG[rr2 * 65 + col]     = acc[mf][nf][2];
                    sG[rr2 * 65 + col + 1] = acc[mf][nf][3];
                }
        }
        __syncthreads();
        if (wn == 1) {                        // up cols -> combine
            #pragma unroll
            for (int mf = 0; mf < 4; mf++)
                #pragma unroll
                for (int nf = 0; nf < 8; nf++) {
                    int col = nf * 8 + c2;
                    int rr1 = wm * 64 + mf * 16 + r4;
                    #pragma unroll
                    for (int half = 0; half < 2; half++) {
                        int rr = rr1 + half * 8;
                        bool ok = (MODE == 1) || (m0 + rr < cnt);
                        if (ok) {
                            size_t row = (MODE == 1) ? (size_t)(m0 + rr) : (size_t)(off + m0 + rr);
                            float g0 = sG[rr * 65 + col], g1 = sG[rr * 65 + col + 1];
                            float u0 = acc[mf][nf][half * 2], u1 = acc[mf][nf][half * 2 + 1];
                            float o0 = g0 / (1.f + fexp(-g0)) * u0;
                            float o1 = g1 / (1.f + fexp(-g1)) * u1;
                            uint32_t hi, lo;
                            split2(o0, o1, hi, lo);
                            *(uint32_t*)(Ch + row * ldc + nb + col) = hi;
                            *(uint32_t*)(Cl + row * ldc + nb + col) = lo;
                        }
                    }
                }
        }
    } else {  // MODE 3
        #pragma unroll
        for (int mf = 0; mf < 4; mf++) {
            int rr1 = wm * 64 + mf * 16 + r4;
            #pragma unroll
            for (int half = 0; half < 2; half++) {
                int rr = rr1 + half * 8;
                if (m0 + rr < cnt) {
                    int tok = g_ptok[off + m0 + rr];
                    float w = g_pw[off + m0 + rr];
                    float* dst = C + (size_t)tok * ldc;
                    #pragma unroll
                    for (int nf = 0; nf < 8; nf++) {
                        int col = nb + wn * 64 + nf * 8 + c2;
                        atomicAdd(dst + col,     w * acc[mf][nf][half * 2]);
                        atomicAdd(dst + col + 1, w * acc[mf][nf][half * 2 + 1]);
                    }
                }
            }
        }
    }
}

// ------------------------- small kernels ------------------------------------
__global__ void zero_counts_k() {
    if (threadIdx.x < NEXP) g_cnt[threadIdx.x] = 0;
}

__global__ void cs_prep_k(const int* __restrict__ pos) {
    int t = blockIdx.x, i = threadIdx.x;   // 64 threads
    double e = exp(-((double)(2 * i) / 128.0) * log(500000.0));
    float f = (float)pos[t] * (float)e;
    float sn, cs; sincosf(f, &sn, &cs);
    g_cs[t * 64 + i] = make_float2(cs, sn);
}

// rmsnorm: writes optional fp32 y + optional bf16 split yh/yl
__global__ void rmsnorm_k(const float* __restrict__ x, const float* __restrict__ w,
                          float* __restrict__ y,
                          __nv_bfloat16* __restrict__ yh, __nv_bfloat16* __restrict__ yl,
                          int cols, int ldx, int ldy)
{
    int row = blockIdx.x;
    const float* xr = x + (size_t)row * ldx;
    float ss = 0.f;
    for (int c = threadIdx.x; c < cols; c += 256) { float v = xr[c]; ss = fmaf(v, v, ss); }
    __shared__ float wred[8];
    #pragma unroll
    for (int d = 16; d; d >>= 1) ss += __shfl_xor_sync(0xffffffffu, ss, d);
    if ((threadIdx.x & 31) == 0) wred[threadIdx.x >> 5] = ss;
    __syncthreads();
    if (threadIdx.x < 32) {
        float v = (threadIdx.x < 8) ? wred[threadIdx.x] : 0.f;
        #pragma unroll
        for (int d = 4; d; d >>= 1) v += __shfl_xor_sync(0xffffffffu, v, d);
        if (threadIdx.x == 0) wred[0] = v;
    }
    __syncthreads();
    float r = rsqrtf(wred[0] / (float)cols + 1e-5f);
    for (int c = threadIdx.x; c < cols; c += 256) {
        float v = xr[c] * r * w[c];
        if (y) y[(size_t)row * ldy + c] = v;
        if (yh) {
            __nv_bfloat16 h = __float2bfloat16_rn(v);
            yh[(size_t)row * ldy + c] = h;
            yl[(size_t)row * ldy + c] = __float2bfloat16_rn(v - __bfloat162float(h));
        }
    }
}

// rope on q (reads qproj fp32, writes split bf16 with SCALE folded)
__global__ void rope_q_k(const float* __restrict__ qp,
                         __nv_bfloat16* __restrict__ qh, __nv_bfloat16* __restrict__ ql)
{
    int t = blockIdx.x;
    for (int idx = threadIdx.x; idx < NHEAD * 64; idx += 256) {
        int hh = idx >> 6, i = idx & 63;
        float2 cs = g_cs[t * 64 + i];
        const float* b = qp + (size_t)t * 2048 + hh * HD;
        float x1 = b[i], x2 = b[i + 64];
        float y1 = (x1 * cs.x - x2 * cs.y) * SCALE;
        float y2 = (x2 * cs.x + x1 * cs.y) * SCALE;
        size_t o1 = (size_t)t * 2048 + hh * HD + i;
        __nv_bfloat16 h1 = __float2bfloat16_rn(y1);
        qh[o1] = h1; ql[o1] = __float2bfloat16_rn(y1 - __bfloat162float(h1));
        __nv_bfloat16 h2 = __float2bfloat16_rn(y2);
        qh[o1 + 64] = h2; ql[o1 + 64] = __float2bfloat16_rn(y2 - __bfloat162float(h2));
    }
}

// K rope + transpose split; V split
__global__ void kv_prep_k(const float* __restrict__ qkv)
{
    int t = blockIdx.x;
    int tid = threadIdx.x;   // 128
    if (tid < 64) {
        int i = tid;
        float2 cs = g_cs[t * 64 + i];
        const float* kb = qkv + (size_t)t * QKV_N + QDIM;
        float x1 = kb[i], x2 = kb[i + 64];
        float y1 = x1 * cs.x - x2 * cs.y;
        float y2 = x2 * cs.x + x1 * cs.y;
        __nv_bfloat16 h1 = __float2bfloat16_rn(y1);
        g_kth[(size_t)i * SEQ + t] = h1;
        g_ktl[(size_t)i * SEQ + t] = __float2bfloat16_rn(y1 - __bfloat162float(h1));
        __nv_bfloat16 h2 = __float2bfloat16_rn(y2);
        g_kth[(size_t)(i + 64) * SEQ + t] = h2;
        g_ktl[(size_t)(i + 64) * SEQ + t] = __float2bfloat16_rn(y2 - __bfloat162float(h2));
    }
    {
        float v = qkv[(size_t)t * QKV_N + QDIM + HD + tid];
        __nv_bfloat16 h = __float2bfloat16_rn(v);
        g_vh[(size_t)t * HD + tid] = h;
        g_vl[(size_t)t * HD + tid] = __float2bfloat16_rn(v - __bfloat162float(h));
    }
}

// ------------------------- attention: bf16 HMMA flash ----------------------
#define AQ_LD 136
#define AK_LD 72
#define AV_LD 136
#define AP_LD 72
#define AOF_QH 0
#define AOF_QL 34816
#define AOF_KH 69632
#define AOF_KL 88064
#define AOF_VH 106496
#define AOF_VL 123904
#define AOF_PH 141312
#define AOF_PL 159744
#define AOF_M  178176
#define AOF_L  178688
#define AOF_RMAX 179200
#define AOF_RSUM 180224
#define ATTN_SMEM 181248

__global__ __launch_bounds__(256, 1) void attn_k(
    const __nv_bfloat16* __restrict__ Qh, const __nv_bfloat16* __restrict__ Ql,
    __nv_bfloat16* __restrict__ Oh, __nv_bfloat16* __restrict__ Ol)
{
    extern __shared__ __align__(16) char sm[];
    const int bx = blockIdx.x;
    const int qt = 15 - (bx >> 4);     // longest tiles first
    const int h = bx & 15;
    const int q0 = qt * 128;

    const int tid = threadIdx.x;
    const int wid = tid >> 5, lane = tid & 31;
    const int wm = wid >> 1, wn = wid & 1;
    const int lrow = lane & 15, lcol8 = (lane >> 4) * 8;
    const int r4 = lane >> 2, c2 = (lane & 3) * 2;

    float* sM = (float*)(sm + AOF_M);
    float* sL = (float*)(sm + AOF_L);
    float* sRmax = (float*)(sm + AOF_RMAX);   // [2][128]
    float* sRsum = (float*)(sm + AOF_RSUM);   // [2][128]
    const uint32_t uQh = s2u(sm + AOF_QH), uQl = s2u(sm + AOF_QL);
    const uint32_t uKh = s2u(sm + AOF_KH), uKl = s2u(sm + AOF_KL);
    const uint32_t uVh = s2u(sm + AOF_VH), uVl = s2u(sm + AOF_VL);
    const uint32_t uPh = s2u(sm + AOF_PH), uPl = s2u(sm + AOF_PL);

    // load Q tile (128 x 128, hi+lo)
    #pragma unroll
    for (int it = 0; it < 8; it++) {
        int i = tid + it * 256;          // 2048 uint4 per copy
        int r = i >> 4, c = (i & 15) << 3;
        size_t src = (size_t)(q0 + r) * 2048 + h * HD + c;
        *(uint4*)(sm + AOF_QH + r * (AQ_LD*2) + c * 2) = *(const uint4*)(Qh + src);
        *(uint4*)(sm + AOF_QL + r * (AQ_LD*2) + c * 2) = *(const uint4*)(Ql + src);
    }
    if (tid < 128) { sM[tid] = -3.0e30f; sL[tid] = 0.f; }

    float o[2][8][4] = {};
    const int nkt = 2 * qt + 2;

    for (int kt = 0; kt < nkt; kt++) {
        const int k0 = kt * 64;
        __syncthreads();
        // load K tile (transposed source [d][tok]): 128 x 64
        #pragma unroll
        for (int it = 0; it < 4; it++) {
            int i = tid + it * 256;      // 1024 uint4 per copy
            int d = i >> 3, tc = (i & 7) << 3;
            size_t src = (size_t)d * SEQ + k0 + tc;
            *(uint4*)(sm + AOF_KH + d * (AK_LD*2) + tc * 2) = *(const uint4*)(g_kth + src);
            *(uint4*)(sm + AOF_KL + d * (AK_LD*2) + tc * 2) = *(const uint4*)(g_ktl + src);
        }
        // load V tile: 64 x 128
        #pragma unroll
        for (int it = 0; it < 4; it++) {
            int i = tid + it * 256;
            int r = i >> 4, c = (i & 15) << 3;
            size_t src = (size_t)(k0 + r) * HD + c;
            *(uint4*)(sm + AOF_VH + r * (AV_LD*2) + c * 2) = *(const uint4*)(g_vh + src);
            *(uint4*)(sm + AOF_VL + r * (AV_LD*2) + c * 2) = *(const uint4*)(g_vl + src);
        }
        __syncthreads();

        // ---- S = Q K^T (3-pass split) ----
        float sacc[2][4][4] = {};
        #pragma unroll
        for (int ks = 0; ks < 8; ks++) {
            uint32_t ah[2][4], al[2][4], bh[2][4], bl[2][4];
            #pragma unroll
            for (int mf = 0; mf < 2; mf++) {
                uint32_t ro = (uint32_t)((wm * 32 + mf * 16 + lrow) * AQ_LD + ks * 16 + lcol8) * 2;
                ldsm4(ah[mf], uQh + ro);
                ldsm4(al[mf], uQl + ro);
            }
            #pragma unroll
            for (int nh = 0; nh < 2; nh++) {
                uint32_t ro = (uint32_t)((ks * 16 + lrow) * AK_LD + wn * 32 + nh * 16 + lcol8) * 2;
                ldsm4t(bh[nh], uKh + ro);
                ldsm4t(bl[nh], uKl + ro);
            }
            #pragma unroll
            for (int mf = 0; mf < 2; mf++)
                #pragma unroll
                for (int nf = 0; nf < 4; nf++) {
                    uint32_t b0h = bh[nf >> 1][(nf & 1) * 2], b1h = bh[nf >> 1][(nf & 1) * 2 + 1];
                    uint32_t b0l = bl[nf >> 1][(nf & 1) * 2], b1l = bl[nf >> 1][(nf & 1) * 2 + 1];
                    mma16816(sacc[mf][nf], ah[mf], b0h, b1h);
                    mma16816(sacc[mf][nf], ah[mf], b0l, b1l);
                    mma16816(sacc[mf][nf], al[mf], b0h, b1h);
                }
        }

        // causal mask on diagonal tiles
        if (kt >= nkt - 2) {
            #pragma unroll
            for (int mf = 0; mf < 2; mf++)
                #pragma unroll
                for (int nf = 0; nf < 4; nf++)
                    #pragma unroll
                    for (int v = 0; v < 4; v++) {
                        int row = q0 + wm * 32 + mf * 16 + r4 + (v >= 2 ? 8 : 0);
                        int col = k0 + wn * 32 + nf * 8 + c2 + (v & 1);
                        if (col > row) sacc[mf][nf][v] = -1.0e30f;
                    }
        }

        // ---- row max (warp-local then cross-warp) ----
        float rmax[4] = {-3.0e30f, -3.0e30f, -3.0e30f, -3.0e30f};
        #pragma unroll
        for (int mf = 0; mf < 2; mf++)
            #pragma unroll
            for (int nf = 0; nf < 4; nf++) {
                rmax[mf*2]   = fmaxf(rmax[mf*2],   fmaxf(sacc[mf][nf][0], sacc[mf][nf][1]));
                rmax[mf*2+1] = fmaxf(rmax[mf*2+1], fmaxf(sacc[mf][nf][2], sacc[mf][nf][3]));
            }
        #pragma unroll
        for (int s = 0; s < 4; s++) {
            rmax[s] = fmaxf(rmax[s], __shfl_xor_sync(0xffffffffu, rmax[s], 1));
            rmax[s] = fmaxf(rmax[s], __shfl_xor_sync(0xffffffffu, rmax[s], 2));
        }
        if ((lane & 3) == 0) {
            #pragma unroll
            for (int s = 0; s < 4; s++) {
                int lr = wm * 32 + (s >> 1) * 16 + r4 + (s & 1) * 8;
                sRmax[wn * 128 + lr] = rmax[s];
            }
        }
        __syncthreads();

        float mn[4], fct[4];
        #pragma unroll
        for (int s = 0; s < 4; s++) {
            int lr = wm * 32 + (s >> 1) * 16 + r4 + (s & 1) * 8;
            float mo = sM[lr];
            float m2 = fmaxf(sRmax[lr], sRmax[128 + lr]);
            mn[s] = fmaxf(mo, m2);
            fct[s] = fexp(mo - mn[s]);
        }

        // ---- p = exp(s-mn), store split P, partial sums, rescale o ----
        float rsum[4] = {0.f, 0.f, 0.f, 0.f};
        #pragma unroll
        for (int mf = 0; mf < 2; mf++) {
            int lr0 = wm * 32 + mf * 16 + r4;
            #pragma unroll
            for (int nf = 0; nf < 4; nf++) {
                int col = wn * 32 + nf * 8 + c2;
                float p0 = fexp(sacc[mf][nf][0] - mn[mf*2]);
                float p1 = fexp(sacc[mf][nf][1] - mn[mf*2]);
                float p2 = fexp(sacc[mf][nf][2] - mn[mf*2+1]);
                float p3 = fexp(sacc[mf][nf][3] - mn[mf*2+1]);
                rsum[mf*2]   += p0 + p1;
                rsum[mf*2+1] += p2 + p3;
                uint32_t hi, lo;
                split2(p0, p1, hi, lo);
                *(uint32_t*)(sm + AOF_PH + (lr0 * AP_LD + col) * 2) = hi;
                *(uint32_t*)(sm + AOF_PL + (lr0 * AP_LD + col) * 2) = lo;
                split2(p2, p3, hi, lo);
                *(uint32_t*)(sm + AOF_PH + ((lr0 + 8) * AP_LD + col) * 2) = hi;
                *(uint32_t*)(sm + AOF_PL + ((lr0 + 8) * AP_LD + col) * 2) = lo;
            }
        }
        #pragma unroll
        for (int mf = 0; mf < 2; mf++)
            #pragma unroll
            for (int nf8 = 0; nf8 < 8; nf8++) {
                o[mf][nf8][0] *= fct[mf*2];   o[mf][nf8][1] *= fct[mf*2];
                o[mf][nf8][2] *= fct[mf*2+1]; o[mf][nf8][3] *= fct[mf*2+1];
            }
        #pragma unroll
        for (int s = 0; s < 4; s++) {
            rsum[s] += __shfl_xor_sync(0xffffffffu, rsum[s], 1);
            rsum[s] += __shfl_xor_sync(0xffffffffu, rsum[s], 2);
        }
        if ((lane & 3) == 0) {
            #pragma unroll
            for (int s = 0; s < 4; s++) {
                int lr = wm * 32 + (s >> 1) * 16 + r4 + (s & 1) * 8;
                sRsum[wn * 128 + lr] = rsum[s];
            }
        }
        __syncthreads();
        if (wn == 0 && (lane & 3) == 0) {
            #pragma unroll
            for (int s = 0; s < 4; s++) {
                int lr = wm * 32 + (s >> 1) * 16 + r4 + (s & 1) * 8;
                sL[lr] = sL[lr] * fct[s] + sRsum[lr] + sRsum[128 + lr];
                sM[lr] = mn[s];
            }
        }

        // ---- O += P V (3-pass split) ----
        #pragma unroll
        for (int ks = 0; ks < 4; ks++) {
            uint32_t aph[2][4], apl[2][4], bvh[4][4], bvl[4][4];
            #pragma unroll
            for (int mf = 0; mf < 2; mf++) {
                uint32_t ro = (uint32_t)((wm * 32 + mf * 16 + lrow) * AP_LD + ks * 16 + lcol8) * 2;
                ldsm4(aph[mf], uPh + ro);
                ldsm4(apl[mf], uPl + ro);
            }
            #pragma unroll
            for (int nh = 0; nh < 4; nh++) {
                uint32_t ro = (uint32_t)((ks * 16 + lrow) * AV_LD + wn * 64 + nh * 16 + lcol8) * 2;
                ldsm4t(bvh[nh], uVh + ro);
                ldsm4t(bvl[nh], uVl + ro);
            }
            #pragma unroll
            for (int mf = 0; mf < 2; mf++)
                #pragma unroll
                for (int nf8 = 0; nf8 < 8; nf8++) {
                    uint32_t b0h = bvh[nf8 >> 1][(nf8 & 1) * 2], b1h = bvh[nf8 >> 1][(nf8 & 1) * 2 + 1];
                    uint32_t b0l = bvl[nf8 >> 1][(nf8 & 1) * 2], b1l = bvl[nf8 >> 1][(nf8 & 1) * 2 + 1];
                    mma16816(o[mf][nf8], aph[mf], b0h, b1h);
                    mma16816(o[mf][nf8], aph[mf], b0l, b1l);
                    mma16816(o[mf][nf8], apl[mf], b0h, b1h);
                }
        }
    }
    __syncthreads();

    // ---- write O (split bf16) ----
    float inv[4];
    #pragma unroll
    for (int s = 0; s < 4; s++) {
        int lr = wm * 32 + (s >> 1) * 16 + r4 + (s & 1) * 8;
        inv[s] = 1.f / sL[lr];
    }
    #pragma unroll
    for (int mf = 0; mf < 2; mf++) {
        int row0 = q0 + wm * 32 + mf * 16 + r4;
        #pragma unroll
        for (int nf8 = 0; nf8 < 8; nf8++) {
            int col = h * HD + wn * 64 + nf8 * 8 + c2;
            uint32_t hi, lo;
            split2(o[mf][nf8][0] * inv[mf*2], o[mf][nf8][1] * inv[mf*2], hi, lo);
            *(uint32_t*)(Oh + (size_t)row0 * 2048 + col) = hi;
            *(uint32_t*)(Ol + (size_t)row0 * 2048 + col) = lo;
            split2(o[mf][nf8][2] * inv[mf*2+1], o[mf][nf8][3] * inv[mf*2+1], hi, lo);
            *(uint32_t*)(Oh + (size_t)(row0 + 8) * 2048 + col) = hi;
            *(uint32_t*)(Ol + (size_t)(row0 + 8) * 2048 + col) = lo;
        }
    }
}

// ------------------------- router / topk / scan / fill ---------------------
__global__ __launch_bounds__(256) void router_k(const float* __restrict__ X,
                                                const float* __restrict__ Wr)
{
    __shared__ float part[8][32];
    int t = blockIdx.x;
    int e = threadIdx.x & 31, p = threadIdx.x >> 5;
    const float* xr = X + (size_t)t * HID;
    float s = 0.f;
    for (int k = p * 128; k < p * 128 + 128; k++) s = fmaf(xr[k], Wr[k * 32 + e], s);
    part[p][e] = s;
    __syncthreads();
    if (threadIdx.x < 32) {
        float logit = 0.f;
        #pragma unroll
        for (int q = 0; q < 8; q++) logit += part[q][e];
        float m = logit;
        for (int d = 16; d; d >>= 1) m = fmaxf(m, __shfl_xor_sync(0xffffffffu, m, d));
        float ex = __expf(logit - m);
        float cur = ex;
        float wsel[3]; int isel[3];
        #pragma unroll
        for (int kk = 0; kk < 3; kk++) {
            float v = cur; int idx = e;
            for (int d = 16; d; d >>= 1) {
                float v2 = __shfl_xor_sync(0xffffffffu, v, d);
                int   i2 = __shfl_xor_sync(0xffffffffu, idx, d);
                if (v2 > v || (v2 == v && i2 < idx)) { v = v2; idx = i2; }
            }
            wsel[kk] = v; isel[kk] = idx;
            if (e == idx) cur = -1.f;
        }
        float tot = wsel[0] + wsel[1] + wsel[2];
        if (e < 3) { g_topi[t * 3 + e] = isel[e]; g_topw[t * 3 + e] = wsel[e] / tot; }
        if (e == 0) {
            atomicAdd(&g_cnt[isel[0]], 1);
            atomicAdd(&g_cnt[isel[1]], 1);
            atomicAdd(&g_cnt[isel[2]], 1);
        }
    }
}

__global__ void scan_k()
{
    int e = threadIdx.x;
    int c = g_cnt[e];
    int x = c;
    for (int d = 1; d < 32; d <<= 1) {
        int y = __shfl_up_sync(0xffffffffu, x, d);
        if (e >= d) x += y;
    }
    int excl = x - c;
    g_off[e] = excl;
    g_fill[e] = excl;
}

__global__ void fill_k()
{
    int t = blockIdx.x * 256 + threadIdx.x;
    if (t < SEQ) {
        #pragma unroll
        for (int k = 0; k < 3; k++) {
            int e = g_topi[t * 3 + k];
            int slot = atomicAdd(&g_fill[e], 1);
            g_ptok[slot] = t;
            g_pw[slot] = g_topw[t * 3 + k];
        }
    }
}

// ------------------------- launch ------------------------------------------
extern "C" void kernel_launch(void* const* d_in, const int* in_sizes, int n_in,
                              void* d_out, int out_size)
{
    const float* hidden   = (const float*)d_in[0];
    const float* w_in     = (const float*)d_in[1];
    const float* w_qkv    = (const float*)d_in[2];
    const float* w_inter  = (const float*)d_in[3];
    const float* w_q      = (const float*)d_in[4];
    const float* w_o      = (const float*)d_in[5];
    const float* w_post   = (const float*)d_in[6];
    const float* w_guse   = (const float*)d_in[7];
    const float* w_dse    = (const float*)d_in[8];
    const float* w_router = (const float*)d_in[9];
    const float* w_gue    = (const float*)d_in[10];
    const float* w_de     = (const float*)d_in[11];
    const int*   pos      = (const int*)d_in[12];
    float* out = (float*)d_out;

    float *qkv, *qproj, *resid2, *h2;
    cudaGetSymbolAddress((void**)&qkv,    g_qkv);
    cudaGetSymbolAddress((void**)&qproj,  g_qproj);
    cudaGetSymbolAddress((void**)&resid2, g_resid2);
    cudaGetSymbolAddress((void**)&h2,     g_h2);
    __nv_bfloat16 *hnh,*hnl,*qnh,*qnl,*qh,*ql,*aoh,*aol,*h2h,*h2l,*aseh,*asel,*aceh,*acel;
    cudaGetSymbolAddress((void**)&hnh, g_hnh);   cudaGetSymbolAddress((void**)&hnl, g_hnl);
    cudaGetSymbolAddress((void**)&qnh, g_qnh);   cudaGetSymbolAddress((void**)&qnl, g_qnl);
    cudaGetSymbolAddress((void**)&qh,  g_qh);    cudaGetSymbolAddress((void**)&ql,  g_ql);
    cudaGetSymbolAddress((void**)&aoh, g_aoh);   cudaGetSymbolAddress((void**)&aol, g_aol);
    cudaGetSymbolAddress((void**)&h2h, g_h2h);   cudaGetSymbolAddress((void**)&h2l, g_h2l);
    cudaGetSymbolAddress((void**)&aseh,g_aseh);  cudaGetSymbolAddress((void**)&asel,g_asel);
    cudaGetSymbolAddress((void**)&aceh,g_aceh);  cudaGetSymbolAddress((void**)&acel,g_acel);

    cudaFuncSetAttribute(attn_k, cudaFuncAttributeMaxDynamicSharedMemorySize, ATTN_SMEM);
    cudaFuncSetAttribute(gemm_tc<0>, cudaFuncAttributeMaxDynamicSharedMemorySize, SMEM_TOTAL_G);
    cudaFuncSetAttribute(gemm_tc<1>, cudaFuncAttributeMaxDynamicSharedMemorySize, SMEM_TOTAL_G);
    cudaFuncSetAttribute(gemm_tc<2>, cudaFuncAttributeMaxDynamicSharedMemorySize, SMEM_TOTAL_G);
    cudaFuncSetAttribute(gemm_tc<3>, cudaFuncAttributeMaxDynamicSharedMemorySize, SMEM_TOTAL_G);

    zero_counts_k<<<1, 32>>>();
    cs_prep_k<<<SEQ, 64>>>(pos);
    rmsnorm_k<<<SEQ, 256>>>(hidden, w_in, nullptr, hnh, hnl, HID, HID, HID);
    gemm_tc<0><<<dim3(QKV_N/128, SEQ/128), 128, SMEM_TOTAL_G>>>(
        hnh, hnl, w_qkv, qkv, nullptr, nullptr, nullptr, HID, HID, QKV_N, QKV_N, 0, 0);
    rmsnorm_k<<<SEQ, 256>>>(qkv, w_inter, nullptr, qnh, qnl, QDIM, QKV_N, QDIM);
    gemm_tc<0><<<dim3(2048/128, SEQ/128), 128, SMEM_TOTAL_G>>>(
        qnh, qnl, w_q, qproj, nullptr, nullptr, nullptr, QDIM, QDIM, 2048, 2048, 0, 0);
    rope_q_k<<<SEQ, 256>>>(qproj, qh, ql);
    kv_prep_k<<<SEQ, 128>>>(qkv);
    attn_k<<<256, 256, ATTN_SMEM>>>(qh, ql, aoh, aol);
    gemm_tc<0><<<dim3(HID/128, SEQ/128), 128, SMEM_TOTAL_G>>>(
        aoh, aol, w_o, resid2, nullptr, nullptr, hidden, 2048, 2048, HID, HID, 0, 0);
    rmsnorm_k<<<SEQ, 256>>>(resid2, w_post, h2, h2h, h2l, HID, HID, HID);
    gemm_tc<1><<<dim3(IDIM/64, SEQ/128), 128, SMEM_TOTAL_G>>>(
        h2h, h2l, w_guse, nullptr, aseh, asel, nullptr, HID, HID, 2*IDIM, IDIM, IDIM, 0);
    gemm_tc<0><<<dim3(HID/128, SEQ/128), 128, SMEM_TOTAL_G>>>(
        aseh, asel, w_dse, out, nullptr, nullptr, resid2, IDIM, IDIM, HID, HID, 0, 0);
    router_k<<<SEQ, 256>>>(h2, w_router);
    scan_k<<<1, 32>>>();
    fill_k<<<SEQ/256, 256>>>();
    gemm_tc<2><<<dim3(IDIM/64, 16, NEXP), 128, SMEM_TOTAL_G>>>(
        h2h, h2l, w_gue, nullptr, aceh, acel, nullptr, HID, HID, 2*IDIM, IDIM, IDIM,
        (size_t)HID * 2 * IDIM);
    gemm_tc<3><<<dim3(HID/128, 16, NEXP), 128, SMEM_TOTAL_G>>>(
        aceh, acel, w_de, out, nullptr, nullptr, nullptr, IDIM, IDIM, HID, HID, 0,
        (size_t)IDIM * HID);
}

// round 7
// speedup vs baseline: 4.4609x; 1.0639x over previous
#include <cuda_runtime.h>
#include <cuda_bf16.h>
#include <math.h>
#include <stdint.h>

#define SEQ 2048
#define HID 1024
#define NHEAD 16
#define HD 128
#define QDIM 512
#define NEXP 32
#define IDIM 1024
#define QKV_N 768
#define SCALE 0.08838834764831845f   // 1/sqrt(128)

// ------------------------- device scratch ----------------------------------
__device__ float g_qkv[SEQ*QKV_N];
__device__ float g_qproj[SEQ*NHEAD*HD];
__device__ float g_resid2[SEQ*HID];
__device__ float g_h2[SEQ*HID];
__device__ float2 g_cs[SEQ*64];

__device__ __nv_bfloat16 g_hnh[SEQ*HID],  g_hnl[SEQ*HID];
__device__ __nv_bfloat16 g_qnh[SEQ*QDIM], g_qnl[SEQ*QDIM];
__device__ __nv_bfloat16 g_qh[SEQ*2048],  g_ql[SEQ*2048];
__device__ __nv_bfloat16 g_kth[128*SEQ],  g_ktl[128*SEQ];   // transposed [d][token]
__device__ __nv_bfloat16 g_vh[SEQ*128],   g_vl[SEQ*128];
__device__ __nv_bfloat16 g_aoh[SEQ*2048], g_aol[SEQ*2048];
__device__ __nv_bfloat16 g_h2h[SEQ*HID],  g_h2l[SEQ*HID];
__device__ __nv_bfloat16 g_aseh[SEQ*IDIM],g_asel[SEQ*IDIM];
__device__ __nv_bfloat16 g_aceh[SEQ*3*IDIM], g_acel[SEQ*3*IDIM];

__device__ int   g_topi[SEQ*3];
__device__ float g_topw[SEQ*3];
__device__ int   g_cnt[NEXP];
__device__ int   g_off[NEXP];
__device__ int   g_fill[NEXP];
__device__ int   g_ptok[SEQ*3];
__device__ float g_pw[SEQ*3];

// ------------------------- helpers -----------------------------------------
__device__ __forceinline__ uint32_t s2u(const void* p) {
    uint32_t a;
    asm("{ .reg .u64 t; cvta.to.shared.u64 t, %1; cvt.u32.u64 %0, t; }" : "=r"(a) : "l"(p));
    return a;
}
__device__ __forceinline__ void ldsm4(uint32_t* r, uint32_t addr) {
    asm volatile("ldmatrix.sync.aligned.m8n8.x4.shared.b16 {%0,%1,%2,%3}, [%4];"
        : "=r"(r[0]), "=r"(r[1]), "=r"(r[2]), "=r"(r[3]) : "r"(addr));
}
__device__ __forceinline__ void ldsm4t(uint32_t* r, uint32_t addr) {
    asm volatile("ldmatrix.sync.aligned.m8n8.x4.trans.shared.b16 {%0,%1,%2,%3}, [%4];"
        : "=r"(r[0]), "=r"(r[1]), "=r"(r[2]), "=r"(r[3]) : "r"(addr));
}
__device__ __forceinline__ void mma16816(float* c, const uint32_t* a, uint32_t b0, uint32_t b1) {
    asm volatile("mma.sync.aligned.m16n8k16.row.col.f32.bf16.bf16.f32 "
        "{%0,%1,%2,%3}, {%4,%5,%6,%7}, {%8,%9}, {%0,%1,%2,%3};"
        : "+f"(c[0]), "+f"(c[1]), "+f"(c[2]), "+f"(c[3])
        : "r"(a[0]), "r"(a[1]), "r"(a[2]), "r"(a[3]), "r"(b0), "r"(b1));
}
__device__ __forceinline__ void cpa16(uint32_t dst, const void* src) {
    asm volatile("cp.async.cg.shared.global [%0], [%1], 16;" :: "r"(dst), "l"(src));
}
#define CPA_COMMIT() asm volatile("cp.async.commit_group;" ::: "memory")
#define CPA_WAIT()   asm volatile("cp.async.wait_group 0;" ::: "memory")

__device__ __forceinline__ uint32_t pack_hi(float f0, float f1) {
    __nv_bfloat162 h = __floats2bfloat162_rn(f0, f1);
    return *(uint32_t*)&h;
}
__device__ __forceinline__ uint32_t pack_lo(float f0, float f1, uint32_t hibits) {
    __nv_bfloat162 h = *(__nv_bfloat162*)&hibits;
    __nv_bfloat162 l = __floats2bfloat162_rn(f0 - __bfloat162float(h.x),
                                             f1 - __bfloat162float(h.y));
    return *(uint32_t*)&l;
}
__device__ __forceinline__ void split2(float a, float b, uint32_t& hi, uint32_t& lo) {
    hi = pack_hi(a, b);
    lo = pack_lo(a, b, hi);
}
// FFMA-only exp (rel err ~4e-5), avoids MUFU
__device__ __forceinline__ float fexp(float x) {
    x = fminf(fmaxf(x, -80.f), 80.f);
    float y = x * 1.4426950408889634f;
    float n = rintf(y);
    float f = y - n;
    float p = fmaf(f, 0.009618130f, 0.055504110f);
    p = fmaf(p, f, 0.240226507f);
    p = fmaf(p, f, 0.693147181f);
    p = fmaf(p, f, 1.0f);
    return p * __int_as_float(((int)n + 127) << 23);
}

// ------------------------- GEMM (pipelined, double-buffered, 2 CTA/SM) ------
#define LDA 40
#define LDB 136
#define ASZ (128*LDA*2)          // 10240 bytes per A array
#define BSZ (32*LDB*2)           // 8704 bytes per B array
#define OFF_AH(b) ((b) * (2*ASZ))
#define OFF_AL(b) ((b) * (2*ASZ) + ASZ)
#define OFF_BH(b) (4*ASZ + (b) * (2*BSZ))
#define OFF_BL(b) (4*ASZ + (b) * (2*BSZ) + BSZ)
#define OFF_TOK   (4*ASZ + 4*BSZ)
#define SMEM_TOTAL_G (OFF_TOK + 128*4)

// MODE 0: plain  C = A@B (+add) fp32       (128 out cols / CTA)
// MODE 1: gated  Ch/Cl = split(silu(A@Bg)*(A@Bu))  (64 cols/CTA, up at +upOff)
// MODE 2: moe gathered gated -> split rows off+r
// MODE 3: moe scatter: C[tok] += w * (A@B)  fp32 atomic
template<int MODE>
__global__ __launch_bounds__(256, 2) void gemm_tc(
    const __nv_bfloat16* __restrict__ Ah, const __nv_bfloat16* __restrict__ Al,
    const float* __restrict__ B,
    float* __restrict__ C, __nv_bfloat16* __restrict__ Ch, __nv_bfloat16* __restrict__ Cl,
    const float* __restrict__ add,
    int K, int lda, int ldb, int ldc, int upOff, size_t bStride)
{
    int cnt = 0, off = 0;
    if (MODE >= 2) {
        int e = blockIdx.z;
        cnt = g_cnt[e];
        if ((int)blockIdx.y * 128 >= cnt) return;
        off = g_off[e];
        B += bStride * e;
    }
    const int m0 = blockIdx.y * 128;
    const int nb = blockIdx.x * ((MODE == 1 || MODE == 2) ? 64 : 128);

    extern __shared__ __align__(16) char sm[];
    int* sTok = (int*)(sm + OFF_TOK);
    const uint32_t sb = s2u(sm);

    const int tid = threadIdx.x;
    const int wid = tid >> 5, lane = tid & 31;
    const int wm = wid >> 2, wn = wid & 3;

    if (MODE == 2 && tid < 128) {
        int gr = m0 + tid;
        sTok[tid] = (gr < cnt) ? g_ptok[off + gr] : 0;
    }
    __syncthreads();

    float acc[4][4][4] = {};
    const int lrow = lane & 15, lcol8 = (lane >> 4) * 8;

    // per-thread A cp.async indices: 2 segments (idx, idx+256)
    const int am0 = tid >> 2, aseg0 = (tid & 3);
    const int am1 = (tid + 256) >> 2, aseg1 = ((tid + 256) & 3);

    // A row base pointers (element offsets)
    size_t arow0, arow1;
    {
        int mA0 = am0, mA1 = am1;
        if (MODE == 2) {
            arow0 = (size_t)sTok[mA0] * lda;
            arow1 = (size_t)sTok[mA1] * lda;
        } else if (MODE == 3) {
            int r0 = (m0 + mA0 < cnt) ? m0 + mA0 : 0;
            int r1 = (m0 + mA1 < cnt) ? m0 + mA1 : 0;
            arow0 = (size_t)(off + r0) * lda;
            arow1 = (size_t)(off + r1) * lda;
        } else {
            arow0 = (size_t)(m0 + am0) * lda;
            arow1 = (size_t)(m0 + am1) * lda;
        }
    }
    const uint32_t adst0 = sb + am0 * (LDA*2) + aseg0 * 16;
    const uint32_t adst1 = sb + am1 * (LDA*2) + aseg1 * 16;

    // B load indexing (4 float4 per thread)
    int bcol[4]; size_t brow[4];
    #pragma unroll
    for (int it = 0; it < 4; it++) {
        int i = tid + it * 256;
        int kk = i >> 5;
        int n4 = (i & 31) << 2;
        int col;
        if (MODE == 1 || MODE == 2) col = (n4 < 64) ? nb + n4 : upOff + nb + (n4 - 64);
        else                        col = nb + n4;
        bcol[it] = n4;
        brow[it] = (size_t)kk * ldb + col;
    }

    const int nkt = K >> 5;
    float4 br[4];

    // ---- prologue: chunk 0 ----
    {
        cpa16(adst0 + OFF_AH(0), Ah + arow0 + aseg0 * 8);
        cpa16(adst0 + OFF_AL(0), Al + arow0 + aseg0 * 8);
        cpa16(adst1 + OFF_AH(0), Ah + arow1 + aseg1 * 8);
        cpa16(adst1 + OFF_AL(0), Al + arow1 + aseg1 * 8);
        CPA_COMMIT();
        #pragma unroll
        for (int it = 0; it < 4; it++) br[it] = *(const float4*)(B + brow[it]);
        CPA_WAIT();
        __syncthreads();
        #pragma unroll
        for (int it = 0; it < 4; it++) {
            int i = tid + it * 256;
            int kk = i >> 5;
            uint32_t h0 = pack_hi(br[it].x, br[it].y), h1 = pack_hi(br[it].z, br[it].w);
            uint32_t l0 = pack_lo(br[it].x, br[it].y, h0), l1 = pack_lo(br[it].z, br[it].w, h1);
            uint32_t* ph = (uint32_t*)(sm + OFF_BH(0) + kk * (LDB*2) + bcol[it] * 2);
            uint32_t* pl = (uint32_t*)(sm + OFF_BL(0) + kk * (LDB*2) + bcol[it] * 2);
            ph[0] = h0; ph[1] = h1;
            pl[0] = l0; pl[1] = l1;
        }
        __syncthreads();
    }

    int p = 0;
    for (int c = 0; c < nkt; c++) {
        const int q = p ^ 1;
        const bool more = (c + 1 < nkt);
        if (more) {
            const int k1 = (c + 1) << 5;
            cpa16(adst0 + OFF_AH(q), Ah + arow0 + k1 + aseg0 * 8);
            cpa16(adst0 + OFF_AL(q), Al + arow0 + k1 + aseg0 * 8);
            cpa16(adst1 + OFF_AH(q), Ah + arow1 + k1 + aseg1 * 8);
            cpa16(adst1 + OFF_AL(q), Al + arow1 + k1 + aseg1 * 8);
            CPA_COMMIT();
            #pragma unroll
            for (int it = 0; it < 4; it++)
                br[it] = *(const float4*)(B + (size_t)k1 * ldb + brow[it]);
        }

        // ---- MMA on buffer p ----
        const uint32_t uAh = sb + OFF_AH(p), uAl = sb + OFF_AL(p);
        const uint32_t uBh = sb + OFF_BH(p), uBl = sb + OFF_BL(p);
        #pragma unroll
        for (int ks = 0; ks < 2; ks++) {
            uint32_t ah[4][4], al[4][4], bh[2][4], bl[2][4];
            #pragma unroll
            for (int mf = 0; mf < 4; mf++) {
                uint32_t ro = (uint32_t)((wm * 64 + mf * 16 + lrow) * LDA + ks * 16 + lcol8) * 2;
                ldsm4(ah[mf], uAh + ro);
                ldsm4(al[mf], uAl + ro);
            }
            #pragma unroll
            for (int nh = 0; nh < 2; nh++) {
                uint32_t ro = (uint32_t)((ks * 16 + lrow) * LDB + wn * 32 + nh * 16 + lcol8) * 2;
                ldsm4t(bh[nh], uBh + ro);
                ldsm4t(bl[nh], uBl + ro);
            }
            #pragma unroll
            for (int mf = 0; mf < 4; mf++)
                #pragma unroll
                for (int nf = 0; nf < 4; nf++) {
                    uint32_t bh0 = bh[nf >> 1][(nf & 1) * 2], bh1 = bh[nf >> 1][(nf & 1) * 2 + 1];
                    uint32_t bl0 = bl[nf >> 1][(nf & 1) * 2], bl1 = bl[nf >> 1][(nf & 1) * 2 + 1];
                    mma16816(acc[mf][nf], ah[mf], bh0, bh1);
                    mma16816(acc[mf][nf], ah[mf], bl0, bl1);
                    mma16816(acc[mf][nf], al[mf], bh0, bh1);
                }
        }

        if (more) {
            #pragma unroll
            for (int it = 0; it < 4; it++) {
                int i = tid + it * 256;
                int kk = i >> 5;
                uint32_t h0 = pack_hi(br[it].x, br[it].y), h1 = pack_hi(br[it].z, br[it].w);
                uint32_t l0 = pack_lo(br[it].x, br[it].y, h0), l1 = pack_lo(br[it].z, br[it].w, h1);
                uint32_t* ph = (uint32_t*)(sm + OFF_BH(q) + kk * (LDB*2) + bcol[it] * 2);
                uint32_t* pl = (uint32_t*)(sm + OFF_BL(q) + kk * (LDB*2) + bcol[it] * 2);
                ph[0] = h0; ph[1] = h1;
                pl[0] = l0; pl[1] = l1;
            }
            CPA_WAIT();
            __syncthreads();
        }
        p = q;
    }
    __syncthreads();

    // ---- epilogue ----
    const int r4 = lane >> 2, c2 = (lane & 3) * 2;
    if (MODE == 0) {
        #pragma unroll
        for (int mf = 0; mf < 4; mf++) {
            #pragma unroll
            for (int nf = 0; nf < 4; nf++) {
                int col = nb + wn * 32 + nf * 8 + c2;
                size_t r1 = (size_t)(m0 + wm * 64 + mf * 16 + r4);
                size_t r2 = r1 + 8;
                float v0 = acc[mf][nf][0], v1 = acc[mf][nf][1];
                float v2 = acc[mf][nf][2], v3 = acc[mf][nf][3];
                if (add) {
                    v0 += add[r1 * ldc + col]; v1 += add[r1 * ldc + col + 1];
                    v2 += add[r2 * ldc + col]; v3 += add[r2 * ldc + col + 1];
                }
                *(float2*)(C + r1 * ldc + col) = make_float2(v0, v1);
                *(float2*)(C + r2 * ldc + col) = make_float2(v2, v3);
            }
        }
    } else if (MODE == 1 || MODE == 2) {
        float* sG = (float*)sm;              // [128][65]
        if (wn < 2) {
            #pragma unroll
            for (int mf = 0; mf < 4; mf++)
                #pragma unroll
                for (int nf = 0; nf < 4; nf++) {
                    int col = wn * 32 + nf * 8 + c2;
                    int rr1 = wm * 64 + mf * 16 + r4, rr2 = rr1 + 8;
                    sG[rr1 * 65 + col]     = acc[mf][nf][0];
                    sG[rr1 * 65 + col + 1] = acc[mf][nf][1];
                    sG[rr2 * 65 + col]     = acc[mf][nf][2];
                    sG[rr2 * 65 + col + 1] = acc[mf][nf][3];
                }
        }
        __syncthreads();
        if (wn >= 2) {
            #pragma unroll
            for (int mf = 0; mf < 4; mf++)
                #pragma unroll
                for (int nf = 0; nf < 4; nf++) {
                    int col = (wn - 2) * 32 + nf * 8 + c2;
                    int rr1 = wm * 64 + mf * 16 + r4;
                    #pragma unroll
                    for (int half = 0; half < 2; half++) {
                        int rr = rr1 + half * 8;
                        bool ok = (MODE == 1) || (m0 + rr < cnt);
                        if (ok) {
                            size_t row = (MODE == 1) ? (size_t)(m0 + rr) : (size_t)(off + m0 + rr);
                            float g0 = sG[rr * 65 + col], g1 = sG[rr * 65 + col + 1];
                            float u0 = acc[mf][nf][half * 2], u1 = acc[mf][nf][half * 2 + 1];
                            float o0 = g0 / (1.f + fexp(-g0)) * u0;
                            float o1 = g1 / (1.f + fexp(-g1)) * u1;
                            uint32_t hi, lo;
                            split2(o0, o1, hi, lo);
                            *(uint32_t*)(Ch + row * ldc + nb + col) = hi;
                            *(uint32_t*)(Cl + row * ldc + nb + col) = lo;
                        }
                    }
                }
        }
    } else {  // MODE 3
        #pragma unroll
        for (int mf = 0; mf < 4; mf++) {
            int rr1 = wm * 64 + mf * 16 + r4;
            #pragma unroll
            for (int half = 0; half < 2; half++) {
                int rr = rr1 + half * 8;
                if (m0 + rr < cnt) {
                    int tok = g_ptok[off + m0 + rr];
                    float w = g_pw[off + m0 + rr];
                    float* dst = C + (size_t)tok * ldc;
                    #pragma unroll
                    for (int nf = 0; nf < 4; nf++) {
                        int col = nb + wn * 32 + nf * 8 + c2;
                        atomicAdd(dst + col,     w * acc[mf][nf][half * 2]);
                        atomicAdd(dst + col + 1, w * acc[mf][nf][half * 2 + 1]);
                    }
                }
            }
        }
    }
}

// ------------------------- small kernels ------------------------------------
__global__ void zero_counts_k() {
    if (threadIdx.x < NEXP) g_cnt[threadIdx.x] = 0;
}

__global__ void cs_prep_k(const int* __restrict__ pos) {
    int t = blockIdx.x, i = threadIdx.x;   // 64 threads
    double e = exp(-((double)(2 * i) / 128.0) * log(500000.0));
    float f = (float)pos[t] * (float)e;
    float sn, cs; sincosf(f, &sn, &cs);
    g_cs[t * 64 + i] = make_float2(cs, sn);
}

// rmsnorm: writes optional fp32 y + optional bf16 split yh/yl
__global__ void rmsnorm_k(const float* __restrict__ x, const float* __restrict__ w,
                          float* __restrict__ y,
                          __nv_bfloat16* __restrict__ yh, __nv_bfloat16* __restrict__ yl,
                          int cols, int ldx, int ldy)
{
    int row = blockIdx.x;
    const float* xr = x + (size_t)row * ldx;
    float ss = 0.f;
    for (int c = threadIdx.x; c < cols; c += 256) { float v = xr[c]; ss = fmaf(v, v, ss); }
    __shared__ float wred[8];
    #pragma unroll
    for (int d = 16; d; d >>= 1) ss += __shfl_xor_sync(0xffffffffu, ss, d);
    if ((threadIdx.x & 31) == 0) wred[threadIdx.x >> 5] = ss;
    __syncthreads();
    if (threadIdx.x < 32) {
        float v = (threadIdx.x < 8) ? wred[threadIdx.x] : 0.f;
        #pragma unroll
        for (int d = 4; d; d >>= 1) v += __shfl_xor_sync(0xffffffffu, v, d);
        if (threadIdx.x == 0) wred[0] = v;
    }
    __syncthreads();
    float r = rsqrtf(wred[0] / (float)cols + 1e-5f);
    for (int c = threadIdx.x; c < cols; c += 256) {
        float v = xr[c] * r * w[c];
        if (y) y[(size_t)row * ldy + c] = v;
        if (yh) {
            __nv_bfloat16 h = __float2bfloat16_rn(v);
            yh[(size_t)row * ldy + c] = h;
            yl[(size_t)row * ldy + c] = __float2bfloat16_rn(v - __bfloat162float(h));
        }
    }
}

// rope on q (reads qproj fp32, writes split bf16 with SCALE folded)
__global__ void rope_q_k(const float* __restrict__ qp,
                         __nv_bfloat16* __restrict__ qh, __nv_bfloat16* __restrict__ ql)
{
    int t = blockIdx.x;
    for (int idx = threadIdx.x; idx < NHEAD * 64; idx += 256) {
        int hh = idx >> 6, i = idx & 63;
        float2 cs = g_cs[t * 64 + i];
        const float* b = qp + (size_t)t * 2048 + hh * HD;
        float x1 = b[i], x2 = b[i + 64];
        float y1 = (x1 * cs.x - x2 * cs.y) * SCALE;
        float y2 = (x2 * cs.x + x1 * cs.y) * SCALE;
        size_t o1 = (size_t)t * 2048 + hh * HD + i;
        __nv_bfloat16 h1 = __float2bfloat16_rn(y1);
        qh[o1] = h1; ql[o1] = __float2bfloat16_rn(y1 - __bfloat162float(h1));
        __nv_bfloat16 h2 = __float2bfloat16_rn(y2);
        qh[o1 + 64] = h2; ql[o1 + 64] = __float2bfloat16_rn(y2 - __bfloat162float(h2));
    }
}

// K rope + transpose split; V split
__global__ void kv_prep_k(const float* __restrict__ qkv)
{
    int t = blockIdx.x;
    int tid = threadIdx.x;   // 128
    if (tid < 64) {
        int i = tid;
        float2 cs = g_cs[t * 64 + i];
        const float* kb = qkv + (size_t)t * QKV_N + QDIM;
        float x1 = kb[i], x2 = kb[i + 64];
        float y1 = x1 * cs.x - x2 * cs.y;
        float y2 = x2 * cs.x + x1 * cs.y;
        __nv_bfloat16 h1 = __float2bfloat16_rn(y1);
        g_kth[(size_t)i * SEQ + t] = h1;
        g_ktl[(size_t)i * SEQ + t] = __float2bfloat16_rn(y1 - __bfloat162float(h1));
        __nv_bfloat16 h2 = __float2bfloat16_rn(y2);
        g_kth[(size_t)(i + 64) * SEQ + t] = h2;
        g_ktl[(size_t)(i + 64) * SEQ + t] = __float2bfloat16_rn(y2 - __bfloat162float(h2));
    }
    {
        float v = qkv[(size_t)t * QKV_N + QDIM + HD + tid];
        __nv_bfloat16 h = __float2bfloat16_rn(v);
        g_vh[(size_t)t * HD + tid] = h;
        g_vl[(size_t)t * HD + tid] = __float2bfloat16_rn(v - __bfloat162float(h));
    }
}

// ------------------------- attention: bf16 HMMA flash ----------------------
#define AQ_LD 136
#define AK_LD 72
#define AV_LD 136
#define AP_LD 72
#define AOF_QH 0
#define AOF_QL 34816
#define AOF_KH 69632
#define AOF_KL 88064
#define AOF_VH 106496
#define AOF_VL 123904
#define AOF_PH 141312
#define AOF_PL 159744
#define AOF_M  178176
#define AOF_L  178688
#define AOF_RMAX 179200
#define AOF_RSUM 180224
#define ATTN_SMEM 181248

__global__ __launch_bounds__(256, 1) void attn_k(
    const __nv_bfloat16* __restrict__ Qh, const __nv_bfloat16* __restrict__ Ql,
    __nv_bfloat16* __restrict__ Oh, __nv_bfloat16* __restrict__ Ol)
{
    extern __shared__ __align__(16) char sm[];
    const int bx = blockIdx.x;
    const int qt = 15 - (bx >> 4);     // longest tiles first
    const int h = bx & 15;
    const int q0 = qt * 128;

    const int tid = threadIdx.x;
    const int wid = tid >> 5, lane = tid & 31;
    const int wm = wid >> 1, wn = wid & 1;
    const int lrow = lane & 15, lcol8 = (lane >> 4) * 8;
    const int r4 = lane >> 2, c2 = (lane & 3) * 2;

    float* sM = (float*)(sm + AOF_M);
    float* sL = (float*)(sm + AOF_L);
    float* sRmax = (float*)(sm + AOF_RMAX);   // [2][128]
    float* sRsum = (float*)(sm + AOF_RSUM);   // [2][128]
    const uint32_t uQh = s2u(sm + AOF_QH), uQl = s2u(sm + AOF_QL);
    const uint32_t uKh = s2u(sm + AOF_KH), uKl = s2u(sm + AOF_KL);
    const uint32_t uVh = s2u(sm + AOF_VH), uVl = s2u(sm + AOF_VL);
    const uint32_t uPh = s2u(sm + AOF_PH), uPl = s2u(sm + AOF_PL);

    // load Q tile (128 x 128, hi+lo)
    #pragma unroll
    for (int it = 0; it < 8; it++) {
        int i = tid + it * 256;          // 2048 uint4 per copy
        int r = i >> 4, c = (i & 15) << 3;
        size_t src = (size_t)(q0 + r) * 2048 + h * HD + c;
        *(uint4*)(sm + AOF_QH + r * (AQ_LD*2) + c * 2) = *(const uint4*)(Qh + src);
        *(uint4*)(sm + AOF_QL + r * (AQ_LD*2) + c * 2) = *(const uint4*)(Ql + src);
    }
    if (tid < 128) { sM[tid] = -3.0e30f; sL[tid] = 0.f; }

    float o[2][8][4] = {};
    const int nkt = 2 * qt + 2;

    for (int kt = 0; kt < nkt; kt++) {
        const int k0 = kt * 64;
        __syncthreads();
        // load K tile (transposed source [d][tok]): 128 x 64
        #pragma unroll
        for (int it = 0; it < 4; it++) {
            int i = tid + it * 256;      // 1024 uint4 per copy
            int d = i >> 3, tc = (i & 7) << 3;
            size_t src = (size_t)d * SEQ + k0 + tc;
            *(uint4*)(sm + AOF_KH + d * (AK_LD*2) + tc * 2) = *(const uint4*)(g_kth + src);
            *(uint4*)(sm + AOF_KL + d * (AK_LD*2) + tc * 2) = *(const uint4*)(g_ktl + src);
        }
        // load V tile: 64 x 128
        #pragma unroll
        for (int it = 0; it < 4; it++) {
            int i = tid + it * 256;
            int r = i >> 4, c = (i & 15) << 3;
            size_t src = (size_t)(k0 + r) * HD + c;
            *(uint4*)(sm + AOF_VH + r * (AV_LD*2) + c * 2) = *(const uint4*)(g_vh + src);
            *(uint4*)(sm + AOF_VL + r * (AV_LD*2) + c * 2) = *(const uint4*)(g_vl + src);
        }
        __syncthreads();

        // ---- S = Q K^T (3-pass split) ----
        float sacc[2][4][4] = {};
        #pragma unroll
        for (int ks = 0; ks < 8; ks++) {
            uint32_t ah[2][4], al[2][4], bh[2][4], bl[2][4];
            #pragma unroll
            for (int mf = 0; mf < 2; mf++) {
                uint32_t ro = (uint32_t)((wm * 32 + mf * 16 + lrow) * AQ_LD + ks * 16 + lcol8) * 2;
                ldsm4(ah[mf], uQh + ro);
                ldsm4(al[mf], uQl + ro);
            }
            #pragma unroll
            for (int nh = 0; nh < 2; nh++) {
                uint32_t ro = (uint32_t)((ks * 16 + lrow) * AK_LD + wn * 32 + nh * 16 + lcol8) * 2;
                ldsm4t(bh[nh], uKh + ro);
                ldsm4t(bl[nh], uKl + ro);
            }
            #pragma unroll
            for (int mf = 0; mf < 2; mf++)
                #pragma unroll
                for (int nf = 0; nf < 4; nf++) {
                    uint32_t b0h = bh[nf >> 1][(nf & 1) * 2], b1h = bh[nf >> 1][(nf & 1) * 2 + 1];
                    uint32_t b0l = bl[nf >> 1][(nf & 1) * 2], b1l = bl[nf >> 1][(nf & 1) * 2 + 1];
                    mma16816(sacc[mf][nf], ah[mf], b0h, b1h);
                    mma16816(sacc[mf][nf], ah[mf], b0l, b1l);
                    mma16816(sacc[mf][nf], al[mf], b0h, b1h);
                }
        }

        // causal mask on diagonal tiles
        if (kt >= nkt - 2) {
            #pragma unroll
            for (int mf = 0; mf < 2; mf++)
                #pragma unroll
                for (int nf = 0; nf < 4; nf++)
                    #pragma unroll
                    for (int v = 0; v < 4; v++) {
                        int row = q0 + wm * 32 + mf * 16 + r4 + (v >= 2 ? 8 : 0);
                        int col = k0 + wn * 32 + nf * 8 + c2 + (v & 1);
                        if (col > row) sacc[mf][nf][v] = -1.0e30f;
                    }
        }

        // ---- row max (warp-local then cross-warp) ----
        float rmax[4] = {-3.0e30f, -3.0e30f, -3.0e30f, -3.0e30f};
        #pragma unroll
        for (int mf = 0; mf < 2; mf++)
            #pragma unroll
            for (int nf = 0; nf < 4; nf++) {
                rmax[mf*2]   = fmaxf(rmax[mf*2],   fmaxf(sacc[mf][nf][0], sacc[mf][nf][1]));
                rmax[mf*2+1] = fmaxf(rmax[mf*2+1], fmaxf(sacc[mf][nf][2], sacc[mf][nf][3]));
            }
        #pragma unroll
        for (int s = 0; s < 4; s++) {
            rmax[s] = fmaxf(rmax[s], __shfl_xor_sync(0xffffffffu, rmax[s], 1));
            rmax[s] = fmaxf(rmax[s], __shfl_xor_sync(0xffffffffu, rmax[s], 2));
        }
        if ((lane & 3) == 0) {
            #pragma unroll
            for (int s = 0; s < 4; s++) {
                int lr = wm * 32 + (s >> 1) * 16 + r4 + (s & 1) * 8;
                sRmax[wn * 128 + lr] = rmax[s];
            }
        }
        __syncthreads();

        float mn[4], fct[4];
        #pragma unroll
        for (int s = 0; s < 4; s++) {
            int lr = wm * 32 + (s >> 1) * 16 + r4 + (s & 1) * 8;
            float mo = sM[lr];
            float m2 = fmaxf(sRmax[lr], sRmax[128 + lr]);
            mn[s] = fmaxf(mo, m2);
            fct[s] = fexp(mo - mn[s]);
        }

        // ---- p = exp(s-mn), store split P, partial sums, rescale o ----
        float rsum[4] = {0.f, 0.f, 0.f, 0.f};
        #pragma unroll
        for (int mf = 0; mf < 2; mf++) {
            int lr0 = wm * 32 + mf * 16 + r4;
            #pragma unroll
            for (int nf = 0; nf < 4; nf++) {
                int col = wn * 32 + nf * 8 + c2;
                float p0 = fexp(sacc[mf][nf][0] - mn[mf*2]);
                float p1 = fexp(sacc[mf][nf][1] - mn[mf*2]);
                float p2 = fexp(sacc[mf][nf][2] - mn[mf*2+1]);
                float p3 = fexp(sacc[mf][nf][3] - mn[mf*2+1]);
                rsum[mf*2]   += p0 + p1;
                rsum[mf*2+1] += p2 + p3;
                uint32_t hi, lo;
                split2(p0, p1, hi, lo);
                *(uint32_t*)(sm + AOF_PH + (lr0 * AP_LD + col) * 2) = hi;
                *(uint32_t*)(sm + AOF_PL + (lr0 * AP_LD + col) * 2) = lo;
                split2(p2, p3, hi, lo);
                *(uint32_t*)(sm + AOF_PH + ((lr0 + 8) * AP_LD + col) * 2) = hi;
                *(uint32_t*)(sm + AOF_PL + ((lr0 + 8) * AP_LD + col) * 2) = lo;
            }
        }
        #pragma unroll
        for (int mf = 0; mf < 2; mf++)
            #pragma unroll
            for (int nf8 = 0; nf8 < 8; nf8++) {
                o[mf][nf8][0] *= fct[mf*2];   o[mf][nf8][1] *= fct[mf*2];
                o[mf][nf8][2] *= fct[mf*2+1]; o[mf][nf8][3] *= fct[mf*2+1];
            }
        #pragma unroll
        for (int s = 0; s < 4; s++) {
            rsum[s] += __shfl_xor_sync(0xffffffffu, rsum[s], 1);
            rsum[s] += __shfl_xor_sync(0xffffffffu, rsum[s], 2);
        }
        if ((lane & 3) == 0) {
            #pragma unroll
            for (int s = 0; s < 4; s++) {
                int lr = wm * 32 + (s >> 1) * 16 + r4 + (s & 1) * 8;
                sRsum[wn * 128 + lr] = rsum[s];
            }
        }
        __syncthreads();
        if (wn == 0 && (lane & 3) == 0) {
            #pragma unroll
            for (int s = 0; s < 4; s++) {
                int lr = wm * 32 + (s >> 1) * 16 + r4 + (s & 1) * 8;
                sL[lr] = sL[lr] * fct[s] + sRsum[lr] + sRsum[128 + lr];
                sM[lr] = mn[s];
            }
        }

        // ---- O += P V (3-pass split) ----
        #pragma unroll
        for (int ks = 0; ks < 4; ks++) {
            uint32_t aph[2][4], apl[2][4], bvh[4][4], bvl[4][4];
            #pragma unroll
            for (int mf = 0; mf < 2; mf++) {
                uint32_t ro = (uint32_t)((wm * 32 + mf * 16 + lrow) * AP_LD + ks * 16 + lcol8) * 2;
                ldsm4(aph[mf], uPh + ro);
                ldsm4(apl[mf], uPl + ro);
            }
            #pragma unroll
            for (int nh = 0; nh < 4; nh++) {
                uint32_t ro = (uint32_t)((ks * 16 + lrow) * AV_LD + wn * 64 + nh * 16 + lcol8) * 2;
                ldsm4t(bvh[nh], uVh + ro);
                ldsm4t(bvl[nh], uVl + ro);
            }
            #pragma unroll
            for (int mf = 0; mf < 2; mf++)
                #pragma unroll
                for (int nf8 = 0; nf8 < 8; nf8++) {
                    uint32_t b0h = bvh[nf8 >> 1][(nf8 & 1) * 2], b1h = bvh[nf8 >> 1][(nf8 & 1) * 2 + 1];
                    uint32_t b0l = bvl[nf8 >> 1][(nf8 & 1) * 2], b1l = bvl[nf8 >> 1][(nf8 & 1) * 2 + 1];
                    mma16816(o[mf][nf8], aph[mf], b0h, b1h);
                    mma16816(o[mf][nf8], aph[mf], b0l, b1l);
                    mma16816(o[mf][nf8], apl[mf], b0h, b1h);
                }
        }
    }
    __syncthreads();

    // ---- write O (split bf16) ----
    float inv[4];
    #pragma unroll
    for (int s = 0; s < 4; s++) {
        int lr = wm * 32 + (s >> 1) * 16 + r4 + (s & 1) * 8;
        inv[s] = 1.f / sL[lr];
    }
    #pragma unroll
    for (int mf = 0; mf < 2; mf++) {
        int row0 = q0 + wm * 32 + mf * 16 + r4;
        #pragma unroll
        for (int nf8 = 0; nf8 < 8; nf8++) {
            int col = h * HD + wn * 64 + nf8 * 8 + c2;
            uint32_t hi, lo;
            split2(o[mf][nf8][0] * inv[mf*2], o[mf][nf8][1] * inv[mf*2], hi, lo);
            *(uint32_t*)(Oh + (size_t)row0 * 2048 + col) = hi;
            *(uint32_t*)(Ol + (size_t)row0 * 2048 + col) = lo;
            split2(o[mf][nf8][2] * inv[mf*2+1], o[mf][nf8][3] * inv[mf*2+1], hi, lo);
            *(uint32_t*)(Oh + (size_t)(row0 + 8) * 2048 + col) = hi;
            *(uint32_t*)(Ol + (size_t)(row0 + 8) * 2048 + col) = lo;
        }
    }
}

// ------------------------- router / topk / scan / fill ---------------------
__global__ __launch_bounds__(256) void router_k(const float* __restrict__ X,
                                                const float* __restrict__ Wr)
{
    __shared__ float part[8][32];
    int t = blockIdx.x;
    int e = threadIdx.x & 31, p = threadIdx.x >> 5;
    const float* xr = X + (size_t)t * HID;
    float s = 0.f;
    for (int k = p * 128; k < p * 128 + 128; k++) s = fmaf(xr[k], Wr[k * 32 + e], s);
    part[p][e] = s;
    __syncthreads();
    if (threadIdx.x < 32) {
        float logit = 0.f;
        #pragma unroll
        for (int q = 0; q < 8; q++) logit += part[q][e];
        float m = logit;
        for (int d = 16; d; d >>= 1) m = fmaxf(m, __shfl_xor_sync(0xffffffffu, m, d));
        float ex = __expf(logit - m);
        float cur = ex;
        float wsel[3]; int isel[3];
        #pragma unroll
        for (int kk = 0; kk < 3; kk++) {
            float v = cur; int idx = e;
            for (int d = 16; d; d >>= 1) {
                float v2 = __shfl_xor_sync(0xffffffffu, v, d);
                int   i2 = __shfl_xor_sync(0xffffffffu, idx, d);
                if (v2 > v || (v2 == v && i2 < idx)) { v = v2; idx = i2; }
            }
            wsel[kk] = v; isel[kk] = idx;
            if (e == idx) cur = -1.f;
        }
        float tot = wsel[0] + wsel[1] + wsel[2];
        if (e < 3) { g_topi[t * 3 + e] = isel[e]; g_topw[t * 3 + e] = wsel[e] / tot; }
        if (e == 0) {
            atomicAdd(&g_cnt[isel[0]], 1);
            atomicAdd(&g_cnt[isel[1]], 1);
            atomicAdd(&g_cnt[isel[2]], 1);
        }
    }
}

__global__ void scan_k()
{
    int e = threadIdx.x;
    int c = g_cnt[e];
    int x = c;
    for (int d = 1; d < 32; d <<= 1) {
        int y = __shfl_up_sync(0xffffffffu, x, d);
        if (e >= d) x += y;
    }
    int excl = x - c;
    g_off[e] = excl;
    g_fill[e] = excl;
}

__global__ void fill_k()
{
    int t = blockIdx.x * 256 + threadIdx.x;
    if (t < SEQ) {
        #pragma unroll
        for (int k = 0; k < 3; k++) {
            int e = g_topi[t * 3 + k];
            int slot = atomicAdd(&g_fill[e], 1);
            g_ptok[slot] = t;
            g_pw[slot] = g_topw[t * 3 + k];
        }
    }
}

// ------------------------- launch ------------------------------------------
extern "C" void kernel_launch(void* const* d_in, const int* in_sizes, int n_in,
                              void* d_out, int out_size)
{
    const float* hidden   = (const float*)d_in[0];
    const float* w_in     = (const float*)d_in[1];
    const float* w_qkv    = (const float*)d_in[2];
    const float* w_inter  = (const float*)d_in[3];
    const float* w_q      = (const float*)d_in[4];
    const float* w_o      = (const float*)d_in[5];
    const float* w_post   = (const float*)d_in[6];
    const float* w_guse   = (const float*)d_in[7];
    const float* w_dse    = (const float*)d_in[8];
    const float* w_router = (const float*)d_in[9];
    const float* w_gue    = (const float*)d_in[10];
    const float* w_de     = (const float*)d_in[11];
    const int*   pos      = (const int*)d_in[12];
    float* out = (float*)d_out;

    float *qkv, *qproj, *resid2, *h2;
    cudaGetSymbolAddress((void**)&qkv,    g_qkv);
    cudaGetSymbolAddress((void**)&qproj,  g_qproj);
    cudaGetSymbolAddress((void**)&resid2, g_resid2);
    cudaGetSymbolAddress((void**)&h2,     g_h2);
    __nv_bfloat16 *hnh,*hnl,*qnh,*qnl,*qh,*ql,*aoh,*aol,*h2h,*h2l,*aseh,*asel,*aceh,*acel;
    cudaGetSymbolAddress((void**)&hnh, g_hnh);   cudaGetSymbolAddress((void**)&hnl, g_hnl);
    cudaGetSymbolAddress((void**)&qnh, g_qnh);   cudaGetSymbolAddress((void**)&qnl, g_qnl);
    cudaGetSymbolAddress((void**)&qh,  g_qh);    cudaGetSymbolAddress((void**)&ql,  g_ql);
    cudaGetSymbolAddress((void**)&aoh, g_aoh);   cudaGetSymbolAddress((void**)&aol, g_aol);
    cudaGetSymbolAddress((void**)&h2h, g_h2h);   cudaGetSymbolAddress((void**)&h2l, g_h2l);
    cudaGetSymbolAddress((void**)&aseh,g_aseh);  cudaGetSymbolAddress((void**)&asel,g_asel);
    cudaGetSymbolAddress((void**)&aceh,g_aceh);  cudaGetSymbolAddress((void**)&acel,g_acel);

    cudaFuncSetAttribute(attn_k, cudaFuncAttributeMaxDynamicSharedMemorySize, ATTN_SMEM);
    cudaFuncSetAttribute(gemm_tc<0>, cudaFuncAttributeMaxDynamicSharedMemorySize, SMEM_TOTAL_G);
    cudaFuncSetAttribute(gemm_tc<1>, cudaFuncAttributeMaxDynamicSharedMemorySize, SMEM_TOTAL_G);
    cudaFuncSetAttribute(gemm_tc<2>, cudaFuncAttributeMaxDynamicSharedMemorySize, SMEM_TOTAL_G);
    cudaFuncSetAttribute(gemm_tc<3>, cudaFuncAttributeMaxDynamicSharedMemorySize, SMEM_TOTAL_G);

    zero_counts_k<<<1, 32>>>();
    cs_prep_k<<<SEQ, 64>>>(pos);
    rmsnorm_k<<<SEQ, 256>>>(hidden, w_in, nullptr, hnh, hnl, HID, HID, HID);
    gemm_tc<0><<<dim3(QKV_N/128, SEQ/128), 256, SMEM_TOTAL_G>>>(
        hnh, hnl, w_qkv, qkv, nullptr, nullptr, nullptr, HID, HID, QKV_N, QKV_N, 0, 0);
    rmsnorm_k<<<SEQ, 256>>>(qkv, w_inter, nullptr, qnh, qnl, QDIM, QKV_N, QDIM);
    gemm_tc<0><<<dim3(2048/128, SEQ/128), 256, SMEM_TOTAL_G>>>(
        qnh, qnl, w_q, qproj, nullptr, nullptr, nullptr, QDIM, QDIM, 2048, 2048, 0, 0);
    rope_q_k<<<SEQ, 256>>>(qproj, qh, ql);
    kv_prep_k<<<SEQ, 128>>>(qkv);
    attn_k<<<256, 256, ATTN_SMEM>>>(qh, ql, aoh, aol);
    gemm_tc<0><<<dim3(HID/128, SEQ/128), 256, SMEM_TOTAL_G>>>(
        aoh, aol, w_o, resid2, nullptr, nullptr, hidden, 2048, 2048, HID, HID, 0, 0);
    rmsnorm_k<<<SEQ, 256>>>(resid2, w_post, h2, h2h, h2l, HID, HID, HID);
    gemm_tc<1><<<dim3(IDIM/64, SEQ/128), 256, SMEM_TOTAL_G>>>(
        h2h, h2l, w_guse, nullptr, aseh, asel, nullptr, HID, HID, 2*IDIM, IDIM, IDIM, 0);
    gemm_tc<0><<<dim3(HID/128, SEQ/128), 256, SMEM_TOTAL_G>>>(
        aseh, asel, w_dse, out, nullptr, nullptr, resid2, IDIM, IDIM, HID, HID, 0, 0);
    router_k<<<SEQ, 256>>>(h2, w_router);
    scan_k<<<1, 32>>>();
    fill_k<<<SEQ/256, 256>>>();
    gemm_tc<2><<<dim3(IDIM/64, 16, NEXP), 256, SMEM_TOTAL_G>>>(
        h2h, h2l, w_gue, nullptr, aceh, acel, nullptr, HID, HID, 2*IDIM, IDIM, IDIM,
        (size_t)HID * 2 * IDIM);
    gemm_tc<3><<<dim3(HID/128, 16, NEXP), 256, SMEM_TOTAL_G>>>(
        aceh, acel, w_de, out, nullptr, nullptr, nullptr, IDIM, IDIM, HID, HID, 0,
        (size_t)IDIM * HID);
}

// round 8
// speedup vs baseline: 4.6281x; 1.0375x over previous
#include <cuda_runtime.h>
#include <cuda_bf16.h>
#include <math.h>
#include <stdint.h>

#define SEQ 2048
#define HID 1024
#define NHEAD 16
#define HD 128
#define QDIM 512
#define NEXP 32
#define IDIM 1024
#define QKV_N 768
#define SCALE 0.08838834764831845f   // 1/sqrt(128)

// ------------------------- device scratch ----------------------------------
__device__ float g_qkv[SEQ*QKV_N];
__device__ float g_qproj[SEQ*NHEAD*HD];
__device__ float g_resid2[SEQ*HID];
__device__ float g_h2[SEQ*HID];
__device__ float2 g_cs[SEQ*64];

__device__ __nv_bfloat16 g_hnh[SEQ*HID],  g_hnl[SEQ*HID];
__device__ __nv_bfloat16 g_qnh[SEQ*QDIM], g_qnl[SEQ*QDIM];
__device__ __nv_bfloat16 g_qh[SEQ*2048],  g_ql[SEQ*2048];
__device__ __nv_bfloat16 g_kth[128*SEQ],  g_ktl[128*SEQ];   // transposed [d][token]
__device__ __nv_bfloat16 g_vh[SEQ*128],   g_vl[SEQ*128];
__device__ __nv_bfloat16 g_aoh[SEQ*2048], g_aol[SEQ*2048];
__device__ __nv_bfloat16 g_h2h[SEQ*HID],  g_h2l[SEQ*HID];
__device__ __nv_bfloat16 g_aseh[SEQ*IDIM],g_asel[SEQ*IDIM];
__device__ __nv_bfloat16 g_aceh[SEQ*3*IDIM], g_acel[SEQ*3*IDIM];

__device__ int   g_topi[SEQ*3];
__device__ float g_topw[SEQ*3];
__device__ int   g_cnt[NEXP];
__device__ int   g_off[NEXP];
__device__ int   g_fill[NEXP];
__device__ int   g_ptok[SEQ*3];
__device__ float g_pw[SEQ*3];

// ------------------------- helpers -----------------------------------------
__device__ __forceinline__ uint32_t s2u(const void* p) {
    uint32_t a;
    asm("{ .reg .u64 t; cvta.to.shared.u64 t, %1; cvt.u32.u64 %0, t; }" : "=r"(a) : "l"(p));
    return a;
}
__device__ __forceinline__ void ldsm4(uint32_t* r, uint32_t addr) {
    asm volatile("ldmatrix.sync.aligned.m8n8.x4.shared.b16 {%0,%1,%2,%3}, [%4];"
        : "=r"(r[0]), "=r"(r[1]), "=r"(r[2]), "=r"(r[3]) : "r"(addr));
}
__device__ __forceinline__ void ldsm4t(uint32_t* r, uint32_t addr) {
    asm volatile("ldmatrix.sync.aligned.m8n8.x4.trans.shared.b16 {%0,%1,%2,%3}, [%4];"
        : "=r"(r[0]), "=r"(r[1]), "=r"(r[2]), "=r"(r[3]) : "r"(addr));
}
__device__ __forceinline__ void mma16816(float* c, const uint32_t* a, uint32_t b0, uint32_t b1) {
    asm volatile("mma.sync.aligned.m16n8k16.row.col.f32.bf16.bf16.f32 "
        "{%0,%1,%2,%3}, {%4,%5,%6,%7}, {%8,%9}, {%0,%1,%2,%3};"
        : "+f"(c[0]), "+f"(c[1]), "+f"(c[2]), "+f"(c[3])
        : "r"(a[0]), "r"(a[1]), "r"(a[2]), "r"(a[3]), "r"(b0), "r"(b1));
}
__device__ __forceinline__ void cpa16(uint32_t dst, const void* src) {
    asm volatile("cp.async.cg.shared.global [%0], [%1], 16;" :: "r"(dst), "l"(src));
}
#define CPA_COMMIT() asm volatile("cp.async.commit_group;" ::: "memory")
#define CPA_WAIT()   asm volatile("cp.async.wait_group 0;" ::: "memory")

__device__ __forceinline__ uint32_t pack_hi(float f0, float f1) {
    __nv_bfloat162 h = __floats2bfloat162_rn(f0, f1);
    return *(uint32_t*)&h;
}
__device__ __forceinline__ uint32_t pack_lo(float f0, float f1, uint32_t hibits) {
    __nv_bfloat162 h = *(__nv_bfloat162*)&hibits;
    __nv_bfloat162 l = __floats2bfloat162_rn(f0 - __bfloat162float(h.x),
                                             f1 - __bfloat162float(h.y));
    return *(uint32_t*)&l;
}
__device__ __forceinline__ void split2(float a, float b, uint32_t& hi, uint32_t& lo) {
    hi = pack_hi(a, b);
    lo = pack_lo(a, b, hi);
}
// FFMA-only exp (rel err ~4e-5), avoids MUFU
__device__ __forceinline__ float fexp(float x) {
    x = fminf(fmaxf(x, -80.f), 80.f);
    float y = x * 1.4426950408889634f;
    float n = rintf(y);
    float f = y - n;
    float p = fmaf(f, 0.009618130f, 0.055504110f);
    p = fmaf(p, f, 0.240226507f);
    p = fmaf(p, f, 0.693147181f);
    p = fmaf(p, f, 1.0f);
    return p * __int_as_float(((int)n + 127) << 23);
}

// ------------------------- GEMM: 64xN tiles, 128 thr, 3 CTA/SM --------------
#define LDA 40
#define LDB 136
#define ASZ (64*LDA*2)           // 5120 bytes per A array
#define BSZ (32*LDB*2)           // 8704 bytes per B array
#define OFF_AH(b) ((b) * (2*ASZ))
#define OFF_AL(b) ((b) * (2*ASZ) + ASZ)
#define OFF_BH(b) (4*ASZ + (b) * (2*BSZ))
#define OFF_BL(b) (4*ASZ + (b) * (2*BSZ) + BSZ)
#define OFF_TOK   (4*ASZ + 4*BSZ)
#define SMEM_TOTAL_G (OFF_TOK + 64*4)

// MODE 0: plain  C = A@B (+add) fp32       (64 rows x 128 out cols / CTA)
// MODE 1: gated  Ch/Cl = split(silu(A@Bg)*(A@Bu))  (64 rows x 64 cols, up at +upOff)
// MODE 2: moe gathered gated -> split rows off+r
// MODE 3: moe scatter: C[tok] += w * (A@B)  fp32 atomic
template<int MODE>
__global__ __launch_bounds__(128, 3) void gemm_tc(
    const __nv_bfloat16* __restrict__ Ah, const __nv_bfloat16* __restrict__ Al,
    const float* __restrict__ B,
    float* __restrict__ C, __nv_bfloat16* __restrict__ Ch, __nv_bfloat16* __restrict__ Cl,
    const float* __restrict__ add,
    int K, int lda, int ldb, int ldc, int upOff, size_t bStride)
{
    int cnt = 0, off = 0;
    if (MODE >= 2) {
        int e = blockIdx.z;
        cnt = g_cnt[e];
        if ((int)blockIdx.y * 64 >= cnt) return;
        off = g_off[e];
        B += bStride * e;
    }
    const int m0 = blockIdx.y * 64;
    const int nb = blockIdx.x * ((MODE == 1 || MODE == 2) ? 64 : 128);

    extern __shared__ __align__(16) char sm[];
    int* sTok = (int*)(sm + OFF_TOK);
    const uint32_t sb = s2u(sm);

    const int tid = threadIdx.x;
    const int wid = tid >> 5, lane = tid & 31;
    const int wm = wid >> 1, wn = wid & 1;

    if (MODE == 2 && tid < 64) {
        int gr = m0 + tid;
        sTok[tid] = (gr < cnt) ? g_ptok[off + gr] : 0;
    }
    __syncthreads();

    float acc[2][8][4] = {};
    const int lrow = lane & 15, lcol8 = (lane >> 4) * 8;

    // per-thread A cp.async indices: 2 segments (tid, tid+128); 256 segs total
    const int am0 = tid >> 2, aseg0 = (tid & 3);
    const int am1 = (tid + 128) >> 2, aseg1 = ((tid + 128) & 3);

    size_t arow0, arow1;
    {
        if (MODE == 2) {
            arow0 = (size_t)sTok[am0] * lda;
            arow1 = (size_t)sTok[am1] * lda;
        } else if (MODE == 3) {
            int r0 = (m0 + am0 < cnt) ? m0 + am0 : 0;
            int r1 = (m0 + am1 < cnt) ? m0 + am1 : 0;
            arow0 = (size_t)(off + r0) * lda;
            arow1 = (size_t)(off + r1) * lda;
        } else {
            arow0 = (size_t)(m0 + am0) * lda;
            arow1 = (size_t)(m0 + am1) * lda;
        }
    }
    const uint32_t adst0 = sb + am0 * (LDA*2) + aseg0 * 16;
    const uint32_t adst1 = sb + am1 * (LDA*2) + aseg1 * 16;

    // B load indexing (8 float4 per thread: 32k x 128n)
    int bcol[8]; size_t brow[8];
    #pragma unroll
    for (int it = 0; it < 8; it++) {
        int i = tid + it * 128;
        int kk = i >> 5;
        int n4 = (i & 31) << 2;
        int col;
        if (MODE == 1 || MODE == 2) col = (n4 < 64) ? nb + n4 : upOff + nb + (n4 - 64);
        else                        col = nb + n4;
        bcol[it] = n4;
        brow[it] = (size_t)kk * ldb + col;
    }

    const int nkt = K >> 5;
    float4 br[8];

    // ---- prologue: chunk 0 ----
    {
        cpa16(adst0 + OFF_AH(0), Ah + arow0 + aseg0 * 8);
        cpa16(adst0 + OFF_AL(0), Al + arow0 + aseg0 * 8);
        cpa16(adst1 + OFF_AH(0), Ah + arow1 + aseg1 * 8);
        cpa16(adst1 + OFF_AL(0), Al + arow1 + aseg1 * 8);
        CPA_COMMIT();
        #pragma unroll
        for (int it = 0; it < 8; it++) br[it] = *(const float4*)(B + brow[it]);
        CPA_WAIT();
        __syncthreads();
        #pragma unroll
        for (int it = 0; it < 8; it++) {
            int i = tid + it * 128;
            int kk = i >> 5;
            uint32_t h0 = pack_hi(br[it].x, br[it].y), h1 = pack_hi(br[it].z, br[it].w);
            uint32_t l0 = pack_lo(br[it].x, br[it].y, h0), l1 = pack_lo(br[it].z, br[it].w, h1);
            uint32_t* ph = (uint32_t*)(sm + OFF_BH(0) + kk * (LDB*2) + bcol[it] * 2);
            uint32_t* pl = (uint32_t*)(sm + OFF_BL(0) + kk * (LDB*2) + bcol[it] * 2);
            ph[0] = h0; ph[1] = h1;
            pl[0] = l0; pl[1] = l1;
        }
        __syncthreads();
    }

    int p = 0;
    for (int c = 0; c < nkt; c++) {
        const int q = p ^ 1;
        const bool more = (c + 1 < nkt);
        if (more) {
            const int k1 = (c + 1) << 5;
            cpa16(adst0 + OFF_AH(q), Ah + arow0 + k1 + aseg0 * 8);
            cpa16(adst0 + OFF_AL(q), Al + arow0 + k1 + aseg0 * 8);
            cpa16(adst1 + OFF_AH(q), Ah + arow1 + k1 + aseg1 * 8);
            cpa16(adst1 + OFF_AL(q), Al + arow1 + k1 + aseg1 * 8);
            CPA_COMMIT();
            #pragma unroll
            for (int it = 0; it < 8; it++)
                br[it] = *(const float4*)(B + (size_t)k1 * ldb + brow[it]);
        }

        // ---- MMA on buffer p : warp tile 32x64 ----
        const uint32_t uAh = sb + OFF_AH(p), uAl = sb + OFF_AL(p);
        const uint32_t uBh = sb + OFF_BH(p), uBl = sb + OFF_BL(p);
        #pragma unroll
        for (int ks = 0; ks < 2; ks++) {
            uint32_t ah[2][4], al[2][4];
            #pragma unroll
            for (int mf = 0; mf < 2; mf++) {
                uint32_t ro = (uint32_t)((wm * 32 + mf * 16 + lrow) * LDA + ks * 16 + lcol8) * 2;
                ldsm4(ah[mf], uAh + ro);
                ldsm4(al[mf], uAl + ro);
            }
            #pragma unroll
            for (int nh = 0; nh < 4; nh++) {
                uint32_t bh[4], bl[4];
                uint32_t ro = (uint32_t)((ks * 16 + lrow) * LDB + wn * 64 + nh * 16 + lcol8) * 2;
                ldsm4t(bh, uBh + ro);
                ldsm4t(bl, uBl + ro);
                #pragma unroll
                for (int mf = 0; mf < 2; mf++)
                    #pragma unroll
                    for (int sub = 0; sub < 2; sub++) {
                        int nf = nh * 2 + sub;
                        uint32_t b0h = bh[sub * 2], b1h = bh[sub * 2 + 1];
                        uint32_t b0l = bl[sub * 2], b1l = bl[sub * 2 + 1];
                        mma16816(acc[mf][nf], ah[mf], b0h, b1h);
                        mma16816(acc[mf][nf], ah[mf], b0l, b1l);
                        mma16816(acc[mf][nf], al[mf], b0h, b1h);
                    }
            }
        }

        if (more) {
            #pragma unroll
            for (int it = 0; it < 8; it++) {
                int i = tid + it * 128;
                int kk = i >> 5;
                uint32_t h0 = pack_hi(br[it].x, br[it].y), h1 = pack_hi(br[it].z, br[it].w);
                uint32_t l0 = pack_lo(br[it].x, br[it].y, h0), l1 = pack_lo(br[it].z, br[it].w, h1);
                uint32_t* ph = (uint32_t*)(sm + OFF_BH(q) + kk * (LDB*2) + bcol[it] * 2);
                uint32_t* pl = (uint32_t*)(sm + OFF_BL(q) + kk * (LDB*2) + bcol[it] * 2);
                ph[0] = h0; ph[1] = h1;
                pl[0] = l0; pl[1] = l1;
            }
            CPA_WAIT();
            __syncthreads();
        }
        p = q;
    }
    __syncthreads();

    // ---- epilogue ----
    const int r4 = lane >> 2, c2 = (lane & 3) * 2;
    if (MODE == 0) {
        #pragma unroll
        for (int mf = 0; mf < 2; mf++) {
            #pragma unroll
            for (int nf = 0; nf < 8; nf++) {
                int col = nb + wn * 64 + nf * 8 + c2;
                size_t r1 = (size_t)(m0 + wm * 32 + mf * 16 + r4);
                size_t r2 = r1 + 8;
                float v0 = acc[mf][nf][0], v1 = acc[mf][nf][1];
                float v2 = acc[mf][nf][2], v3 = acc[mf][nf][3];
                if (add) {
                    v0 += add[r1 * ldc + col]; v1 += add[r1 * ldc + col + 1];
                    v2 += add[r2 * ldc + col]; v3 += add[r2 * ldc + col + 1];
                }
                *(float2*)(C + r1 * ldc + col) = make_float2(v0, v1);
                *(float2*)(C + r2 * ldc + col) = make_float2(v2, v3);
            }
        }
    } else if (MODE == 1 || MODE == 2) {
        float* sG = (float*)sm;              // [64][65]
        if (wn == 0) {                        // gate cols 0..63
            #pragma unroll
            for (int mf = 0; mf < 2; mf++)
                #pragma unroll
                for (int nf = 0; nf < 8; nf++) {
                    int col = nf * 8 + c2;
                    int rr1 = wm * 32 + mf * 16 + r4, rr2 = rr1 + 8;
                    sG[rr1 * 65 + col]     = acc[mf][nf][0];
                    sG[rr1 * 65 + col + 1] = acc[mf][nf][1];
                    sG[rr2 * 65 + col]     = acc[mf][nf][2];
                    sG[rr2 * 65 + col + 1] = acc[mf][nf][3];
                }
        }
        __syncthreads();
        if (wn == 1) {                        // up cols -> combine
            #pragma unroll
            for (int mf = 0; mf < 2; mf++)
                #pragma unroll
                for (int nf = 0; nf < 8; nf++) {
                    int col = nf * 8 + c2;
                    int rr1 = wm * 32 + mf * 16 + r4;
                    #pragma unroll
                    for (int half = 0; half < 2; half++) {
                        int rr = rr1 + half * 8;
                        bool ok = (MODE == 1) || (m0 + rr < cnt);
                        if (ok) {
                            size_t row = (MODE == 1) ? (size_t)(m0 + rr) : (size_t)(off + m0 + rr);
                            float g0 = sG[rr * 65 + col], g1 = sG[rr * 65 + col + 1];
                            float u0 = acc[mf][nf][half * 2], u1 = acc[mf][nf][half * 2 + 1];
                            float o0 = g0 / (1.f + fexp(-g0)) * u0;
                            float o1 = g1 / (1.f + fexp(-g1)) * u1;
                            uint32_t hi, lo;
                            split2(o0, o1, hi, lo);
                            *(uint32_t*)(Ch + row * ldc + nb + col) = hi;
                            *(uint32_t*)(Cl + row * ldc + nb + col) = lo;
                        }
                    }
                }
        }
    } else {  // MODE 3
        #pragma unroll
        for (int mf = 0; mf < 2; mf++) {
            int rr1 = wm * 32 + mf * 16 + r4;
            #pragma unroll
            for (int half = 0; half < 2; half++) {
                int rr = rr1 + half * 8;
                if (m0 + rr < cnt) {
                    int tok = g_ptok[off + m0 + rr];
                    float w = g_pw[off + m0 + rr];
                    float* dst = C + (size_t)tok * ldc;
                    #pragma unroll
                    for (int nf = 0; nf < 8; nf++) {
                        int col = nb + wn * 64 + nf * 8 + c2;
                        atomicAdd(dst + col,     w * acc[mf][nf][half * 2]);
                        atomicAdd(dst + col + 1, w * acc[mf][nf][half * 2 + 1]);
                    }
                }
            }
        }
    }
}

// ------------------------- small kernels ------------------------------------
__global__ void zero_counts_k() {
    if (threadIdx.x < NEXP) g_cnt[threadIdx.x] = 0;
}

__global__ void cs_prep_k(const int* __restrict__ pos) {
    int t = blockIdx.x, i = threadIdx.x;   // 64 threads
    double e = exp(-((double)(2 * i) / 128.0) * log(500000.0));
    float f = (float)pos[t] * (float)e;
    float sn, cs; sincosf(f, &sn, &cs);
    g_cs[t * 64 + i] = make_float2(cs, sn);
}

// rmsnorm: writes optional fp32 y + optional bf16 split yh/yl
__global__ void rmsnorm_k(const float* __restrict__ x, const float* __restrict__ w,
                          float* __restrict__ y,
                          __nv_bfloat16* __restrict__ yh, __nv_bfloat16* __restrict__ yl,
                          int cols, int ldx, int ldy)
{
    int row = blockIdx.x;
    const float* xr = x + (size_t)row * ldx;
    float ss = 0.f;
    for (int c = threadIdx.x; c < cols; c += 256) { float v = xr[c]; ss = fmaf(v, v, ss); }
    __shared__ float wred[8];
    #pragma unroll
    for (int d = 16; d; d >>= 1) ss += __shfl_xor_sync(0xffffffffu, ss, d);
    if ((threadIdx.x & 31) == 0) wred[threadIdx.x >> 5] = ss;
    __syncthreads();
    if (threadIdx.x < 32) {
        float v = (threadIdx.x < 8) ? wred[threadIdx.x] : 0.f;
        #pragma unroll
        for (int d = 4; d; d >>= 1) v += __shfl_xor_sync(0xffffffffu, v, d);
        if (threadIdx.x == 0) wred[0] = v;
    }
    __syncthreads();
    float r = rsqrtf(wred[0] / (float)cols + 1e-5f);
    for (int c = threadIdx.x; c < cols; c += 256) {
        float v = xr[c] * r * w[c];
        if (y) y[(size_t)row * ldy + c] = v;
        if (yh) {
            __nv_bfloat16 h = __float2bfloat16_rn(v);
            yh[(size_t)row * ldy + c] = h;
            yl[(size_t)row * ldy + c] = __float2bfloat16_rn(v - __bfloat162float(h));
        }
    }
}

// rope on q (reads qproj fp32, writes split bf16 with SCALE folded)
__global__ void rope_q_k(const float* __restrict__ qp,
                         __nv_bfloat16* __restrict__ qh, __nv_bfloat16* __restrict__ ql)
{
    int t = blockIdx.x;
    for (int idx = threadIdx.x; idx < NHEAD * 64; idx += 256) {
        int hh = idx >> 6, i = idx & 63;
        float2 cs = g_cs[t * 64 + i];
        const float* b = qp + (size_t)t * 2048 + hh * HD;
        float x1 = b[i], x2 = b[i + 64];
        float y1 = (x1 * cs.x - x2 * cs.y) * SCALE;
        float y2 = (x2 * cs.x + x1 * cs.y) * SCALE;
        size_t o1 = (size_t)t * 2048 + hh * HD + i;
        __nv_bfloat16 h1 = __float2bfloat16_rn(y1);
        qh[o1] = h1; ql[o1] = __float2bfloat16_rn(y1 - __bfloat162float(h1));
        __nv_bfloat16 h2 = __float2bfloat16_rn(y2);
        qh[o1 + 64] = h2; ql[o1 + 64] = __float2bfloat16_rn(y2 - __bfloat162float(h2));
    }
}

// K rope + transpose split; V split
__global__ void kv_prep_k(const float* __restrict__ qkv)
{
    int t = blockIdx.x;
    int tid = threadIdx.x;   // 128
    if (tid < 64) {
        int i = tid;
        float2 cs = g_cs[t * 64 + i];
        const float* kb = qkv + (size_t)t * QKV_N + QDIM;
        float x1 = kb[i], x2 = kb[i + 64];
        float y1 = x1 * cs.x - x2 * cs.y;
        float y2 = x2 * cs.x + x1 * cs.y;
        __nv_bfloat16 h1 = __float2bfloat16_rn(y1);
        g_kth[(size_t)i * SEQ + t] = h1;
        g_ktl[(size_t)i * SEQ + t] = __float2bfloat16_rn(y1 - __bfloat162float(h1));
        __nv_bfloat16 h2 = __float2bfloat16_rn(y2);
        g_kth[(size_t)(i + 64) * SEQ + t] = h2;
        g_ktl[(size_t)(i + 64) * SEQ + t] = __float2bfloat16_rn(y2 - __bfloat162float(h2));
    }
    {
        float v = qkv[(size_t)t * QKV_N + QDIM + HD + tid];
        __nv_bfloat16 h = __float2bfloat16_rn(v);
        g_vh[(size_t)t * HD + tid] = h;
        g_vl[(size_t)t * HD + tid] = __float2bfloat16_rn(v - __bfloat162float(h));
    }
}

// ------------------------- attention: bf16 HMMA flash ----------------------
#define AQ_LD 136
#define AK_LD 72
#define AV_LD 136
#define AP_LD 72
#define AOF_QH 0
#define AOF_QL 34816
#define AOF_KH 69632
#define AOF_KL 88064
#define AOF_VH 106496
#define AOF_VL 123904
#define AOF_PH 141312
#define AOF_PL 159744
#define AOF_M  178176
#define AOF_L  178688
#define AOF_RMAX 179200
#define AOF_RSUM 180224
#define ATTN_SMEM 181248

__global__ __launch_bounds__(256, 1) void attn_k(
    const __nv_bfloat16* __restrict__ Qh, const __nv_bfloat16* __restrict__ Ql,
    __nv_bfloat16* __restrict__ Oh, __nv_bfloat16* __restrict__ Ol)
{
    extern __shared__ __align__(16) char sm[];
    const int bx = blockIdx.x;
    const int qt = 15 - (bx >> 4);     // longest tiles first
    const int h = bx & 15;
    const int q0 = qt * 128;

    const int tid = threadIdx.x;
    const int wid = tid >> 5, lane = tid & 31;
    const int wm = wid >> 1, wn = wid & 1;
    const int lrow = lane & 15, lcol8 = (lane >> 4) * 8;
    const int r4 = lane >> 2, c2 = (lane & 3) * 2;

    float* sM = (float*)(sm + AOF_M);
    float* sL = (float*)(sm + AOF_L);
    float* sRmax = (float*)(sm + AOF_RMAX);   // [2][128]
    float* sRsum = (float*)(sm + AOF_RSUM);   // [2][128]
    const uint32_t uQh = s2u(sm + AOF_QH), uQl = s2u(sm + AOF_QL);
    const uint32_t uKh = s2u(sm + AOF_KH), uKl = s2u(sm + AOF_KL);
    const uint32_t uVh = s2u(sm + AOF_VH), uVl = s2u(sm + AOF_VL);
    const uint32_t uPh = s2u(sm + AOF_PH), uPl = s2u(sm + AOF_PL);

    // load Q tile (128 x 128, hi+lo)
    #pragma unroll
    for (int it = 0; it < 8; it++) {
        int i = tid + it * 256;          // 2048 uint4 per copy
        int r = i >> 4, c = (i & 15) << 3;
        size_t src = (size_t)(q0 + r) * 2048 + h * HD + c;
        *(uint4*)(sm + AOF_QH + r * (AQ_LD*2) + c * 2) = *(const uint4*)(Qh + src);
        *(uint4*)(sm + AOF_QL + r * (AQ_LD*2) + c * 2) = *(const uint4*)(Ql + src);
    }
    if (tid < 128) { sM[tid] = -3.0e30f; sL[tid] = 0.f; }

    float o[2][8][4] = {};
    const int nkt = 2 * qt + 2;

    for (int kt = 0; kt < nkt; kt++) {
        const int k0 = kt * 64;
        __syncthreads();
        // load K tile (transposed source [d][tok]): 128 x 64
        #pragma unroll
        for (int it = 0; it < 4; it++) {
            int i = tid + it * 256;      // 1024 uint4 per copy
            int d = i >> 3, tc = (i & 7) << 3;
            size_t src = (size_t)d * SEQ + k0 + tc;
            *(uint4*)(sm + AOF_KH + d * (AK_LD*2) + tc * 2) = *(const uint4*)(g_kth + src);
            *(uint4*)(sm + AOF_KL + d * (AK_LD*2) + tc * 2) = *(const uint4*)(g_ktl + src);
        }
        // load V tile: 64 x 128
        #pragma unroll
        for (int it = 0; it < 4; it++) {
            int i = tid + it * 256;
            int r = i >> 4, c = (i & 15) << 3;
            size_t src = (size_t)(k0 + r) * HD + c;
            *(uint4*)(sm + AOF_VH + r * (AV_LD*2) + c * 2) = *(const uint4*)(g_vh + src);
            *(uint4*)(sm + AOF_VL + r * (AV_LD*2) + c * 2) = *(const uint4*)(g_vl + src);
        }
        __syncthreads();

        // ---- S = Q K^T (3-pass split) ----
        float sacc[2][4][4] = {};
        #pragma unroll
        for (int ks = 0; ks < 8; ks++) {
            uint32_t ah[2][4], al[2][4], bh[2][4], bl[2][4];
            #pragma unroll
            for (int mf = 0; mf < 2; mf++) {
                uint32_t ro = (uint32_t)((wm * 32 + mf * 16 + lrow) * AQ_LD + ks * 16 + lcol8) * 2;
                ldsm4(ah[mf], uQh + ro);
                ldsm4(al[mf], uQl + ro);
            }
            #pragma unroll
            for (int nh = 0; nh < 2; nh++) {
                uint32_t ro = (uint32_t)((ks * 16 + lrow) * AK_LD + wn * 32 + nh * 16 + lcol8) * 2;
                ldsm4t(bh[nh], uKh + ro);
                ldsm4t(bl[nh], uKl + ro);
            }
            #pragma unroll
            for (int mf = 0; mf < 2; mf++)
                #pragma unroll
                for (int nf = 0; nf < 4; nf++) {
                    uint32_t b0h = bh[nf >> 1][(nf & 1) * 2], b1h = bh[nf >> 1][(nf & 1) * 2 + 1];
                    uint32_t b0l = bl[nf >> 1][(nf & 1) * 2], b1l = bl[nf >> 1][(nf & 1) * 2 + 1];
                    mma16816(sacc[mf][nf], ah[mf], b0h, b1h);
                    mma16816(sacc[mf][nf], ah[mf], b0l, b1l);
                    mma16816(sacc[mf][nf], al[mf], b0h, b1h);
                }
        }

        // causal mask on diagonal tiles
        if (kt >= nkt - 2) {
            #pragma unroll
            for (int mf = 0; mf < 2; mf++)
                #pragma unroll
                for (int nf = 0; nf < 4; nf++)
                    #pragma unroll
                    for (int v = 0; v < 4; v++) {
                        int row = q0 + wm * 32 + mf * 16 + r4 + (v >= 2 ? 8 : 0);
                        int col = k0 + wn * 32 + nf * 8 + c2 + (v & 1);
                        if (col > row) sacc[mf][nf][v] = -1.0e30f;
                    }
        }

        // ---- row max (warp-local then cross-warp) ----
        float rmax[4] = {-3.0e30f, -3.0e30f, -3.0e30f, -3.0e30f};
        #pragma unroll
        for (int mf = 0; mf < 2; mf++)
            #pragma unroll
            for (int nf = 0; nf < 4; nf++) {
                rmax[mf*2]   = fmaxf(rmax[mf*2],   fmaxf(sacc[mf][nf][0], sacc[mf][nf][1]));
                rmax[mf*2+1] = fmaxf(rmax[mf*2+1], fmaxf(sacc[mf][nf][2], sacc[mf][nf][3]));
            }
        #pragma unroll
        for (int s = 0; s < 4; s++) {
            rmax[s] = fmaxf(rmax[s], __shfl_xor_sync(0xffffffffu, rmax[s], 1));
            rmax[s] = fmaxf(rmax[s], __shfl_xor_sync(0xffffffffu, rmax[s], 2));
        }
        if ((lane & 3) == 0) {
            #pragma unroll
            for (int s = 0; s < 4; s++) {
                int lr = wm * 32 + (s >> 1) * 16 + r4 + (s & 1) * 8;
                sRmax[wn * 128 + lr] = rmax[s];
            }
        }
        __syncthreads();

        float mn[4], fct[4];
        #pragma unroll
        for (int s = 0; s < 4; s++) {
            int lr = wm * 32 + (s >> 1) * 16 + r4 + (s & 1) * 8;
            float mo = sM[lr];
            float m2 = fmaxf(sRmax[lr], sRmax[128 + lr]);
            mn[s] = fmaxf(mo, m2);
            fct[s] = fexp(mo - mn[s]);
        }

        // ---- p = exp(s-mn), store split P, partial sums, rescale o ----
        float rsum[4] = {0.f, 0.f, 0.f, 0.f};
        #pragma unroll
        for (int mf = 0; mf < 2; mf++) {
            int lr0 = wm * 32 + mf * 16 + r4;
            #pragma unroll
            for (int nf = 0; nf < 4; nf++) {
                int col = wn * 32 + nf * 8 + c2;
                float p0 = fexp(sacc[mf][nf][0] - mn[mf*2]);
                float p1 = fexp(sacc[mf][nf][1] - mn[mf*2]);
                float p2 = fexp(sacc[mf][nf][2] - mn[mf*2+1]);
                float p3 = fexp(sacc[mf][nf][3] - mn[mf*2+1]);
                rsum[mf*2]   += p0 + p1;
                rsum[mf*2+1] += p2 + p3;
                uint32_t hi, lo;
                split2(p0, p1, hi, lo);
                *(uint32_t*)(sm + AOF_PH + (lr0 * AP_LD + col) * 2) = hi;
                *(uint32_t*)(sm + AOF_PL + (lr0 * AP_LD + col) * 2) = lo;
                split2(p2, p3, hi, lo);
                *(uint32_t*)(sm + AOF_PH + ((lr0 + 8) * AP_LD + col) * 2) = hi;
                *(uint32_t*)(sm + AOF_PL + ((lr0 + 8) * AP_LD + col) * 2) = lo;
            }
        }
        #pragma unroll
        for (int mf = 0; mf < 2; mf++)
            #pragma unroll
            for (int nf8 = 0; nf8 < 8; nf8++) {
                o[mf][nf8][0] *= fct[mf*2];   o[mf][nf8][1] *= fct[mf*2];
                o[mf][nf8][2] *= fct[mf*2+1]; o[mf][nf8][3] *= fct[mf*2+1];
            }
        #pragma unroll
        for (int s = 0; s < 4; s++) {
            rsum[s] += __shfl_xor_sync(0xffffffffu, rsum[s], 1);
            rsum[s] += __shfl_xor_sync(0xffffffffu, rsum[s], 2);
        }
        if ((lane & 3) == 0) {
            #pragma unroll
            for (int s = 0; s < 4; s++) {
                int lr = wm * 32 + (s >> 1) * 16 + r4 + (s & 1) * 8;
                sRsum[wn * 128 + lr] = rsum[s];
            }
        }
        __syncthreads();
        if (wn == 0 && (lane & 3) == 0) {
            #pragma unroll
            for (int s = 0; s < 4; s++) {
                int lr = wm * 32 + (s >> 1) * 16 + r4 + (s & 1) * 8;
                sL[lr] = sL[lr] * fct[s] + sRsum[lr] + sRsum[128 + lr];
                sM[lr] = mn[s];
            }
        }

        // ---- O += P V (3-pass split) ----
        #pragma unroll
        for (int ks = 0; ks < 4; ks++) {
            uint32_t aph[2][4], apl[2][4], bvh[4][4], bvl[4][4];
            #pragma unroll
            for (int mf = 0; mf < 2; mf++) {
                uint32_t ro = (uint32_t)((wm * 32 + mf * 16 + lrow) * AP_LD + ks * 16 + lcol8) * 2;
                ldsm4(aph[mf], uPh + ro);
                ldsm4(apl[mf], uPl + ro);
            }
            #pragma unroll
            for (int nh = 0; nh < 4; nh++) {
                uint32_t ro = (uint32_t)((ks * 16 + lrow) * AV_LD + wn * 64 + nh * 16 + lcol8) * 2;
                ldsm4t(bvh[nh], uVh + ro);
                ldsm4t(bvl[nh], uVl + ro);
            }
            #pragma unroll
            for (int mf = 0; mf < 2; mf++)
                #pragma unroll
                for (int nf8 = 0; nf8 < 8; nf8++) {
                    uint32_t b0h = bvh[nf8 >> 1][(nf8 & 1) * 2], b1h = bvh[nf8 >> 1][(nf8 & 1) * 2 + 1];
                    uint32_t b0l = bvl[nf8 >> 1][(nf8 & 1) * 2], b1l = bvl[nf8 >> 1][(nf8 & 1) * 2 + 1];
                    mma16816(o[mf][nf8], aph[mf], b0h, b1h);
                    mma16816(o[mf][nf8], aph[mf], b0l, b1l);
                    mma16816(o[mf][nf8], apl[mf], b0h, b1h);
                }
        }
    }
    __syncthreads();

    // ---- write O (split bf16) ----
    float inv[4];
    #pragma unroll
    for (int s = 0; s < 4; s++) {
        int lr = wm * 32 + (s >> 1) * 16 + r4 + (s & 1) * 8;
        inv[s] = 1.f / sL[lr];
    }
    #pragma unroll
    for (int mf = 0; mf < 2; mf++) {
        int row0 = q0 + wm * 32 + mf * 16 + r4;
        #pragma unroll
        for (int nf8 = 0; nf8 < 8; nf8++) {
            int col = h * HD + wn * 64 + nf8 * 8 + c2;
            uint32_t hi, lo;
            split2(o[mf][nf8][0] * inv[mf*2], o[mf][nf8][1] * inv[mf*2], hi, lo);
            *(uint32_t*)(Oh + (size_t)row0 * 2048 + col) = hi;
            *(uint32_t*)(Ol + (size_t)row0 * 2048 + col) = lo;
            split2(o[mf][nf8][2] * inv[mf*2+1], o[mf][nf8][3] * inv[mf*2+1], hi, lo);
            *(uint32_t*)(Oh + (size_t)(row0 + 8) * 2048 + col) = hi;
            *(uint32_t*)(Ol + (size_t)(row0 + 8) * 2048 + col) = lo;
        }
    }
}

// ------------------------- router / topk / scan / fill ---------------------
__global__ __launch_bounds__(256) void router_k(const float* __restrict__ X,
                                                const float* __restrict__ Wr)
{
    __shared__ float part[8][32];
    int t = blockIdx.x;
    int e = threadIdx.x & 31, p = threadIdx.x >> 5;
    const float* xr = X + (size_t)t * HID;
    float s = 0.f;
    for (int k = p * 128; k < p * 128 + 128; k++) s = fmaf(xr[k], Wr[k * 32 + e], s);
    part[p][e] = s;
    __syncthreads();
    if (threadIdx.x < 32) {
        float logit = 0.f;
        #pragma unroll
        for (int q = 0; q < 8; q++) logit += part[q][e];
        float m = logit;
        for (int d = 16; d; d >>= 1) m = fmaxf(m, __shfl_xor_sync(0xffffffffu, m, d));
        float ex = __expf(logit - m);
        float cur = ex;
        float wsel[3]; int isel[3];
        #pragma unroll
        for (int kk = 0; kk < 3; kk++) {
            float v = cur; int idx = e;
            for (int d = 16; d; d >>= 1) {
                float v2 = __shfl_xor_sync(0xffffffffu, v, d);
                int   i2 = __shfl_xor_sync(0xffffffffu, idx, d);
                if (v2 > v || (v2 == v && i2 < idx)) { v = v2; idx = i2; }
            }
            wsel[kk] = v; isel[kk] = idx;
            if (e == idx) cur = -1.f;
        }
        float tot = wsel[0] + wsel[1] + wsel[2];
        if (e < 3) { g_topi[t * 3 + e] = isel[e]; g_topw[t * 3 + e] = wsel[e] / tot; }
        if (e == 0) {
            atomicAdd(&g_cnt[isel[0]], 1);
            atomicAdd(&g_cnt[isel[1]], 1);
            atomicAdd(&g_cnt[isel[2]], 1);
        }
    }
}

__global__ void scan_k()
{
    int e = threadIdx.x;
    int c = g_cnt[e];
    int x = c;
    for (int d = 1; d < 32; d <<= 1) {
        int y = __shfl_up_sync(0xffffffffu, x, d);
        if (e >= d) x += y;
    }
    int excl = x - c;
    g_off[e] = excl;
    g_fill[e] = excl;
}

__global__ void fill_k()
{
    int t = blockIdx.x * 256 + threadIdx.x;
    if (t < SEQ) {
        #pragma unroll
        for (int k = 0; k < 3; k++) {
            int e = g_topi[t * 3 + k];
            int slot = atomicAdd(&g_fill[e], 1);
            g_ptok[slot] = t;
            g_pw[slot] = g_topw[t * 3 + k];
        }
    }
}

// ------------------------- launch ------------------------------------------
extern "C" void kernel_launch(void* const* d_in, const int* in_sizes, int n_in,
                              void* d_out, int out_size)
{
    const float* hidden   = (const float*)d_in[0];
    const float* w_in     = (const float*)d_in[1];
    const float* w_qkv    = (const float*)d_in[2];
    const float* w_inter  = (const float*)d_in[3];
    const float* w_q      = (const float*)d_in[4];
    const float* w_o      = (const float*)d_in[5];
    const float* w_post   = (const float*)d_in[6];
    const float* w_guse   = (const float*)d_in[7];
    const float* w_dse    = (const float*)d_in[8];
    const float* w_router = (const float*)d_in[9];
    const float* w_gue    = (const float*)d_in[10];
    const float* w_de     = (const float*)d_in[11];
    const int*   pos      = (const int*)d_in[12];
    float* out = (float*)d_out;

    float *qkv, *qproj, *resid2, *h2;
    cudaGetSymbolAddress((void**)&qkv,    g_qkv);
    cudaGetSymbolAddress((void**)&qproj,  g_qproj);
    cudaGetSymbolAddress((void**)&resid2, g_resid2);
    cudaGetSymbolAddress((void**)&h2,     g_h2);
    __nv_bfloat16 *hnh,*hnl,*qnh,*qnl,*qh,*ql,*aoh,*aol,*h2h,*h2l,*aseh,*asel,*aceh,*acel;
    cudaGetSymbolAddress((void**)&hnh, g_hnh);   cudaGetSymbolAddress((void**)&hnl, g_hnl);
    cudaGetSymbolAddress((void**)&qnh, g_qnh);   cudaGetSymbolAddress((void**)&qnl, g_qnl);
    cudaGetSymbolAddress((void**)&qh,  g_qh);    cudaGetSymbolAddress((void**)&ql,  g_ql);
    cudaGetSymbolAddress((void**)&aoh, g_aoh);   cudaGetSymbolAddress((void**)&aol, g_aol);
    cudaGetSymbolAddress((void**)&h2h, g_h2h);   cudaGetSymbolAddress((void**)&h2l, g_h2l);
    cudaGetSymbolAddress((void**)&aseh,g_aseh);  cudaGetSymbolAddress((void**)&asel,g_asel);
    cudaGetSymbolAddress((void**)&aceh,g_aceh);  cudaGetSymbolAddress((void**)&acel,g_acel);

    cudaFuncSetAttribute(attn_k, cudaFuncAttributeMaxDynamicSharedMemorySize, ATTN_SMEM);
    cudaFuncSetAttribute(gemm_tc<0>, cudaFuncAttributeMaxDynamicSharedMemorySize, SMEM_TOTAL_G);
    cudaFuncSetAttribute(gemm_tc<1>, cudaFuncAttributeMaxDynamicSharedMemorySize, SMEM_TOTAL_G);
    cudaFuncSetAttribute(gemm_tc<2>, cudaFuncAttributeMaxDynamicSharedMemorySize, SMEM_TOTAL_G);
    cudaFuncSetAttribute(gemm_tc<3>, cudaFuncAttributeMaxDynamicSharedMemorySize, SMEM_TOTAL_G);

    zero_counts_k<<<1, 32>>>();
    cs_prep_k<<<SEQ, 64>>>(pos);
    rmsnorm_k<<<SEQ, 256>>>(hidden, w_in, nullptr, hnh, hnl, HID, HID, HID);
    gemm_tc<0><<<dim3(QKV_N/128, SEQ/64), 128, SMEM_TOTAL_G>>>(
        hnh, hnl, w_qkv, qkv, nullptr, nullptr, nullptr, HID, HID, QKV_N, QKV_N, 0, 0);
    rmsnorm_k<<<SEQ, 256>>>(qkv, w_inter, nullptr, qnh, qnl, QDIM, QKV_N, QDIM);
    gemm_tc<0><<<dim3(2048/128, SEQ/64), 128, SMEM_TOTAL_G>>>(
        qnh, qnl, w_q, qproj, nullptr, nullptr, nullptr, QDIM, QDIM, 2048, 2048, 0, 0);
    rope_q_k<<<SEQ, 256>>>(qproj, qh, ql);
    kv_prep_k<<<SEQ, 128>>>(qkv);
    attn_k<<<256, 256, ATTN_SMEM>>>(qh, ql, aoh, aol);
    gemm_tc<0><<<dim3(HID/128, SEQ/64), 128, SMEM_TOTAL_G>>>(
        aoh, aol, w_o, resid2, nullptr, nullptr, hidden, 2048, 2048, HID, HID, 0, 0);
    rmsnorm_k<<<SEQ, 256>>>(resid2, w_post, h2, h2h, h2l, HID, HID, HID);
    gemm_tc<1><<<dim3(IDIM/64, SEQ/64), 128, SMEM_TOTAL_G>>>(
        h2h, h2l, w_guse, nullptr, aseh, asel, nullptr, HID, HID, 2*IDIM, IDIM, IDIM, 0);
    gemm_tc<0><<<dim3(HID/128, SEQ/64), 128, SMEM_TOTAL_G>>>(
        aseh, asel, w_dse, out, nullptr, nullptr, resid2, IDIM, IDIM, HID, HID, 0, 0);
    router_k<<<SEQ, 256>>>(h2, w_router);
    scan_k<<<1, 32>>>();
    fill_k<<<SEQ/256, 256>>>();
    gemm_tc<2><<<dim3(IDIM/64, 32, NEXP), 128, SMEM_TOTAL_G>>>(
        h2h, h2l, w_gue, nullptr, aceh, acel, nullptr, HID, HID, 2*IDIM, IDIM, IDIM,
        (size_t)HID * 2 * IDIM);
    gemm_tc<3><<<dim3(HID/128, 32, NEXP), 128, SMEM_TOTAL_G>>>(
        aceh, acel, w_de, out, nullptr, nullptr, nullptr, IDIM, IDIM, HID, HID, 0,
        (size_t)IDIM * HID);
}